// round 1
// baseline (speedup 1.0000x reference)
#include <cuda_runtime.h>

// Problem constants
#define BATCH 4
#define SEQ   2048
#define DMODEL 1024
#define NHEAD 16
#define DHEAD 64
// derived
#define MROWS (BATCH * SEQ)          // 8192
#define OUT_ELEMS ((size_t)BATCH * SEQ * DMODEL)  // 8388608

// Scratch (allocation-free rule: static __device__ globals)
__device__ float g_qh[(size_t)BATCH * NHEAD * SEQ * DHEAD];  // [B,H,S,64]
__device__ float g_kh[(size_t)BATCH * NHEAD * SEQ * DHEAD];
__device__ float g_vh[(size_t)BATCH * NHEAD * SEQ * DHEAD];
__device__ float g_oh[(size_t)BATCH * SEQ * DMODEL];         // [B,S,H*DV]

// ---------------------------------------------------------------------------
// 128x128x8 SGEMM, row-major A[M,K] x B[K,N] + bias[N].
// MODE 0: C[m*N+n]  (plain row-major)
// MODE 1: head-permuted store: m=(b,s), n=(h,d) -> C[((b*H+h)*S+s)*64+d]
// ---------------------------------------------------------------------------
template <int MODE>
__global__ __launch_bounds__(256) void gemm128(
    const float* __restrict__ A, const float* __restrict__ B,
    const float* __restrict__ bias, float* __restrict__ C,
    int M, int N, int K)
{
    __shared__ float As[8][128];
    __shared__ float Bs[8][128];

    const int tid = threadIdx.x;
    const int rowBase = blockIdx.y * 128;
    const int colBase = blockIdx.x * 128;
    const int tr = tid >> 4;       // 0..15
    const int tc = tid & 15;       // 0..15

    // A tile loader: 128 rows x 8 cols, float4 per thread
    const int arow = tid >> 1;            // 0..127
    const int acol = (tid & 1) * 4;       // 0 or 4
    // B tile loader: 8 rows x 128 cols
    const int brow = tid >> 5;            // 0..7
    const int bcol = (tid & 31) * 4;      // 0..124

    const float* Aptr = A + (size_t)(rowBase + arow) * K + acol;
    const float* Bptr = B + (size_t)brow * N + colBase + bcol;

    float acc[8][8];
#pragma unroll
    for (int i = 0; i < 8; i++)
#pragma unroll
        for (int j = 0; j < 8; j++) acc[i][j] = 0.0f;

    for (int k0 = 0; k0 < K; k0 += 8) {
        float4 av = *(const float4*)(Aptr + k0);
        float4 bv = *(const float4*)(Bptr + (size_t)k0 * N);
        As[acol + 0][arow] = av.x;
        As[acol + 1][arow] = av.y;
        As[acol + 2][arow] = av.z;
        As[acol + 3][arow] = av.w;
        *(float4*)&Bs[brow][bcol] = bv;
        __syncthreads();
#pragma unroll
        for (int kk = 0; kk < 8; kk++) {
            float a[8], b[8];
            *(float4*)(a)     = *(const float4*)&As[kk][tr * 8];
            *(float4*)(a + 4) = *(const float4*)&As[kk][tr * 8 + 4];
            *(float4*)(b)     = *(const float4*)&Bs[kk][tc * 8];
            *(float4*)(b + 4) = *(const float4*)&Bs[kk][tc * 8 + 4];
#pragma unroll
            for (int i = 0; i < 8; i++)
#pragma unroll
                for (int j = 0; j < 8; j++)
                    acc[i][j] += a[i] * b[j];
        }
        __syncthreads();
    }

#pragma unroll
    for (int i = 0; i < 8; i++) {
        const int row = rowBase + tr * 8 + i;
#pragma unroll
        for (int j = 0; j < 8; j++) {
            const int col = colBase + tc * 8 + j;
            float vout = acc[i][j] + bias[col];
            if (MODE == 0) {
                C[(size_t)row * N + col] = vout;
            } else {
                const int b_ = row >> 11;        // row / SEQ
                const int s_ = row & (SEQ - 1);
                const int h_ = col >> 6;         // col / 64
                const int d_ = col & 63;
                C[(((size_t)(b_ * NHEAD + h_)) * SEQ + s_) * DHEAD + d_] = vout;
            }
        }
    }
}

// ---------------------------------------------------------------------------
// Scores: per (b,h): S[q,k] = (Qh[q,:] . Kh[k,:]) / 8, 64x64 tile, K=64 in smem
// ---------------------------------------------------------------------------
__global__ __launch_bounds__(256) void scores_kernel(
    const float* __restrict__ qh, const float* __restrict__ kh,
    float* __restrict__ attn)
{
    __shared__ float Qs[64][64];  // [d][q]
    __shared__ float Ks[64][64];  // [d][k]

    const int z  = blockIdx.z;               // b*H + h
    const int q0 = blockIdx.y * 64;
    const int k0 = blockIdx.x * 64;
    const float* Q  = qh + (size_t)z * SEQ * DHEAD;
    const float* Kp = kh + (size_t)z * SEQ * DHEAD;
    const int tid = threadIdx.x;

#pragma unroll
    for (int t = 0; t < 4; t++) {
        const int fi  = tid + t * 256;     // 0..1023 float4 slots
        const int row = fi >> 4;           // 0..63
        const int c4  = (fi & 15) * 4;     // 0..60
        float4 qv = *(const float4*)&Q[(size_t)(q0 + row) * DHEAD + c4];
        Qs[c4 + 0][row] = qv.x; Qs[c4 + 1][row] = qv.y;
        Qs[c4 + 2][row] = qv.z; Qs[c4 + 3][row] = qv.w;
        float4 kv = *(const float4*)&Kp[(size_t)(k0 + row) * DHEAD + c4];
        Ks[c4 + 0][row] = kv.x; Ks[c4 + 1][row] = kv.y;
        Ks[c4 + 2][row] = kv.z; Ks[c4 + 3][row] = kv.w;
    }
    __syncthreads();

    const int tr = tid >> 4, tc = tid & 15;
    float acc[4][4];
#pragma unroll
    for (int i = 0; i < 4; i++)
#pragma unroll
        for (int j = 0; j < 4; j++) acc[i][j] = 0.0f;

#pragma unroll
    for (int d = 0; d < 64; d++) {
        float4 a = *(const float4*)&Qs[d][tr * 4];
        float4 b = *(const float4*)&Ks[d][tc * 4];
        acc[0][0] += a.x * b.x; acc[0][1] += a.x * b.y; acc[0][2] += a.x * b.z; acc[0][3] += a.x * b.w;
        acc[1][0] += a.y * b.x; acc[1][1] += a.y * b.y; acc[1][2] += a.y * b.z; acc[1][3] += a.y * b.w;
        acc[2][0] += a.z * b.x; acc[2][1] += a.z * b.y; acc[2][2] += a.z * b.z; acc[2][3] += a.z * b.w;
        acc[3][0] += a.w * b.x; acc[3][1] += a.w * b.y; acc[3][2] += a.w * b.z; acc[3][3] += a.w * b.w;
    }

    const float sc = 0.125f;  // 1/sqrt(64)
#pragma unroll
    for (int i = 0; i < 4; i++) {
        const size_t rowoff = ((size_t)z * SEQ + (q0 + tr * 4 + i)) * SEQ;
#pragma unroll
        for (int j = 0; j < 4; j++)
            attn[rowoff + k0 + tc * 4 + j] = acc[i][j] * sc;
    }
}

// ---------------------------------------------------------------------------
// Row softmax over 2048 elements, in place. One CTA (256 threads) per row.
// ---------------------------------------------------------------------------
__global__ __launch_bounds__(256) void softmax_kernel(float* __restrict__ attn)
{
    const size_t row = blockIdx.x;
    float* x = attn + row * (size_t)SEQ;
    const int tid = threadIdx.x;

    float4 v0 = ((float4*)x)[tid * 2];
    float4 v1 = ((float4*)x)[tid * 2 + 1];

    float m = fmaxf(fmaxf(fmaxf(v0.x, v0.y), fmaxf(v0.z, v0.w)),
                    fmaxf(fmaxf(v1.x, v1.y), fmaxf(v1.z, v1.w)));

    __shared__ float red[8];
#pragma unroll
    for (int o = 16; o; o >>= 1) m = fmaxf(m, __shfl_xor_sync(0xffffffffu, m, o));
    if ((tid & 31) == 0) red[tid >> 5] = m;
    __syncthreads();
    m = red[0];
#pragma unroll
    for (int i = 1; i < 8; i++) m = fmaxf(m, red[i]);
    __syncthreads();  // protect red[] before reuse

    v0.x = __expf(v0.x - m); v0.y = __expf(v0.y - m);
    v0.z = __expf(v0.z - m); v0.w = __expf(v0.w - m);
    v1.x = __expf(v1.x - m); v1.y = __expf(v1.y - m);
    v1.z = __expf(v1.z - m); v1.w = __expf(v1.w - m);

    float s = v0.x + v0.y + v0.z + v0.w + v1.x + v1.y + v1.z + v1.w;
#pragma unroll
    for (int o = 16; o; o >>= 1) s += __shfl_xor_sync(0xffffffffu, s, o);
    if ((tid & 31) == 0) red[tid >> 5] = s;
    __syncthreads();
    s = red[0] + red[1] + red[2] + red[3] + red[4] + red[5] + red[6] + red[7];
    const float inv = 1.0f / s;

    v0.x *= inv; v0.y *= inv; v0.z *= inv; v0.w *= inv;
    v1.x *= inv; v1.y *= inv; v1.z *= inv; v1.w *= inv;
    ((float4*)x)[tid * 2]     = v0;
    ((float4*)x)[tid * 2 + 1] = v1;
}

// ---------------------------------------------------------------------------
// AV: per (b,h): O[q,dv] = sum_k P[q,k] * Vh[k,dv]. M=2048,N=64,K=2048.
// Writes into g_oh at [b, q, h*64 + dv] (ldc = 1024).
// ---------------------------------------------------------------------------
__global__ __launch_bounds__(256) void av_kernel(
    const float* __restrict__ attn, const float* __restrict__ vh,
    float* __restrict__ oh)
{
    const int z = blockIdx.z;
    const int b = z >> 4, h = z & 15;
    const float* A  = attn + (size_t)z * SEQ * SEQ;     // [2048, 2048]
    const float* Bv = vh   + (size_t)z * SEQ * DHEAD;   // [2048, 64]
    float* C = oh + (size_t)b * SEQ * DMODEL + h * DHEAD;

    const int rowBase = blockIdx.y * 64;
    __shared__ float As[16][64];
    __shared__ float Bs[16][64];
    const int tid = threadIdx.x;
    const int ar = tid >> 2, ak = (tid & 3) * 4;
    const int bk = tid >> 4, bn = (tid & 15) * 4;
    const int tr = tid >> 4, tc = tid & 15;

    float acc[4][4];
#pragma unroll
    for (int i = 0; i < 4; i++)
#pragma unroll
        for (int j = 0; j < 4; j++) acc[i][j] = 0.0f;

    for (int k0 = 0; k0 < SEQ; k0 += 16) {
        float4 av = *(const float4*)&A[(size_t)(rowBase + ar) * SEQ + k0 + ak];
        As[ak + 0][ar] = av.x; As[ak + 1][ar] = av.y;
        As[ak + 2][ar] = av.z; As[ak + 3][ar] = av.w;
        *(float4*)&Bs[bk][bn] = *(const float4*)&Bv[(size_t)(k0 + bk) * DHEAD + bn];
        __syncthreads();
#pragma unroll
        for (int kk = 0; kk < 16; kk++) {
            float4 a = *(const float4*)&As[kk][tr * 4];
            float4 b = *(const float4*)&Bs[kk][tc * 4];
            acc[0][0] += a.x * b.x; acc[0][1] += a.x * b.y; acc[0][2] += a.x * b.z; acc[0][3] += a.x * b.w;
            acc[1][0] += a.y * b.x; acc[1][1] += a.y * b.y; acc[1][2] += a.y * b.z; acc[1][3] += a.y * b.w;
            acc[2][0] += a.z * b.x; acc[2][1] += a.z * b.y; acc[2][2] += a.z * b.z; acc[2][3] += a.z * b.w;
            acc[3][0] += a.w * b.x; acc[3][1] += a.w * b.y; acc[3][2] += a.w * b.z; acc[3][3] += a.w * b.w;
        }
        __syncthreads();
    }

#pragma unroll
    for (int i = 0; i < 4; i++) {
        const size_t rowoff = (size_t)(rowBase + tr * 4 + i) * DMODEL;
#pragma unroll
        for (int j = 0; j < 4; j++)
            C[rowoff + tc * 4 + j] = acc[i][j];
    }
}

// ---------------------------------------------------------------------------
extern "C" void kernel_launch(void* const* d_in, const int* in_sizes, int n_in,
                              void* d_out, int out_size)
{
    const float* q  = (const float*)d_in[0];
    const float* k  = (const float*)d_in[1];
    const float* v  = (const float*)d_in[2];
    const float* Wq = (const float*)d_in[3];
    const float* bq = (const float*)d_in[4];
    const float* Wk = (const float*)d_in[5];
    const float* bk = (const float*)d_in[6];
    const float* Wv = (const float*)d_in[7];
    const float* bv = (const float*)d_in[8];
    const float* Wo = (const float*)d_in[9];
    const float* bo = (const float*)d_in[10];

    float* out  = (float*)d_out;            // [B,S,D]
    float* attn = out + OUT_ELEMS;          // [B,H,S,S]

    float *qh, *kh, *vh, *oh;
    cudaGetSymbolAddress((void**)&qh, g_qh);
    cudaGetSymbolAddress((void**)&kh, g_kh);
    cudaGetSymbolAddress((void**)&vh, g_vh);
    cudaGetSymbolAddress((void**)&oh, g_oh);

    // 1) Q/K/V projections -> head-major [B,H,S,64]
    dim3 gp(DMODEL / 128, MROWS / 128);  // (8, 64)
    gemm128<1><<<gp, 256>>>(q, Wq, bq, qh, MROWS, DMODEL, DMODEL);
    gemm128<1><<<gp, 256>>>(k, Wk, bk, kh, MROWS, DMODEL, DMODEL);
    gemm128<1><<<gp, 256>>>(v, Wv, bv, vh, MROWS, DMODEL, DMODEL);

    // 2) Scores -> attn region (scaled by 1/8)
    dim3 gs(SEQ / 64, SEQ / 64, BATCH * NHEAD);  // (32, 32, 64)
    scores_kernel<<<gs, 256>>>(qh, kh, attn);

    // 3) Softmax rows in place
    softmax_kernel<<<BATCH * NHEAD * SEQ, 256>>>(attn);

    // 4) AV -> g_oh [B,S,H*DV]
    dim3 ga(1, SEQ / 64, BATCH * NHEAD);  // (1, 32, 64)
    av_kernel<<<ga, 256>>>(attn, vh, oh);

    // 5) Output projection -> d_out
    dim3 go(DMODEL / 128, MROWS / 128);
    gemm128<0><<<go, 256>>>(oh, Wo, bo, out, MROWS, DMODEL, DMODEL);
}

// round 3
// speedup vs baseline: 1.6188x; 1.6188x over previous
#include <cuda_runtime.h>
#include <cuda_bf16.h>
#include <cstdint>

// Problem constants
#define BATCH 4
#define SEQ   2048
#define DMODEL 1024
#define NHEAD 16
#define DHEAD 64
#define MROWS (BATCH * SEQ)                       // 8192
#define OUT_ELEMS ((size_t)BATCH * SEQ * DMODEL)  // 8388608
#define GK 3072                                   // split-bf16 K (3 x 1024)
#define SK 192                                    // split-bf16 K for scores (3 x 64)
#define NZ (BATCH * NHEAD)                        // 64 head-slices

// ---------------------------------------------------------------------------
// Scratch (device globals; allocation-free rule)
// ---------------------------------------------------------------------------
__device__ float g_vh[(size_t)NZ * SEQ * DHEAD];   // V heads fp32 [z,s,64]
__device__ float g_oh[(size_t)BATCH * SEQ * DMODEL];

// split-bf16 activations for projections: [R, 3072] = [hi | lo | hi]
__device__ __nv_bfloat16 g_qs [(size_t)MROWS * GK];
__device__ __nv_bfloat16 g_ks [(size_t)MROWS * GK];
__device__ __nv_bfloat16 g_vs [(size_t)MROWS * GK];
__device__ __nv_bfloat16 g_ohs[(size_t)MROWS * GK];
// split-bf16 weights, transposed: [N, 3072] = [hi | hi | lo]
__device__ __nv_bfloat16 g_wqs[(size_t)DMODEL * GK];
__device__ __nv_bfloat16 g_wks[(size_t)DMODEL * GK];
__device__ __nv_bfloat16 g_wvs[(size_t)DMODEL * GK];
__device__ __nv_bfloat16 g_wos[(size_t)DMODEL * GK];
// split-bf16 Q/K heads for scores: [z, s, 192]
__device__ __nv_bfloat16 g_qsp[(size_t)NZ * SEQ * SK];  // [hi|lo|hi]
__device__ __nv_bfloat16 g_ksp[(size_t)NZ * SEQ * SK];  // [hi|hi|lo]

// ---------------------------------------------------------------------------
// MMA helpers (sm_80-era PTX: valid on plain sm_103 virtual target)
// ---------------------------------------------------------------------------
__device__ __forceinline__ uint32_t smem_u32(const void* p) {
    uint32_t a;
    asm("{ .reg .u64 t; cvta.to.shared.u64 t, %1; cvt.u32.u64 %0, t; }"
        : "=r"(a) : "l"(p));
    return a;
}

#define LDSM_X4(r0, r1, r2, r3, addr)                                          \
    asm volatile("ldmatrix.sync.aligned.m8n8.x4.shared.b16 {%0,%1,%2,%3}, [%4];" \
                 : "=r"(r0), "=r"(r1), "=r"(r2), "=r"(r3) : "r"(addr))

#define MMA16816(d, a, b)                                                      \
    asm volatile("mma.sync.aligned.m16n8k16.row.col.f32.bf16.bf16.f32 "        \
                 "{%0,%1,%2,%3}, {%4,%5,%6,%7}, {%8,%9}, {%0,%1,%2,%3};"       \
                 : "+f"((d)[0]), "+f"((d)[1]), "+f"((d)[2]), "+f"((d)[3])      \
                 : "r"((a)[0]), "r"((a)[1]), "r"((a)[2]), "r"((a)[3]),         \
                   "r"((b)[0]), "r"((b)[1]))

// Shared tiles: 128x32 bf16 per operand, rows padded to 40 (80 B) to keep
// ldmatrix row-pointer banks distinct (stride 20 words, gcd(20,32)=4 cycle).
struct Tiles {
    __nv_bfloat16 A[128][40];
    __nv_bfloat16 B[128][40];
};

// Core loop: CTA 128x128, 8 warps (2 M x 4 N), K-step 32, reg prefetch.
// A row-major [*, lda] (k contiguous), B row-major [*, ldb] (k contiguous;
// i.e. B^T of the math GEMM -> mma row.col).
__device__ __forceinline__ void mma_loop_128x128(
    Tiles* t, const __nv_bfloat16* __restrict__ Abase,
    const __nv_bfloat16* __restrict__ Bbase,
    int lda, int ldb, int nIters, float acc[4][4][4])
{
    const int tid  = threadIdx.x;
    const int lane = tid & 31;
    const int warp = tid >> 5;
    const int wm = (warp >> 2) * 64;   // 0 / 64
    const int wn = (warp & 3) * 32;    // 0 / 32 / 64 / 96

    // global tile load mapping: 2 uint4 per operand per thread
    const int grow = tid >> 2;          // 0..63
    const int gcol = (tid & 3) * 8;     // bf16 col {0,8,16,24}
    const __nv_bfloat16* Ap = Abase + (size_t)grow * lda + gcol;
    const __nv_bfloat16* Bp = Bbase + (size_t)grow * ldb + gcol;

    // ldmatrix per-lane smem addresses
    const int mrow  = lane & 15;
    const int kA    = (lane & 16) ? 16 : 0;   // byte offset (8 bf16)
    const int nrow  = (lane & 7) + ((lane & 16) ? 8 : 0);
    const int kB    = (lane & 8) ? 16 : 0;
    const uint32_t sA = smem_u32(&t->A[0][0]);
    const uint32_t sB = smem_u32(&t->B[0][0]);
    const uint32_t aAddr = sA + (uint32_t)(wm + mrow) * 80u + (uint32_t)kA;
    const uint32_t bAddr = sB + (uint32_t)(wn + nrow) * 80u + (uint32_t)kB;

    uint4 ra0 = *(const uint4*)Ap;
    uint4 ra1 = *(const uint4*)(Ap + (size_t)64 * lda);
    uint4 rb0 = *(const uint4*)Bp;
    uint4 rb1 = *(const uint4*)(Bp + (size_t)64 * ldb);

    for (int it = 0; it < nIters; ++it) {
        __syncthreads();
        *(uint4*)&t->A[grow][gcol]      = ra0;
        *(uint4*)&t->A[grow + 64][gcol] = ra1;
        *(uint4*)&t->B[grow][gcol]      = rb0;
        *(uint4*)&t->B[grow + 64][gcol] = rb1;
        __syncthreads();

        if (it + 1 < nIters) {
            const __nv_bfloat16* An = Ap + (it + 1) * 32;
            const __nv_bfloat16* Bn = Bp + (it + 1) * 32;
            ra0 = *(const uint4*)An;
            ra1 = *(const uint4*)(An + (size_t)64 * lda);
            rb0 = *(const uint4*)Bn;
            rb1 = *(const uint4*)(Bn + (size_t)64 * ldb);
        }

#pragma unroll
        for (int ks = 0; ks < 2; ++ks) {
            uint32_t a[4][4], b[4][2];
#pragma unroll
            for (int mi = 0; mi < 4; ++mi)
                LDSM_X4(a[mi][0], a[mi][1], a[mi][2], a[mi][3],
                        aAddr + (uint32_t)(mi * 16 * 80 + ks * 32));
            LDSM_X4(b[0][0], b[0][1], b[1][0], b[1][1],
                    bAddr + (uint32_t)(ks * 32));
            LDSM_X4(b[2][0], b[2][1], b[3][0], b[3][1],
                    bAddr + (uint32_t)(16 * 80 + ks * 32));
#pragma unroll
            for (int mi = 0; mi < 4; ++mi)
#pragma unroll
                for (int ni = 0; ni < 4; ++ni)
                    MMA16816(acc[mi][ni], a[mi], b[ni]);
        }
    }
}

// ---------------------------------------------------------------------------
// Projection GEMM: D[8192, 1024] = A'[8192, 3072] x B'[1024, 3072]^T + bias
// MODE 0: fp32 row-major (out projection)
// MODE 1: Q split [hi|lo|hi]   -> g_qsp [z, s, 192]
// MODE 2: K split [hi|hi|lo]   -> g_ksp [z, s, 192]
// MODE 3: V fp32 head-major    -> g_vh  [z, s, 64]
// ---------------------------------------------------------------------------
template <int MODE>
__global__ __launch_bounds__(256) void proj_mma(
    const __nv_bfloat16* __restrict__ Ag, const __nv_bfloat16* __restrict__ Bg,
    const float* __restrict__ bias, float* __restrict__ Cf,
    __nv_bfloat16* __restrict__ Cs)
{
    __shared__ Tiles t;
    const int mbase = blockIdx.y * 128;
    const int nbase = blockIdx.x * 128;

    float acc[4][4][4];
#pragma unroll
    for (int i = 0; i < 4; i++)
#pragma unroll
        for (int j = 0; j < 4; j++)
#pragma unroll
            for (int r = 0; r < 4; r++) acc[i][j][r] = 0.0f;

    mma_loop_128x128(&t, Ag + (size_t)mbase * GK, Bg + (size_t)nbase * GK,
                     GK, GK, GK / 32, acc);

    const int lane = threadIdx.x & 31;
    const int warp = threadIdx.x >> 5;
    const int wm = (warp >> 2) * 64;
    const int wn = (warp & 3) * 32;
    const int g = lane >> 2, tg = lane & 3;

#pragma unroll
    for (int mi = 0; mi < 4; ++mi) {
#pragma unroll
        for (int ni = 0; ni < 4; ++ni) {
#pragma unroll
            for (int half = 0; half < 2; ++half) {
                const int m = mbase + wm + mi * 16 + g + half * 8;
                const int ncol0 = nbase + wn + ni * 8 + tg * 2;
#pragma unroll
                for (int e = 0; e < 2; ++e) {
                    const int n = ncol0 + e;
                    const float val = acc[mi][ni][half * 2 + e] + bias[n];
                    if (MODE == 0) {
                        Cf[(size_t)m * DMODEL + n] = val;
                    } else {
                        const int z = ((m >> 11) << 4) + (n >> 6);
                        const int s = m & (SEQ - 1);
                        const int d = n & 63;
                        if (MODE == 3) {
                            Cf[((size_t)z * SEQ + s) * DHEAD + d] = val;
                        } else {
                            const size_t base = ((size_t)z * SEQ + s) * SK;
                            const __nv_bfloat16 hi = __float2bfloat16(val);
                            const __nv_bfloat16 lo =
                                __float2bfloat16(val - __bfloat162float(hi));
                            if (MODE == 1) {         // Q: [hi | lo | hi]
                                Cs[base + d]        = hi;
                                Cs[base + 64 + d]   = lo;
                                Cs[base + 128 + d]  = hi;
                            } else {                 // K: [hi | hi | lo]
                                Cs[base + d]        = hi;
                                Cs[base + 64 + d]   = hi;
                                Cs[base + 128 + d]  = lo;
                            }
                        }
                    }
                }
            }
        }
    }
}

// ---------------------------------------------------------------------------
// Scores GEMM per head-slice z: attn[z,q,k] = (Qsp[q,:] . Ksp[k,:]) * 0.125
// M = N = 2048, K = 192 (split-bf16).
// ---------------------------------------------------------------------------
__global__ __launch_bounds__(256) void scores_mma(
    const __nv_bfloat16* __restrict__ qsp, const __nv_bfloat16* __restrict__ ksp,
    float* __restrict__ attn)
{
    __shared__ Tiles t;
    const int z     = blockIdx.z;
    const int qbase = blockIdx.y * 128;
    const int kbase = blockIdx.x * 128;

    float acc[4][4][4];
#pragma unroll
    for (int i = 0; i < 4; i++)
#pragma unroll
        for (int j = 0; j < 4; j++)
#pragma unroll
            for (int r = 0; r < 4; r++) acc[i][j][r] = 0.0f;

    const __nv_bfloat16* Abase = qsp + ((size_t)z * SEQ + qbase) * SK;
    const __nv_bfloat16* Bbase = ksp + ((size_t)z * SEQ + kbase) * SK;
    mma_loop_128x128(&t, Abase, Bbase, SK, SK, SK / 32, acc);

    const int lane = threadIdx.x & 31;
    const int warp = threadIdx.x >> 5;
    const int wm = (warp >> 2) * 64;
    const int wn = (warp & 3) * 32;
    const int g = lane >> 2, tg = lane & 3;

    float* out = attn + ((size_t)z * SEQ + qbase) * SEQ + kbase;
#pragma unroll
    for (int mi = 0; mi < 4; ++mi) {
#pragma unroll
        for (int ni = 0; ni < 4; ++ni) {
#pragma unroll
            for (int half = 0; half < 2; ++half) {
                const int r = wm + mi * 16 + g + half * 8;
                const int c = wn + ni * 8 + tg * 2;
                float2 v;
                v.x = acc[mi][ni][half * 2 + 0] * 0.125f;
                v.y = acc[mi][ni][half * 2 + 1] * 0.125f;
                *(float2*)&out[(size_t)r * SEQ + c] = v;
            }
        }
    }
}

// ---------------------------------------------------------------------------
// prep_act: X[R,1024] fp32 -> Y[R,3072] bf16 as [hi | lo | hi]
// ---------------------------------------------------------------------------
__global__ __launch_bounds__(256) void prep_act(
    const float* __restrict__ X, __nv_bfloat16* __restrict__ Y, int total4)
{
    int i = blockIdx.x * 256 + threadIdx.x;
    if (i >= total4) return;
    float4 xv = ((const float4*)X)[i];
    int r = i >> 8;
    int k = (i & 255) * 4;
    size_t base = (size_t)r * GK + k;

    float xs[4] = {xv.x, xv.y, xv.z, xv.w};
    __nv_bfloat16 hi[4], lo[4];
#pragma unroll
    for (int j = 0; j < 4; j++) {
        hi[j] = __float2bfloat16(xs[j]);
        lo[j] = __float2bfloat16(xs[j] - __bfloat162float(hi[j]));
    }
    *(__nv_bfloat162*)(Y + base)        = __nv_bfloat162(hi[0], hi[1]);
    *(__nv_bfloat162*)(Y + base + 2)    = __nv_bfloat162(hi[2], hi[3]);
    *(__nv_bfloat162*)(Y + base + 1024) = __nv_bfloat162(lo[0], lo[1]);
    *(__nv_bfloat162*)(Y + base + 1026) = __nv_bfloat162(lo[2], lo[3]);
    *(__nv_bfloat162*)(Y + base + 2048) = __nv_bfloat162(hi[0], hi[1]);
    *(__nv_bfloat162*)(Y + base + 2050) = __nv_bfloat162(hi[2], hi[3]);
}

// ---------------------------------------------------------------------------
// prep_wgt: W[1024,1024] fp32 (K rows) -> Ws[N=1024, 3072] bf16 [hi|hi|lo]
// ---------------------------------------------------------------------------
__global__ __launch_bounds__(256) void prep_wgt(
    const float* __restrict__ W, __nv_bfloat16* __restrict__ Ws)
{
    __shared__ float t[32][33];
    const int k0 = blockIdx.y * 32, n0 = blockIdx.x * 32;
    const int tx = threadIdx.x, ty = threadIdx.y;   // (32, 8)
#pragma unroll
    for (int r = ty; r < 32; r += 8)
        t[r][tx] = W[(size_t)(k0 + r) * DMODEL + n0 + tx];
    __syncthreads();
#pragma unroll
    for (int r = ty; r < 32; r += 8) {
        const int n = n0 + r;
        const int k = k0 + tx;
        const float x = t[tx][r];
        __nv_bfloat16 hi = __float2bfloat16(x);
        __nv_bfloat16 lo = __float2bfloat16(x - __bfloat162float(hi));
        size_t base = (size_t)n * GK;
        Ws[base + k]        = hi;
        Ws[base + 1024 + k] = hi;
        Ws[base + 2048 + k] = lo;
    }
}

// ---------------------------------------------------------------------------
// Row softmax over 2048 elements, in place.
// ---------------------------------------------------------------------------
__global__ __launch_bounds__(256) void softmax_kernel(float* __restrict__ attn)
{
    const size_t row = blockIdx.x;
    float* x = attn + row * (size_t)SEQ;
    const int tid = threadIdx.x;

    float4 v0 = ((float4*)x)[tid * 2];
    float4 v1 = ((float4*)x)[tid * 2 + 1];

    float m = fmaxf(fmaxf(fmaxf(v0.x, v0.y), fmaxf(v0.z, v0.w)),
                    fmaxf(fmaxf(v1.x, v1.y), fmaxf(v1.z, v1.w)));

    __shared__ float red[8];
#pragma unroll
    for (int o = 16; o; o >>= 1) m = fmaxf(m, __shfl_xor_sync(0xffffffffu, m, o));
    if ((tid & 31) == 0) red[tid >> 5] = m;
    __syncthreads();
    m = red[0];
#pragma unroll
    for (int i = 1; i < 8; i++) m = fmaxf(m, red[i]);
    __syncthreads();

    v0.x = __expf(v0.x - m); v0.y = __expf(v0.y - m);
    v0.z = __expf(v0.z - m); v0.w = __expf(v0.w - m);
    v1.x = __expf(v1.x - m); v1.y = __expf(v1.y - m);
    v1.z = __expf(v1.z - m); v1.w = __expf(v1.w - m);

    float s = v0.x + v0.y + v0.z + v0.w + v1.x + v1.y + v1.z + v1.w;
#pragma unroll
    for (int o = 16; o; o >>= 1) s += __shfl_xor_sync(0xffffffffu, s, o);
    if ((tid & 31) == 0) red[tid >> 5] = s;
    __syncthreads();
    s = red[0] + red[1] + red[2] + red[3] + red[4] + red[5] + red[6] + red[7];
    const float inv = 1.0f / s;

    v0.x *= inv; v0.y *= inv; v0.z *= inv; v0.w *= inv;
    v1.x *= inv; v1.y *= inv; v1.z *= inv; v1.w *= inv;
    ((float4*)x)[tid * 2]     = v0;
    ((float4*)x)[tid * 2 + 1] = v1;
}

// ---------------------------------------------------------------------------
// AV: per z: O[q,dv] = sum_k P[q,k] * Vh[k,dv] (fp32)
// ---------------------------------------------------------------------------
__global__ __launch_bounds__(256) void av_kernel(
    const float* __restrict__ attn, const float* __restrict__ vh,
    float* __restrict__ oh)
{
    const int z = blockIdx.z;
    const int b = z >> 4, h = z & 15;
    const float* A  = attn + (size_t)z * SEQ * SEQ;
    const float* Bv = vh   + (size_t)z * SEQ * DHEAD;
    float* C = oh + (size_t)b * SEQ * DMODEL + h * DHEAD;

    const int rowBase = blockIdx.y * 64;
    __shared__ float As[16][64];
    __shared__ float Bs[16][64];
    const int tid = threadIdx.x;
    const int ar = tid >> 2, ak = (tid & 3) * 4;
    const int bk = tid >> 4, bn = (tid & 15) * 4;
    const int tr = tid >> 4, tc = tid & 15;

    float acc[4][4];
#pragma unroll
    for (int i = 0; i < 4; i++)
#pragma unroll
        for (int j = 0; j < 4; j++) acc[i][j] = 0.0f;

    for (int k0 = 0; k0 < SEQ; k0 += 16) {
        float4 av = *(const float4*)&A[(size_t)(rowBase + ar) * SEQ + k0 + ak];
        As[ak + 0][ar] = av.x; As[ak + 1][ar] = av.y;
        As[ak + 2][ar] = av.z; As[ak + 3][ar] = av.w;
        *(float4*)&Bs[bk][bn] = *(const float4*)&Bv[(size_t)(k0 + bk) * DHEAD + bn];
        __syncthreads();
#pragma unroll
        for (int kk = 0; kk < 16; kk++) {
            float4 a = *(const float4*)&As[kk][tr * 4];
            float4 b = *(const float4*)&Bs[kk][tc * 4];
            acc[0][0] += a.x * b.x; acc[0][1] += a.x * b.y; acc[0][2] += a.x * b.z; acc[0][3] += a.x * b.w;
            acc[1][0] += a.y * b.x; acc[1][1] += a.y * b.y; acc[1][2] += a.y * b.z; acc[1][3] += a.y * b.w;
            acc[2][0] += a.z * b.x; acc[2][1] += a.z * b.y; acc[2][2] += a.z * b.z; acc[2][3] += a.z * b.w;
            acc[3][0] += a.w * b.x; acc[3][1] += a.w * b.y; acc[3][2] += a.w * b.z; acc[3][3] += a.w * b.w;
        }
        __syncthreads();
    }

#pragma unroll
    for (int i = 0; i < 4; i++) {
        const size_t rowoff = (size_t)(rowBase + tr * 4 + i) * DMODEL;
#pragma unroll
        for (int j = 0; j < 4; j++)
            C[rowoff + tc * 4 + j] = acc[i][j];
    }
}

// ---------------------------------------------------------------------------
extern "C" void kernel_launch(void* const* d_in, const int* in_sizes, int n_in,
                              void* d_out, int out_size)
{
    const float* q  = (const float*)d_in[0];
    const float* k  = (const float*)d_in[1];
    const float* v  = (const float*)d_in[2];
    const float* Wq = (const float*)d_in[3];
    const float* bq = (const float*)d_in[4];
    const float* Wk = (const float*)d_in[5];
    const float* bk = (const float*)d_in[6];
    const float* Wv = (const float*)d_in[7];
    const float* bv = (const float*)d_in[8];
    const float* Wo = (const float*)d_in[9];
    const float* bo = (const float*)d_in[10];

    float* out  = (float*)d_out;
    float* attn = out + OUT_ELEMS;

    float *vh, *oh;
    cudaGetSymbolAddress((void**)&vh, g_vh);
    cudaGetSymbolAddress((void**)&oh, g_oh);
    __nv_bfloat16 *qs, *ks, *vs, *ohs, *wqs, *wks, *wvs, *wos, *qsp, *ksp;
    cudaGetSymbolAddress((void**)&qs,  g_qs);
    cudaGetSymbolAddress((void**)&ks,  g_ks);
    cudaGetSymbolAddress((void**)&vs,  g_vs);
    cudaGetSymbolAddress((void**)&ohs, g_ohs);
    cudaGetSymbolAddress((void**)&wqs, g_wqs);
    cudaGetSymbolAddress((void**)&wks, g_wks);
    cudaGetSymbolAddress((void**)&wvs, g_wvs);
    cudaGetSymbolAddress((void**)&wos, g_wos);
    cudaGetSymbolAddress((void**)&qsp, g_qsp);
    cudaGetSymbolAddress((void**)&ksp, g_ksp);

    const int act4 = MROWS * DMODEL / 4;
    dim3 wgrid(32, 32);
    dim3 wblk(32, 8);
    dim3 ggrid(DMODEL / 128, MROWS / 128);  // (8, 64)

    // 0) split-bf16 conversions
    prep_wgt<<<wgrid, wblk>>>(Wq, wqs);
    prep_wgt<<<wgrid, wblk>>>(Wk, wks);
    prep_wgt<<<wgrid, wblk>>>(Wv, wvs);
    prep_wgt<<<wgrid, wblk>>>(Wo, wos);
    prep_act<<<(act4 + 255) / 256, 256>>>(q, qs, act4);
    prep_act<<<(act4 + 255) / 256, 256>>>(k, ks, act4);
    prep_act<<<(act4 + 255) / 256, 256>>>(v, vs, act4);

    // 1) Q/K/V projections (HMMA). Q/K -> split heads, V -> fp32 heads.
    proj_mma<1><<<ggrid, 256>>>(qs, wqs, bq, nullptr, qsp);
    proj_mma<2><<<ggrid, 256>>>(ks, wks, bk, nullptr, ksp);
    proj_mma<3><<<ggrid, 256>>>(vs, wvs, bv, vh, nullptr);

    // 2) Scores (HMMA, split-bf16, K=192) -> attn region
    dim3 gs(SEQ / 128, SEQ / 128, NZ);  // (16, 16, 64)
    scores_mma<<<gs, 256>>>(qsp, ksp, attn);

    // 3) Softmax rows in place
    softmax_kernel<<<NZ * SEQ, 256>>>(attn);

    // 4) AV -> g_oh [B,S,H*DV] (fp32)
    dim3 ga(1, SEQ / 64, NZ);
    av_kernel<<<ga, 256>>>(attn, vh, oh);

    // 5) Output projection (HMMA) -> d_out
    prep_act<<<(act4 + 255) / 256, 256>>>(oh, ohs, act4);
    proj_mma<0><<<ggrid, 256>>>(ohs, wos, bo, out, nullptr);
}

// round 4
// speedup vs baseline: 1.9816x; 1.2241x over previous
#include <cuda_runtime.h>
#include <cuda_bf16.h>
#include <cstdint>

// Problem constants
#define BATCH 4
#define SEQ   2048
#define DMODEL 1024
#define NHEAD 16
#define DHEAD 64
#define MROWS (BATCH * SEQ)                       // 8192
#define OUT_ELEMS ((size_t)BATCH * SEQ * DMODEL)  // 8388608
#define GK 3072                                   // split-bf16 K (3 x 1024)
#define SK 192                                    // split-bf16 K for scores (3 x 64)
#define NZ (BATCH * NHEAD)                        // 64 head-slices
#define VK 6144                                   // split K_eff for AV (3 x 2048)

// ---------------------------------------------------------------------------
// Scratch (device globals; allocation-free rule)
// ---------------------------------------------------------------------------
__device__ float g_oh[(size_t)BATCH * SEQ * DMODEL];

// split-bf16 activations for projections: [R, 3072] = [hi | lo | hi]
__device__ __nv_bfloat16 g_qs [(size_t)MROWS * GK];
__device__ __nv_bfloat16 g_ks [(size_t)MROWS * GK];
__device__ __nv_bfloat16 g_vs [(size_t)MROWS * GK];
__device__ __nv_bfloat16 g_ohs[(size_t)MROWS * GK];
// split-bf16 weights, transposed: [N, 3072] = [hi | hi | lo]
__device__ __nv_bfloat16 g_wqs[(size_t)DMODEL * GK];
__device__ __nv_bfloat16 g_wks[(size_t)DMODEL * GK];
__device__ __nv_bfloat16 g_wvs[(size_t)DMODEL * GK];
__device__ __nv_bfloat16 g_wos[(size_t)DMODEL * GK];
// split-bf16 Q/K heads for scores: [z, s, 192]
__device__ __nv_bfloat16 g_qsp[(size_t)NZ * SEQ * SK];  // [hi|lo|hi]
__device__ __nv_bfloat16 g_ksp[(size_t)NZ * SEQ * SK];  // [hi|hi|lo]
// split-bf16 V^T for AV: [z, d(64), 6144] with per-32-chunk [Vhi|Vhi|Vlo]
__device__ __nv_bfloat16 g_vsp[(size_t)NZ * DHEAD * VK];

// ---------------------------------------------------------------------------
// MMA helpers (sm_80-era PTX: valid on plain sm_103 virtual target)
// ---------------------------------------------------------------------------
__device__ __forceinline__ uint32_t smem_u32(const void* p) {
    uint32_t a;
    asm("{ .reg .u64 t; cvta.to.shared.u64 t, %1; cvt.u32.u64 %0, t; }"
        : "=r"(a) : "l"(p));
    return a;
}

#define LDSM_X4(r0, r1, r2, r3, addr)                                          \
    asm volatile("ldmatrix.sync.aligned.m8n8.x4.shared.b16 {%0,%1,%2,%3}, [%4];" \
                 : "=r"(r0), "=r"(r1), "=r"(r2), "=r"(r3) : "r"(addr))

#define MMA16816(d, a, b)                                                      \
    asm volatile("mma.sync.aligned.m16n8k16.row.col.f32.bf16.bf16.f32 "        \
                 "{%0,%1,%2,%3}, {%4,%5,%6,%7}, {%8,%9}, {%0,%1,%2,%3};"       \
                 : "+f"((d)[0]), "+f"((d)[1]), "+f"((d)[2]), "+f"((d)[3])      \
                 : "r"((a)[0]), "r"((a)[1]), "r"((a)[2]), "r"((a)[3]),         \
                   "r"((b)[0]), "r"((b)[1]))

// Shared tiles: 128x32 bf16 per operand, rows padded to 40 (80 B).
struct Tiles {
    __nv_bfloat16 A[128][40];
    __nv_bfloat16 B[128][40];
};

// Core loop: CTA 128x128, 8 warps (2 M x 4 N), K-step 32, reg prefetch.
__device__ __forceinline__ void mma_loop_128x128(
    Tiles* t, const __nv_bfloat16* __restrict__ Abase,
    const __nv_bfloat16* __restrict__ Bbase,
    int lda, int ldb, int nIters, float acc[4][4][4])
{
    const int tid  = threadIdx.x;
    const int lane = tid & 31;
    const int warp = tid >> 5;
    const int wm = (warp >> 2) * 64;
    const int wn = (warp & 3) * 32;

    const int grow = tid >> 2;
    const int gcol = (tid & 3) * 8;
    const __nv_bfloat16* Ap = Abase + (size_t)grow * lda + gcol;
    const __nv_bfloat16* Bp = Bbase + (size_t)grow * ldb + gcol;

    const int mrow  = lane & 15;
    const int kA    = (lane & 16) ? 16 : 0;
    const int nrow  = (lane & 7) + ((lane & 16) ? 8 : 0);
    const int kB    = (lane & 8) ? 16 : 0;
    const uint32_t sA = smem_u32(&t->A[0][0]);
    const uint32_t sB = smem_u32(&t->B[0][0]);
    const uint32_t aAddr = sA + (uint32_t)(wm + mrow) * 80u + (uint32_t)kA;
    const uint32_t bAddr = sB + (uint32_t)(wn + nrow) * 80u + (uint32_t)kB;

    uint4 ra0 = *(const uint4*)Ap;
    uint4 ra1 = *(const uint4*)(Ap + (size_t)64 * lda);
    uint4 rb0 = *(const uint4*)Bp;
    uint4 rb1 = *(const uint4*)(Bp + (size_t)64 * ldb);

    for (int it = 0; it < nIters; ++it) {
        __syncthreads();
        *(uint4*)&t->A[grow][gcol]      = ra0;
        *(uint4*)&t->A[grow + 64][gcol] = ra1;
        *(uint4*)&t->B[grow][gcol]      = rb0;
        *(uint4*)&t->B[grow + 64][gcol] = rb1;
        __syncthreads();

        if (it + 1 < nIters) {
            const __nv_bfloat16* An = Ap + (it + 1) * 32;
            const __nv_bfloat16* Bn = Bp + (it + 1) * 32;
            ra0 = *(const uint4*)An;
            ra1 = *(const uint4*)(An + (size_t)64 * lda);
            rb0 = *(const uint4*)Bn;
            rb1 = *(const uint4*)(Bn + (size_t)64 * ldb);
        }

#pragma unroll
        for (int ks = 0; ks < 2; ++ks) {
            uint32_t a[4][4], b[4][2];
#pragma unroll
            for (int mi = 0; mi < 4; ++mi)
                LDSM_X4(a[mi][0], a[mi][1], a[mi][2], a[mi][3],
                        aAddr + (uint32_t)(mi * 16 * 80 + ks * 32));
            LDSM_X4(b[0][0], b[0][1], b[1][0], b[1][1],
                    bAddr + (uint32_t)(ks * 32));
            LDSM_X4(b[2][0], b[2][1], b[3][0], b[3][1],
                    bAddr + (uint32_t)(16 * 80 + ks * 32));
#pragma unroll
            for (int mi = 0; mi < 4; ++mi)
#pragma unroll
                for (int ni = 0; ni < 4; ++ni)
                    MMA16816(acc[mi][ni], a[mi], b[ni]);
        }
    }
}

// ---------------------------------------------------------------------------
// Projection GEMM: D[8192, 1024] = A'[8192, 3072] x B'[1024, 3072]^T + bias
// MODE 0: fp32 row-major (out projection)
// MODE 1: Q split [hi|lo|hi]   -> g_qsp [z, s, 192]
// MODE 2: K split [hi|hi|lo]   -> g_ksp [z, s, 192]
// MODE 3: V split transposed   -> g_vsp [z, d, 6144] chunks [hi|hi|lo]
// ---------------------------------------------------------------------------
template <int MODE>
__global__ __launch_bounds__(256) void proj_mma(
    const __nv_bfloat16* __restrict__ Ag, const __nv_bfloat16* __restrict__ Bg,
    const float* __restrict__ bias, float* __restrict__ Cf,
    __nv_bfloat16* __restrict__ Cs)
{
    __shared__ Tiles t;
    const int mbase = blockIdx.y * 128;
    const int nbase = blockIdx.x * 128;

    float acc[4][4][4];
#pragma unroll
    for (int i = 0; i < 4; i++)
#pragma unroll
        for (int j = 0; j < 4; j++)
#pragma unroll
            for (int r = 0; r < 4; r++) acc[i][j][r] = 0.0f;

    mma_loop_128x128(&t, Ag + (size_t)mbase * GK, Bg + (size_t)nbase * GK,
                     GK, GK, GK / 32, acc);

    const int lane = threadIdx.x & 31;
    const int warp = threadIdx.x >> 5;
    const int wm = (warp >> 2) * 64;
    const int wn = (warp & 3) * 32;
    const int g = lane >> 2, tg = lane & 3;

#pragma unroll
    for (int mi = 0; mi < 4; ++mi) {
#pragma unroll
        for (int ni = 0; ni < 4; ++ni) {
#pragma unroll
            for (int half = 0; half < 2; ++half) {
                const int m = mbase + wm + mi * 16 + g + half * 8;
                const int ncol0 = nbase + wn + ni * 8 + tg * 2;
#pragma unroll
                for (int e = 0; e < 2; ++e) {
                    const int n = ncol0 + e;
                    const float val = acc[mi][ni][half * 2 + e] + bias[n];
                    if (MODE == 0) {
                        Cf[(size_t)m * DMODEL + n] = val;
                    } else {
                        const int z = ((m >> 11) << 4) + (n >> 6);
                        const int s = m & (SEQ - 1);
                        const int d = n & 63;
                        const __nv_bfloat16 hi = __float2bfloat16(val);
                        const __nv_bfloat16 lo =
                            __float2bfloat16(val - __bfloat162float(hi));
                        if (MODE == 1) {         // Q: [hi | lo | hi]
                            const size_t base = ((size_t)z * SEQ + s) * SK;
                            Cs[base + d]        = hi;
                            Cs[base + 64 + d]   = lo;
                            Cs[base + 128 + d]  = hi;
                        } else if (MODE == 2) {  // K: [hi | hi | lo]
                            const size_t base = ((size_t)z * SEQ + s) * SK;
                            Cs[base + d]        = hi;
                            Cs[base + 64 + d]   = hi;
                            Cs[base + 128 + d]  = lo;
                        } else {                 // V^T split for AV
                            const size_t base =
                                ((size_t)z * DHEAD + d) * VK + 96 * (s >> 5) + (s & 31);
                            Cs[base]       = hi;
                            Cs[base + 32]  = hi;
                            Cs[base + 64]  = lo;
                        }
                    }
                }
            }
        }
    }
}

// ---------------------------------------------------------------------------
// Scores GEMM per head-slice z: attn[z,q,k] = (Qsp[q,:] . Ksp[k,:]) * 0.125
// ---------------------------------------------------------------------------
__global__ __launch_bounds__(256) void scores_mma(
    const __nv_bfloat16* __restrict__ qsp, const __nv_bfloat16* __restrict__ ksp,
    float* __restrict__ attn)
{
    __shared__ Tiles t;
    const int z     = blockIdx.z;
    const int qbase = blockIdx.y * 128;
    const int kbase = blockIdx.x * 128;

    float acc[4][4][4];
#pragma unroll
    for (int i = 0; i < 4; i++)
#pragma unroll
        for (int j = 0; j < 4; j++)
#pragma unroll
            for (int r = 0; r < 4; r++) acc[i][j][r] = 0.0f;

    const __nv_bfloat16* Abase = qsp + ((size_t)z * SEQ + qbase) * SK;
    const __nv_bfloat16* Bbase = ksp + ((size_t)z * SEQ + kbase) * SK;
    mma_loop_128x128(&t, Abase, Bbase, SK, SK, SK / 32, acc);

    const int lane = threadIdx.x & 31;
    const int warp = threadIdx.x >> 5;
    const int wm = (warp >> 2) * 64;
    const int wn = (warp & 3) * 32;
    const int g = lane >> 2, tg = lane & 3;

    float* out = attn + ((size_t)z * SEQ + qbase) * SEQ + kbase;
#pragma unroll
    for (int mi = 0; mi < 4; ++mi) {
#pragma unroll
        for (int ni = 0; ni < 4; ++ni) {
#pragma unroll
            for (int half = 0; half < 2; ++half) {
                const int r = wm + mi * 16 + g + half * 8;
                const int c = wn + ni * 8 + tg * 2;
                float2 v;
                v.x = acc[mi][ni][half * 2 + 0] * 0.125f;
                v.y = acc[mi][ni][half * 2 + 1] * 0.125f;
                *(float2*)&out[(size_t)r * SEQ + c] = v;
            }
        }
    }
}

// ---------------------------------------------------------------------------
// AV GEMM (HMMA, in-kernel split of P):
// per z: O[q, d] = sum_k P[q,k] V[k,d], CTA tile M=128 x N=64, K_eff = 6144.
// P fp32 converted on the fly to [hi|lo|hi] per 32-chunk; V pre-split in g_vsp.
// 8 warps, warp tile 32x32 (4 M x 2 N).
// ---------------------------------------------------------------------------
__global__ __launch_bounds__(256) void av_mma(
    const float* __restrict__ attn, const __nv_bfloat16* __restrict__ vsp,
    float* __restrict__ oh)
{
    __shared__ __nv_bfloat16 Asm[3][128][40];
    __shared__ __nv_bfloat16 Bsm[3][64][40];

    const int z = blockIdx.y;
    const int mbase = blockIdx.x * 128;
    const int b = z >> 4, h = z & 15;
    const int tid = threadIdx.x, lane = tid & 31, warp = tid >> 5;
    const int wm = (warp >> 1) * 32, wn = (warp & 1) * 32;

    const float* P = attn + ((size_t)z * SEQ + mbase) * SEQ;
    const __nv_bfloat16* Vb = vsp + (size_t)z * DHEAD * VK;

    float acc[2][4][4];
#pragma unroll
    for (int i = 0; i < 2; i++)
#pragma unroll
        for (int j = 0; j < 4; j++)
#pragma unroll
            for (int r = 0; r < 4; r++) acc[i][j][r] = 0.0f;

    const uint32_t sA = smem_u32(&Asm[0][0][0]);
    const uint32_t sB = smem_u32(&Bsm[0][0][0]);
    const int mrow = lane & 15;
    const int kA = (lane & 16) ? 16 : 0;
    const int nr = (lane & 7) + ((lane & 16) ? 8 : 0);
    const int kB = (lane & 8) ? 16 : 0;

    // prefetch it=0
    float4 pa[4];
    uint4  pb[3];
#pragma unroll
    for (int i = 0; i < 4; ++i) {
        const int idx = tid + i * 256;
        const int row = idx >> 3, c4 = (idx & 7) * 4;
        pa[i] = *(const float4*)&P[(size_t)row * SEQ + c4];
    }
#pragma unroll
    for (int i = 0; i < 3; ++i) {
        const int idx = tid + i * 256;
        const int d = idx / 12, jc = (idx % 12) * 8;
        pb[i] = *(const uint4*)&Vb[(size_t)d * VK + jc];
    }

    for (int it = 0; it < SEQ / 32; ++it) {
        __syncthreads();
        // convert + store A (P chunk -> [hi|lo|hi])
#pragma unroll
        for (int i = 0; i < 4; ++i) {
            const int idx = tid + i * 256;
            const int row = idx >> 3, c4 = (idx & 7) * 4;
            float xs[4] = {pa[i].x, pa[i].y, pa[i].z, pa[i].w};
            __nv_bfloat16 hi[4], lo[4];
#pragma unroll
            for (int j = 0; j < 4; ++j) {
                hi[j] = __float2bfloat16(xs[j]);
                lo[j] = __float2bfloat16(xs[j] - __bfloat162float(hi[j]));
            }
            uint2 hp, lp;
            hp.x = *(const uint32_t*)&__nv_bfloat162(hi[0], hi[1]);
            hp.y = *(const uint32_t*)&__nv_bfloat162(hi[2], hi[3]);
            lp.x = *(const uint32_t*)&__nv_bfloat162(lo[0], lo[1]);
            lp.y = *(const uint32_t*)&__nv_bfloat162(lo[2], lo[3]);
            *(uint2*)&Asm[0][row][c4] = hp;
            *(uint2*)&Asm[1][row][c4] = lp;
            *(uint2*)&Asm[2][row][c4] = hp;
        }
        // store B
#pragma unroll
        for (int i = 0; i < 3; ++i) {
            const int idx = tid + i * 256;
            const int d = idx / 12, jc = (idx % 12) * 8;
            *(uint4*)&Bsm[jc >> 5][d][jc & 31] = pb[i];
        }
        __syncthreads();

        if (it + 1 < SEQ / 32) {
#pragma unroll
            for (int i = 0; i < 4; ++i) {
                const int idx = tid + i * 256;
                const int row = idx >> 3, c4 = (idx & 7) * 4;
                pa[i] = *(const float4*)&P[(size_t)row * SEQ + (it + 1) * 32 + c4];
            }
#pragma unroll
            for (int i = 0; i < 3; ++i) {
                const int idx = tid + i * 256;
                const int d = idx / 12, jc = (idx % 12) * 8;
                pb[i] = *(const uint4*)&Vb[(size_t)d * VK + (it + 1) * 96 + jc];
            }
        }

#pragma unroll
        for (int sub = 0; sub < 3; ++sub) {
            const uint32_t aBase = sA + (uint32_t)sub * (128 * 80);
            const uint32_t bBase = sB + (uint32_t)sub * (64 * 80);
#pragma unroll
            for (int ks = 0; ks < 2; ++ks) {
                uint32_t a[2][4], bq[4][2];
#pragma unroll
                for (int mi = 0; mi < 2; ++mi)
                    LDSM_X4(a[mi][0], a[mi][1], a[mi][2], a[mi][3],
                            aBase + (uint32_t)((wm + mi * 16 + mrow) * 80 + kA + ks * 32));
                LDSM_X4(bq[0][0], bq[0][1], bq[1][0], bq[1][1],
                        bBase + (uint32_t)((wn + nr) * 80 + kB + ks * 32));
                LDSM_X4(bq[2][0], bq[2][1], bq[3][0], bq[3][1],
                        bBase + (uint32_t)((wn + 16 + nr) * 80 + kB + ks * 32));
#pragma unroll
                for (int mi = 0; mi < 2; ++mi)
#pragma unroll
                    for (int ni = 0; ni < 4; ++ni)
                        MMA16816(acc[mi][ni], a[mi], bq[ni]);
            }
        }
    }

    // epilogue -> oh[b, s, h*64 + d]
    const int g = lane >> 2, tg = lane & 3;
#pragma unroll
    for (int mi = 0; mi < 2; ++mi) {
#pragma unroll
        for (int ni = 0; ni < 4; ++ni) {
#pragma unroll
            for (int half = 0; half < 2; ++half) {
                const int r = wm + mi * 16 + g + half * 8;
                const int c = wn + ni * 8 + tg * 2;
                float2 v;
                v.x = acc[mi][ni][half * 2 + 0];
                v.y = acc[mi][ni][half * 2 + 1];
                *(float2*)&oh[((size_t)b * SEQ + mbase + r) * DMODEL + h * DHEAD + c] = v;
            }
        }
    }
}

// ---------------------------------------------------------------------------
// prep_act: X[R,1024] fp32 -> Y[R,3072] bf16 as [hi | lo | hi]
// ---------------------------------------------------------------------------
__global__ __launch_bounds__(256) void prep_act(
    const float* __restrict__ X, __nv_bfloat16* __restrict__ Y, int total4)
{
    int i = blockIdx.x * 256 + threadIdx.x;
    if (i >= total4) return;
    float4 xv = ((const float4*)X)[i];
    int r = i >> 8;
    int k = (i & 255) * 4;
    size_t base = (size_t)r * GK + k;

    float xs[4] = {xv.x, xv.y, xv.z, xv.w};
    __nv_bfloat16 hi[4], lo[4];
#pragma unroll
    for (int j = 0; j < 4; j++) {
        hi[j] = __float2bfloat16(xs[j]);
        lo[j] = __float2bfloat16(xs[j] - __bfloat162float(hi[j]));
    }
    *(__nv_bfloat162*)(Y + base)        = __nv_bfloat162(hi[0], hi[1]);
    *(__nv_bfloat162*)(Y + base + 2)    = __nv_bfloat162(hi[2], hi[3]);
    *(__nv_bfloat162*)(Y + base + 1024) = __nv_bfloat162(lo[0], lo[1]);
    *(__nv_bfloat162*)(Y + base + 1026) = __nv_bfloat162(lo[2], lo[3]);
    *(__nv_bfloat162*)(Y + base + 2048) = __nv_bfloat162(hi[0], hi[1]);
    *(__nv_bfloat162*)(Y + base + 2050) = __nv_bfloat162(hi[2], hi[3]);
}

// ---------------------------------------------------------------------------
// prep_wgt: W[1024,1024] fp32 (K rows) -> Ws[N=1024, 3072] bf16 [hi|hi|lo]
// ---------------------------------------------------------------------------
__global__ __launch_bounds__(256) void prep_wgt(
    const float* __restrict__ W, __nv_bfloat16* __restrict__ Ws)
{
    __shared__ float t[32][33];
    const int k0 = blockIdx.y * 32, n0 = blockIdx.x * 32;
    const int tx = threadIdx.x, ty = threadIdx.y;   // (32, 8)
#pragma unroll
    for (int r = ty; r < 32; r += 8)
        t[r][tx] = W[(size_t)(k0 + r) * DMODEL + n0 + tx];
    __syncthreads();
#pragma unroll
    for (int r = ty; r < 32; r += 8) {
        const int n = n0 + r;
        const int k = k0 + tx;
        const float x = t[tx][r];
        __nv_bfloat16 hi = __float2bfloat16(x);
        __nv_bfloat16 lo = __float2bfloat16(x - __bfloat162float(hi));
        size_t base = (size_t)n * GK;
        Ws[base + k]        = hi;
        Ws[base + 1024 + k] = hi;
        Ws[base + 2048 + k] = lo;
    }
}

// ---------------------------------------------------------------------------
// Row softmax over 2048 elements, in place.
// ---------------------------------------------------------------------------
__global__ __launch_bounds__(256) void softmax_kernel(float* __restrict__ attn)
{
    const size_t row = blockIdx.x;
    float* x = attn + row * (size_t)SEQ;
    const int tid = threadIdx.x;

    float4 v0 = ((float4*)x)[tid * 2];
    float4 v1 = ((float4*)x)[tid * 2 + 1];

    float m = fmaxf(fmaxf(fmaxf(v0.x, v0.y), fmaxf(v0.z, v0.w)),
                    fmaxf(fmaxf(v1.x, v1.y), fmaxf(v1.z, v1.w)));

    __shared__ float red[8];
#pragma unroll
    for (int o = 16; o; o >>= 1) m = fmaxf(m, __shfl_xor_sync(0xffffffffu, m, o));
    if ((tid & 31) == 0) red[tid >> 5] = m;
    __syncthreads();
    m = red[0];
#pragma unroll
    for (int i = 1; i < 8; i++) m = fmaxf(m, red[i]);
    __syncthreads();

    v0.x = __expf(v0.x - m); v0.y = __expf(v0.y - m);
    v0.z = __expf(v0.z - m); v0.w = __expf(v0.w - m);
    v1.x = __expf(v1.x - m); v1.y = __expf(v1.y - m);
    v1.z = __expf(v1.z - m); v1.w = __expf(v1.w - m);

    float s = v0.x + v0.y + v0.z + v0.w + v1.x + v1.y + v1.z + v1.w;
#pragma unroll
    for (int o = 16; o; o >>= 1) s += __shfl_xor_sync(0xffffffffu, s, o);
    if ((tid & 31) == 0) red[tid >> 5] = s;
    __syncthreads();
    s = red[0] + red[1] + red[2] + red[3] + red[4] + red[5] + red[6] + red[7];
    const float inv = 1.0f / s;

    v0.x *= inv; v0.y *= inv; v0.z *= inv; v0.w *= inv;
    v1.x *= inv; v1.y *= inv; v1.z *= inv; v1.w *= inv;
    ((float4*)x)[tid * 2]     = v0;
    ((float4*)x)[tid * 2 + 1] = v1;
}

// ---------------------------------------------------------------------------
extern "C" void kernel_launch(void* const* d_in, const int* in_sizes, int n_in,
                              void* d_out, int out_size)
{
    const float* q  = (const float*)d_in[0];
    const float* k  = (const float*)d_in[1];
    const float* v  = (const float*)d_in[2];
    const float* Wq = (const float*)d_in[3];
    const float* bq = (const float*)d_in[4];
    const float* Wk = (const float*)d_in[5];
    const float* bk = (const float*)d_in[6];
    const float* Wv = (const float*)d_in[7];
    const float* bv = (const float*)d_in[8];
    const float* Wo = (const float*)d_in[9];
    const float* bo = (const float*)d_in[10];

    float* out  = (float*)d_out;
    float* attn = out + OUT_ELEMS;

    float* oh;
    cudaGetSymbolAddress((void**)&oh, g_oh);
    __nv_bfloat16 *qs, *ks, *vs, *ohs, *wqs, *wks, *wvs, *wos, *qsp, *ksp, *vsp;
    cudaGetSymbolAddress((void**)&qs,  g_qs);
    cudaGetSymbolAddress((void**)&ks,  g_ks);
    cudaGetSymbolAddress((void**)&vs,  g_vs);
    cudaGetSymbolAddress((void**)&ohs, g_ohs);
    cudaGetSymbolAddress((void**)&wqs, g_wqs);
    cudaGetSymbolAddress((void**)&wks, g_wks);
    cudaGetSymbolAddress((void**)&wvs, g_wvs);
    cudaGetSymbolAddress((void**)&wos, g_wos);
    cudaGetSymbolAddress((void**)&qsp, g_qsp);
    cudaGetSymbolAddress((void**)&ksp, g_ksp);
    cudaGetSymbolAddress((void**)&vsp, g_vsp);

    const int act4 = MROWS * DMODEL / 4;
    dim3 wgrid(32, 32);
    dim3 wblk(32, 8);
    dim3 ggrid(DMODEL / 128, MROWS / 128);  // (8, 64)

    // 0) split-bf16 conversions
    prep_wgt<<<wgrid, wblk>>>(Wq, wqs);
    prep_wgt<<<wgrid, wblk>>>(Wk, wks);
    prep_wgt<<<wgrid, wblk>>>(Wv, wvs);
    prep_wgt<<<wgrid, wblk>>>(Wo, wos);
    prep_act<<<(act4 + 255) / 256, 256>>>(q, qs, act4);
    prep_act<<<(act4 + 255) / 256, 256>>>(k, ks, act4);
    prep_act<<<(act4 + 255) / 256, 256>>>(v, vs, act4);

    // 1) Q/K/V projections (HMMA). Q/K -> split heads, V -> split V^T.
    proj_mma<1><<<ggrid, 256>>>(qs, wqs, bq, nullptr, qsp);
    proj_mma<2><<<ggrid, 256>>>(ks, wks, bk, nullptr, ksp);
    proj_mma<3><<<ggrid, 256>>>(vs, wvs, bv, nullptr, vsp);

    // 2) Scores (HMMA, split-bf16, K=192) -> attn region
    dim3 gs(SEQ / 128, SEQ / 128, NZ);  // (16, 16, 64)
    scores_mma<<<gs, 256>>>(qsp, ksp, attn);

    // 3) Softmax rows in place
    softmax_kernel<<<NZ * SEQ, 256>>>(attn);

    // 4) AV (HMMA, in-kernel P split) -> g_oh [B,S,H*DV]
    dim3 ga(SEQ / 128, NZ);  // (16, 64)
    av_mma<<<ga, 256>>>(attn, vsp, oh);

    // 5) Output projection (HMMA) -> d_out
    prep_act<<<(act4 + 255) / 256, 256>>>(oh, ohs, act4);
    proj_mma<0><<<ggrid, 256>>>(ohs, wos, bo, out, nullptr);
}

// round 5
// speedup vs baseline: 2.2803x; 1.1508x over previous
#include <cuda_runtime.h>
#include <cuda_bf16.h>
#include <cstdint>

// Problem constants
#define BATCH 4
#define SEQ   2048
#define DMODEL 1024
#define NHEAD 16
#define DHEAD 64
#define MROWS (BATCH * SEQ)                       // 8192
#define OUT_ELEMS ((size_t)BATCH * SEQ * DMODEL)  // 8388608
#define GK 3072                                   // split-bf16 K (3 x 1024)
#define SK 192                                    // split-bf16 K for scores (3 x 64)
#define NZ (BATCH * NHEAD)                        // 64 head-slices
#define VK 6144                                   // split K_eff for AV (3 x 2048)

// ---------------------------------------------------------------------------
// Scratch (device globals; allocation-free rule)
// ---------------------------------------------------------------------------
// split-bf16 activations for projections: [R, 3072] = [hi | lo | hi]
__device__ __nv_bfloat16 g_qs [(size_t)MROWS * GK];
__device__ __nv_bfloat16 g_ks [(size_t)MROWS * GK];
__device__ __nv_bfloat16 g_vs [(size_t)MROWS * GK];
__device__ __nv_bfloat16 g_ohs[(size_t)MROWS * GK];
// split-bf16 weights, transposed: [N, 3072] = [hi | hi | lo]
__device__ __nv_bfloat16 g_wqs[(size_t)DMODEL * GK];
__device__ __nv_bfloat16 g_wks[(size_t)DMODEL * GK];
__device__ __nv_bfloat16 g_wvs[(size_t)DMODEL * GK];
__device__ __nv_bfloat16 g_wos[(size_t)DMODEL * GK];
// split-bf16 Q/K heads for scores: [z, s, 192]
__device__ __nv_bfloat16 g_qsp[(size_t)NZ * SEQ * SK];  // [hi|lo|hi], pre-scaled by 0.125
__device__ __nv_bfloat16 g_ksp[(size_t)NZ * SEQ * SK];  // [hi|hi|lo]
// split-bf16 V^T for AV: [z, d(64), 6144] with per-32-chunk [Vhi|Vhi|Vlo]
__device__ __nv_bfloat16 g_vsp[(size_t)NZ * DHEAD * VK];

// ---------------------------------------------------------------------------
// MMA / async-copy helpers (sm_80-era PTX: valid on plain sm_103 target)
// ---------------------------------------------------------------------------
__device__ __forceinline__ uint32_t smem_u32(const void* p) {
    uint32_t a;
    asm("{ .reg .u64 t; cvta.to.shared.u64 t, %1; cvt.u32.u64 %0, t; }"
        : "=r"(a) : "l"(p));
    return a;
}

#define LDSM_X4(r0, r1, r2, r3, addr)                                          \
    asm volatile("ldmatrix.sync.aligned.m8n8.x4.shared.b16 {%0,%1,%2,%3}, [%4];" \
                 : "=r"(r0), "=r"(r1), "=r"(r2), "=r"(r3) : "r"(addr))

#define MMA16816(d, a, b)                                                      \
    asm volatile("mma.sync.aligned.m16n8k16.row.col.f32.bf16.bf16.f32 "        \
                 "{%0,%1,%2,%3}, {%4,%5,%6,%7}, {%8,%9}, {%0,%1,%2,%3};"       \
                 : "+f"((d)[0]), "+f"((d)[1]), "+f"((d)[2]), "+f"((d)[3])      \
                 : "r"((a)[0]), "r"((a)[1]), "r"((a)[2]), "r"((a)[3]),         \
                   "r"((b)[0]), "r"((b)[1]))

#define CP_ASYNC16(dst, src)                                                   \
    asm volatile("cp.async.cg.shared.global [%0], [%1], 16;"                   \
                 :: "r"(dst), "l"(src))
#define CP_COMMIT() asm volatile("cp.async.commit_group;" ::: "memory")
#define CP_WAIT(n)  asm volatile("cp.async.wait_group %0;" :: "n"(n) : "memory")

// Shared tiles: 128x32 bf16 per operand, rows padded to 40 (80 B).
struct Tiles {
    __nv_bfloat16 A[128][40];
    __nv_bfloat16 B[128][40];
};
#define TSTAGE ((uint32_t)sizeof(Tiles))   // 20480 bytes

// Core loop: CTA 128x128, 8 warps (2 M x 4 N), K-step 32,
// cp.async 2-stage double buffer.
__device__ __forceinline__ void mma_loop_128x128(
    Tiles* tl, const __nv_bfloat16* __restrict__ Abase,
    const __nv_bfloat16* __restrict__ Bbase,
    int lda, int ldb, int nIters, float acc[4][4][4])
{
    const int tid  = threadIdx.x;
    const int lane = tid & 31;
    const int warp = tid >> 5;
    const int wm = (warp >> 2) * 64;
    const int wn = (warp & 3) * 32;

    const int grow = tid >> 2;
    const int gcol = (tid & 3) * 8;
    const __nv_bfloat16* Ap = Abase + (size_t)grow * lda + gcol;
    const __nv_bfloat16* Bp = Bbase + (size_t)grow * ldb + gcol;

    const uint32_t aSt = smem_u32(&tl[0].A[grow][gcol]);
    const uint32_t bSt = smem_u32(&tl[0].B[grow][gcol]);

    const int mrow  = lane & 15;
    const int kA    = (lane & 16) ? 16 : 0;
    const int nrow  = (lane & 7) + ((lane & 16) ? 8 : 0);
    const int kB    = (lane & 8) ? 16 : 0;
    const uint32_t sA = smem_u32(&tl[0].A[0][0]);
    const uint32_t sB = smem_u32(&tl[0].B[0][0]);
    const uint32_t aAddr = sA + (uint32_t)(wm + mrow) * 80u + (uint32_t)kA;
    const uint32_t bAddr = sB + (uint32_t)(wn + nrow) * 80u + (uint32_t)kB;

    // prologue: stage 0
    CP_ASYNC16(aSt, Ap);
    CP_ASYNC16(aSt + 64u * 80u, Ap + (size_t)64 * lda);
    CP_ASYNC16(bSt, Bp);
    CP_ASYNC16(bSt + 64u * 80u, Bp + (size_t)64 * ldb);
    CP_COMMIT();

    for (int it = 0; it < nIters; ++it) {
        const uint32_t cur = (uint32_t)(it & 1) * TSTAGE;
        if (it + 1 < nIters) {
            const uint32_t nxt = (uint32_t)((it + 1) & 1) * TSTAGE;
            const __nv_bfloat16* An = Ap + (it + 1) * 32;
            const __nv_bfloat16* Bn = Bp + (it + 1) * 32;
            CP_ASYNC16(aSt + nxt, An);
            CP_ASYNC16(aSt + nxt + 64u * 80u, An + (size_t)64 * lda);
            CP_ASYNC16(bSt + nxt, Bn);
            CP_ASYNC16(bSt + nxt + 64u * 80u, Bn + (size_t)64 * ldb);
            CP_COMMIT();
            CP_WAIT(1);
        } else {
            CP_WAIT(0);
        }
        __syncthreads();

#pragma unroll
        for (int ks = 0; ks < 2; ++ks) {
            uint32_t a[4][4], b[4][2];
#pragma unroll
            for (int mi = 0; mi < 4; ++mi)
                LDSM_X4(a[mi][0], a[mi][1], a[mi][2], a[mi][3],
                        aAddr + cur + (uint32_t)(mi * 16 * 80 + ks * 32));
            LDSM_X4(b[0][0], b[0][1], b[1][0], b[1][1],
                    bAddr + cur + (uint32_t)(ks * 32));
            LDSM_X4(b[2][0], b[2][1], b[3][0], b[3][1],
                    bAddr + cur + (uint32_t)(16 * 80 + ks * 32));
#pragma unroll
            for (int mi = 0; mi < 4; ++mi)
#pragma unroll
                for (int ni = 0; ni < 4; ++ni)
                    MMA16816(acc[mi][ni], a[mi], b[ni]);
        }
        __syncthreads();
    }
}

// ---------------------------------------------------------------------------
// Projection GEMM: D[8192, 1024] = A'[8192, 3072] x B'[1024, 3072]^T + bias
// MODE 0: fp32 row-major (out projection)
// MODE 1: Q split [hi|lo|hi] (pre-scaled 0.125) -> g_qsp [z, s, 192]
// MODE 2: K split [hi|hi|lo]                    -> g_ksp [z, s, 192]
// MODE 3: V split transposed -> g_vsp [z, d, 6144] chunks [hi|hi|lo]
// ---------------------------------------------------------------------------
template <int MODE>
__global__ __launch_bounds__(256) void proj_mma(
    const __nv_bfloat16* __restrict__ Ag, const __nv_bfloat16* __restrict__ Bg,
    const float* __restrict__ bias, float* __restrict__ Cf,
    __nv_bfloat16* __restrict__ Cs)
{
    __shared__ Tiles tl[2];
    const int mbase = blockIdx.y * 128;
    const int nbase = blockIdx.x * 128;

    float acc[4][4][4];
#pragma unroll
    for (int i = 0; i < 4; i++)
#pragma unroll
        for (int j = 0; j < 4; j++)
#pragma unroll
            for (int r = 0; r < 4; r++) acc[i][j][r] = 0.0f;

    mma_loop_128x128(tl, Ag + (size_t)mbase * GK, Bg + (size_t)nbase * GK,
                     GK, GK, GK / 32, acc);

    const int lane = threadIdx.x & 31;
    const int warp = threadIdx.x >> 5;
    const int wm = (warp >> 2) * 64;
    const int wn = (warp & 3) * 32;
    const int g = lane >> 2, tg = lane & 3;

#pragma unroll
    for (int mi = 0; mi < 4; ++mi) {
#pragma unroll
        for (int ni = 0; ni < 4; ++ni) {
#pragma unroll
            for (int half = 0; half < 2; ++half) {
                const int m = mbase + wm + mi * 16 + g + half * 8;
                const int ncol0 = nbase + wn + ni * 8 + tg * 2;
#pragma unroll
                for (int e = 0; e < 2; ++e) {
                    const int n = ncol0 + e;
                    float val = acc[mi][ni][half * 2 + e] + bias[n];
                    if (MODE == 0) {
                        Cf[(size_t)m * DMODEL + n] = val;
                    } else {
                        const int z = ((m >> 11) << 4) + (n >> 6);
                        const int s = m & (SEQ - 1);
                        const int d = n & 63;
                        if (MODE == 1) val *= 0.125f;   // fold 1/sqrt(dk)
                        const __nv_bfloat16 hi = __float2bfloat16(val);
                        const __nv_bfloat16 lo =
                            __float2bfloat16(val - __bfloat162float(hi));
                        if (MODE == 1) {         // Q: [hi | lo | hi]
                            const size_t base = ((size_t)z * SEQ + s) * SK;
                            Cs[base + d]        = hi;
                            Cs[base + 64 + d]   = lo;
                            Cs[base + 128 + d]  = hi;
                        } else if (MODE == 2) {  // K: [hi | hi | lo]
                            const size_t base = ((size_t)z * SEQ + s) * SK;
                            Cs[base + d]        = hi;
                            Cs[base + 64 + d]   = hi;
                            Cs[base + 128 + d]  = lo;
                        } else {                 // V^T split for AV
                            const size_t base =
                                ((size_t)z * DHEAD + d) * VK + 96 * (s >> 5) + (s & 31);
                            Cs[base]       = hi;
                            Cs[base + 32]  = hi;
                            Cs[base + 64]  = lo;
                        }
                    }
                }
            }
        }
    }
}

// ---------------------------------------------------------------------------
// Scores GEMM per head-slice z: attn[z,q,k] = Qsp[q,:] . Ksp[k,:]
// (scale pre-folded into Qsp)
// ---------------------------------------------------------------------------
__global__ __launch_bounds__(256) void scores_mma(
    const __nv_bfloat16* __restrict__ qsp, const __nv_bfloat16* __restrict__ ksp,
    float* __restrict__ attn)
{
    __shared__ Tiles tl[2];
    const int z     = blockIdx.z;
    const int qbase = blockIdx.y * 128;
    const int kbase = blockIdx.x * 128;

    float acc[4][4][4];
#pragma unroll
    for (int i = 0; i < 4; i++)
#pragma unroll
        for (int j = 0; j < 4; j++)
#pragma unroll
            for (int r = 0; r < 4; r++) acc[i][j][r] = 0.0f;

    const __nv_bfloat16* Abase = qsp + ((size_t)z * SEQ + qbase) * SK;
    const __nv_bfloat16* Bbase = ksp + ((size_t)z * SEQ + kbase) * SK;
    mma_loop_128x128(tl, Abase, Bbase, SK, SK, SK / 32, acc);

    const int lane = threadIdx.x & 31;
    const int warp = threadIdx.x >> 5;
    const int wm = (warp >> 2) * 64;
    const int wn = (warp & 3) * 32;
    const int g = lane >> 2, tg = lane & 3;

    float* out = attn + ((size_t)z * SEQ + qbase) * SEQ + kbase;
#pragma unroll
    for (int mi = 0; mi < 4; ++mi) {
#pragma unroll
        for (int ni = 0; ni < 4; ++ni) {
#pragma unroll
            for (int half = 0; half < 2; ++half) {
                const int r = wm + mi * 16 + g + half * 8;
                const int c = wn + ni * 8 + tg * 2;
                float2 v;
                v.x = acc[mi][ni][half * 2 + 0];
                v.y = acc[mi][ni][half * 2 + 1];
                *(float2*)&out[(size_t)r * SEQ + c] = v;
            }
        }
    }
}

// ---------------------------------------------------------------------------
// AV GEMM (HMMA, in-kernel split of P):
// per z: O[q, d] = sum_k P[q,k] V[k,d], CTA tile M=128 x N=64, K_eff = 6144.
// Epilogue writes split-bf16 [hi|lo|hi] directly into g_ohs [m, 3072].
// ---------------------------------------------------------------------------
__global__ __launch_bounds__(256) void av_mma(
    const float* __restrict__ attn, const __nv_bfloat16* __restrict__ vsp,
    __nv_bfloat16* __restrict__ ohs)
{
    __shared__ __nv_bfloat16 Asm[3][128][40];
    __shared__ __nv_bfloat16 Bsm[3][64][40];

    const int z = blockIdx.y;
    const int mbase = blockIdx.x * 128;
    const int b = z >> 4, h = z & 15;
    const int tid = threadIdx.x, lane = tid & 31, warp = tid >> 5;
    const int wm = (warp >> 1) * 32, wn = (warp & 1) * 32;

    const float* P = attn + ((size_t)z * SEQ + mbase) * SEQ;
    const __nv_bfloat16* Vb = vsp + (size_t)z * DHEAD * VK;

    float acc[2][4][4];
#pragma unroll
    for (int i = 0; i < 2; i++)
#pragma unroll
        for (int j = 0; j < 4; j++)
#pragma unroll
            for (int r = 0; r < 4; r++) acc[i][j][r] = 0.0f;

    const uint32_t sA = smem_u32(&Asm[0][0][0]);
    const uint32_t sB = smem_u32(&Bsm[0][0][0]);
    const int mrow = lane & 15;
    const int kA = (lane & 16) ? 16 : 0;
    const int nr = (lane & 7) + ((lane & 16) ? 8 : 0);
    const int kB = (lane & 8) ? 16 : 0;

    // prefetch it=0
    float4 pa[4];
    uint4  pb[3];
#pragma unroll
    for (int i = 0; i < 4; ++i) {
        const int idx = tid + i * 256;
        const int row = idx >> 3, c4 = (idx & 7) * 4;
        pa[i] = *(const float4*)&P[(size_t)row * SEQ + c4];
    }
#pragma unroll
    for (int i = 0; i < 3; ++i) {
        const int idx = tid + i * 256;
        const int d = idx / 12, jc = (idx % 12) * 8;
        pb[i] = *(const uint4*)&Vb[(size_t)d * VK + jc];
    }

    for (int it = 0; it < SEQ / 32; ++it) {
        __syncthreads();
        // convert + store A (P chunk -> [hi|lo|hi])
#pragma unroll
        for (int i = 0; i < 4; ++i) {
            const int idx = tid + i * 256;
            const int row = idx >> 3, c4 = (idx & 7) * 4;
            float xs[4] = {pa[i].x, pa[i].y, pa[i].z, pa[i].w};
            __nv_bfloat16 hi[4], lo[4];
#pragma unroll
            for (int j = 0; j < 4; ++j) {
                hi[j] = __float2bfloat16(xs[j]);
                lo[j] = __float2bfloat16(xs[j] - __bfloat162float(hi[j]));
            }
            uint2 hp, lp;
            hp.x = *(const uint32_t*)&__nv_bfloat162(hi[0], hi[1]);
            hp.y = *(const uint32_t*)&__nv_bfloat162(hi[2], hi[3]);
            lp.x = *(const uint32_t*)&__nv_bfloat162(lo[0], lo[1]);
            lp.y = *(const uint32_t*)&__nv_bfloat162(lo[2], lo[3]);
            *(uint2*)&Asm[0][row][c4] = hp;
            *(uint2*)&Asm[1][row][c4] = lp;
            *(uint2*)&Asm[2][row][c4] = hp;
        }
        // store B
#pragma unroll
        for (int i = 0; i < 3; ++i) {
            const int idx = tid + i * 256;
            const int d = idx / 12, jc = (idx % 12) * 8;
            *(uint4*)&Bsm[jc >> 5][d][jc & 31] = pb[i];
        }
        __syncthreads();

        if (it + 1 < SEQ / 32) {
#pragma unroll
            for (int i = 0; i < 4; ++i) {
                const int idx = tid + i * 256;
                const int row = idx >> 3, c4 = (idx & 7) * 4;
                pa[i] = *(const float4*)&P[(size_t)row * SEQ + (it + 1) * 32 + c4];
            }
#pragma unroll
            for (int i = 0; i < 3; ++i) {
                const int idx = tid + i * 256;
                const int d = idx / 12, jc = (idx % 12) * 8;
                pb[i] = *(const uint4*)&Vb[(size_t)d * VK + (it + 1) * 96 + jc];
            }
        }

#pragma unroll
        for (int sub = 0; sub < 3; ++sub) {
            const uint32_t aBase = sA + (uint32_t)sub * (128 * 80);
            const uint32_t bBase = sB + (uint32_t)sub * (64 * 80);
#pragma unroll
            for (int ks = 0; ks < 2; ++ks) {
                uint32_t a[2][4], bq[4][2];
#pragma unroll
                for (int mi = 0; mi < 2; ++mi)
                    LDSM_X4(a[mi][0], a[mi][1], a[mi][2], a[mi][3],
                            aBase + (uint32_t)((wm + mi * 16 + mrow) * 80 + kA + ks * 32));
                LDSM_X4(bq[0][0], bq[0][1], bq[1][0], bq[1][1],
                        bBase + (uint32_t)((wn + nr) * 80 + kB + ks * 32));
                LDSM_X4(bq[2][0], bq[2][1], bq[3][0], bq[3][1],
                        bBase + (uint32_t)((wn + 16 + nr) * 80 + kB + ks * 32));
#pragma unroll
                for (int mi = 0; mi < 2; ++mi)
#pragma unroll
                    for (int ni = 0; ni < 4; ++ni)
                        MMA16816(acc[mi][ni], a[mi], bq[ni]);
            }
        }
    }

    // epilogue -> g_ohs split [hi|lo|hi] at row m = b*SEQ + mbase + r, col h*64+c
    const int g = lane >> 2, tg = lane & 3;
#pragma unroll
    for (int mi = 0; mi < 2; ++mi) {
#pragma unroll
        for (int ni = 0; ni < 4; ++ni) {
#pragma unroll
            for (int half = 0; half < 2; ++half) {
                const int r = wm + mi * 16 + g + half * 8;
                const int c = wn + ni * 8 + tg * 2;
                const float v0 = acc[mi][ni][half * 2 + 0];
                const float v1 = acc[mi][ni][half * 2 + 1];
                const __nv_bfloat16 h0 = __float2bfloat16(v0);
                const __nv_bfloat16 l0 = __float2bfloat16(v0 - __bfloat162float(h0));
                const __nv_bfloat16 h1 = __float2bfloat16(v1);
                const __nv_bfloat16 l1 = __float2bfloat16(v1 - __bfloat162float(h1));
                const size_t row = (size_t)(b * SEQ + mbase + r);
                const size_t base = row * GK + h * DHEAD + c;
                *(__nv_bfloat162*)&ohs[base]        = __nv_bfloat162(h0, h1);
                *(__nv_bfloat162*)&ohs[base + 1024] = __nv_bfloat162(l0, l1);
                *(__nv_bfloat162*)&ohs[base + 2048] = __nv_bfloat162(h0, h1);
            }
        }
    }
}

// ---------------------------------------------------------------------------
// prep_act: X[R,1024] fp32 -> Y[R,3072] bf16 as [hi | lo | hi]
// ---------------------------------------------------------------------------
__global__ __launch_bounds__(256) void prep_act(
    const float* __restrict__ X, __nv_bfloat16* __restrict__ Y, int total4)
{
    int i = blockIdx.x * 256 + threadIdx.x;
    if (i >= total4) return;
    float4 xv = ((const float4*)X)[i];
    int r = i >> 8;
    int k = (i & 255) * 4;
    size_t base = (size_t)r * GK + k;

    float xs[4] = {xv.x, xv.y, xv.z, xv.w};
    __nv_bfloat16 hi[4], lo[4];
#pragma unroll
    for (int j = 0; j < 4; j++) {
        hi[j] = __float2bfloat16(xs[j]);
        lo[j] = __float2bfloat16(xs[j] - __bfloat162float(hi[j]));
    }
    *(__nv_bfloat162*)(Y + base)        = __nv_bfloat162(hi[0], hi[1]);
    *(__nv_bfloat162*)(Y + base + 2)    = __nv_bfloat162(hi[2], hi[3]);
    *(__nv_bfloat162*)(Y + base + 1024) = __nv_bfloat162(lo[0], lo[1]);
    *(__nv_bfloat162*)(Y + base + 1026) = __nv_bfloat162(lo[2], lo[3]);
    *(__nv_bfloat162*)(Y + base + 2048) = __nv_bfloat162(hi[0], hi[1]);
    *(__nv_bfloat162*)(Y + base + 2050) = __nv_bfloat162(hi[2], hi[3]);
}

// ---------------------------------------------------------------------------
// prep_wgt: W[1024,1024] fp32 (K rows) -> Ws[N=1024, 3072] bf16 [hi|hi|lo]
// ---------------------------------------------------------------------------
__global__ __launch_bounds__(256) void prep_wgt(
    const float* __restrict__ W, __nv_bfloat16* __restrict__ Ws)
{
    __shared__ float t[32][33];
    const int k0 = blockIdx.y * 32, n0 = blockIdx.x * 32;
    const int tx = threadIdx.x, ty = threadIdx.y;   // (32, 8)
#pragma unroll
    for (int r = ty; r < 32; r += 8)
        t[r][tx] = W[(size_t)(k0 + r) * DMODEL + n0 + tx];
    __syncthreads();
#pragma unroll
    for (int r = ty; r < 32; r += 8) {
        const int n = n0 + r;
        const int k = k0 + tx;
        const float x = t[tx][r];
        __nv_bfloat16 hi = __float2bfloat16(x);
        __nv_bfloat16 lo = __float2bfloat16(x - __bfloat162float(hi));
        size_t base = (size_t)n * GK;
        Ws[base + k]        = hi;
        Ws[base + 1024 + k] = hi;
        Ws[base + 2048 + k] = lo;
    }
}

// ---------------------------------------------------------------------------
// Row softmax over 2048 elements, in place.
// ---------------------------------------------------------------------------
__global__ __launch_bounds__(256) void softmax_kernel(float* __restrict__ attn)
{
    const size_t row = blockIdx.x;
    float* x = attn + row * (size_t)SEQ;
    const int tid = threadIdx.x;

    float4 v0 = ((float4*)x)[tid * 2];
    float4 v1 = ((float4*)x)[tid * 2 + 1];

    float m = fmaxf(fmaxf(fmaxf(v0.x, v0.y), fmaxf(v0.z, v0.w)),
                    fmaxf(fmaxf(v1.x, v1.y), fmaxf(v1.z, v1.w)));

    __shared__ float red[8];
#pragma unroll
    for (int o = 16; o; o >>= 1) m = fmaxf(m, __shfl_xor_sync(0xffffffffu, m, o));
    if ((tid & 31) == 0) red[tid >> 5] = m;
    __syncthreads();
    m = red[0];
#pragma unroll
    for (int i = 1; i < 8; i++) m = fmaxf(m, red[i]);
    __syncthreads();

    v0.x = __expf(v0.x - m); v0.y = __expf(v0.y - m);
    v0.z = __expf(v0.z - m); v0.w = __expf(v0.w - m);
    v1.x = __expf(v1.x - m); v1.y = __expf(v1.y - m);
    v1.z = __expf(v1.z - m); v1.w = __expf(v1.w - m);

    float s = v0.x + v0.y + v0.z + v0.w + v1.x + v1.y + v1.z + v1.w;
#pragma unroll
    for (int o = 16; o; o >>= 1) s += __shfl_xor_sync(0xffffffffu, s, o);
    if ((tid & 31) == 0) red[tid >> 5] = s;
    __syncthreads();
    s = red[0] + red[1] + red[2] + red[3] + red[4] + red[5] + red[6] + red[7];
    const float inv = 1.0f / s;

    v0.x *= inv; v0.y *= inv; v0.z *= inv; v0.w *= inv;
    v1.x *= inv; v1.y *= inv; v1.z *= inv; v1.w *= inv;
    ((float4*)x)[tid * 2]     = v0;
    ((float4*)x)[tid * 2 + 1] = v1;
}

// ---------------------------------------------------------------------------
extern "C" void kernel_launch(void* const* d_in, const int* in_sizes, int n_in,
                              void* d_out, int out_size)
{
    const float* q  = (const float*)d_in[0];
    const float* k  = (const float*)d_in[1];
    const float* v  = (const float*)d_in[2];
    const float* Wq = (const float*)d_in[3];
    const float* bq = (const float*)d_in[4];
    const float* Wk = (const float*)d_in[5];
    const float* bk = (const float*)d_in[6];
    const float* Wv = (const float*)d_in[7];
    const float* bv = (const float*)d_in[8];
    const float* Wo = (const float*)d_in[9];
    const float* bo = (const float*)d_in[10];

    float* out  = (float*)d_out;
    float* attn = out + OUT_ELEMS;

    __nv_bfloat16 *qs, *ks, *vs, *ohs, *wqs, *wks, *wvs, *wos, *qsp, *ksp, *vsp;
    cudaGetSymbolAddress((void**)&qs,  g_qs);
    cudaGetSymbolAddress((void**)&ks,  g_ks);
    cudaGetSymbolAddress((void**)&vs,  g_vs);
    cudaGetSymbolAddress((void**)&ohs, g_ohs);
    cudaGetSymbolAddress((void**)&wqs, g_wqs);
    cudaGetSymbolAddress((void**)&wks, g_wks);
    cudaGetSymbolAddress((void**)&wvs, g_wvs);
    cudaGetSymbolAddress((void**)&wos, g_wos);
    cudaGetSymbolAddress((void**)&qsp, g_qsp);
    cudaGetSymbolAddress((void**)&ksp, g_ksp);
    cudaGetSymbolAddress((void**)&vsp, g_vsp);

    const int act4 = MROWS * DMODEL / 4;
    dim3 wgrid(32, 32);
    dim3 wblk(32, 8);
    dim3 ggrid(DMODEL / 128, MROWS / 128);  // (8, 64)

    // 0) split-bf16 conversions
    prep_wgt<<<wgrid, wblk>>>(Wq, wqs);
    prep_wgt<<<wgrid, wblk>>>(Wk, wks);
    prep_wgt<<<wgrid, wblk>>>(Wv, wvs);
    prep_wgt<<<wgrid, wblk>>>(Wo, wos);
    prep_act<<<(act4 + 255) / 256, 256>>>(q, qs, act4);
    prep_act<<<(act4 + 255) / 256, 256>>>(k, ks, act4);
    prep_act<<<(act4 + 255) / 256, 256>>>(v, vs, act4);

    // 1) Q/K/V projections (HMMA). Q/K -> split heads, V -> split V^T.
    proj_mma<1><<<ggrid, 256>>>(qs, wqs, bq, nullptr, qsp);
    proj_mma<2><<<ggrid, 256>>>(ks, wks, bk, nullptr, ksp);
    proj_mma<3><<<ggrid, 256>>>(vs, wvs, bv, nullptr, vsp);

    // 2) Scores (HMMA, split-bf16, K=192; scale folded into Q) -> attn region
    dim3 gs(SEQ / 128, SEQ / 128, NZ);  // (16, 16, 64)
    scores_mma<<<gs, 256>>>(qsp, ksp, attn);

    // 3) Softmax rows in place
    softmax_kernel<<<NZ * SEQ, 256>>>(attn);

    // 4) AV (HMMA, in-kernel P split) -> g_ohs split directly
    dim3 ga(SEQ / 128, NZ);  // (16, 64)
    av_mma<<<ga, 256>>>(attn, vsp, ohs);

    // 5) Output projection (HMMA) -> d_out
    proj_mma<0><<<ggrid, 256>>>(ohs, wos, bo, out, nullptr);
}

// round 6
// speedup vs baseline: 2.3329x; 1.0230x over previous
#include <cuda_runtime.h>
#include <cuda_bf16.h>
#include <cstdint>

// Problem constants
#define BATCH 4
#define SEQ   2048
#define DMODEL 1024
#define NHEAD 16
#define DHEAD 64
#define MROWS (BATCH * SEQ)                       // 8192
#define OUT_ELEMS ((size_t)BATCH * SEQ * DMODEL)  // 8388608
#define GK 3072                                   // split-bf16 K (3 x 1024)
#define SK 192                                    // split-bf16 K for scores (3 x 64)
#define NZ (BATCH * NHEAD)                        // 64 head-slices
#define VK 6144                                   // split K_eff for AV (3 x 2048)

// ---------------------------------------------------------------------------
// Scratch (device globals; allocation-free rule)
// ---------------------------------------------------------------------------
__device__ __nv_bfloat16 g_qs [(size_t)MROWS * GK];
__device__ __nv_bfloat16 g_ks [(size_t)MROWS * GK];
__device__ __nv_bfloat16 g_vs [(size_t)MROWS * GK];
__device__ __nv_bfloat16 g_ohs[(size_t)MROWS * GK];
__device__ __nv_bfloat16 g_wqs[(size_t)DMODEL * GK];
__device__ __nv_bfloat16 g_wks[(size_t)DMODEL * GK];
__device__ __nv_bfloat16 g_wvs[(size_t)DMODEL * GK];
__device__ __nv_bfloat16 g_wos[(size_t)DMODEL * GK];
__device__ __nv_bfloat16 g_qsp[(size_t)NZ * SEQ * SK];  // [hi|lo|hi], pre-scaled 0.125
__device__ __nv_bfloat16 g_ksp[(size_t)NZ * SEQ * SK];  // [hi|hi|lo]
__device__ __nv_bfloat16 g_vsp[(size_t)NZ * DHEAD * VK];

// ---------------------------------------------------------------------------
// MMA / async-copy helpers
// ---------------------------------------------------------------------------
__device__ __forceinline__ uint32_t smem_u32(const void* p) {
    uint32_t a;
    asm("{ .reg .u64 t; cvta.to.shared.u64 t, %1; cvt.u32.u64 %0, t; }"
        : "=r"(a) : "l"(p));
    return a;
}

#define LDSM_X4(r0, r1, r2, r3, addr)                                          \
    asm volatile("ldmatrix.sync.aligned.m8n8.x4.shared.b16 {%0,%1,%2,%3}, [%4];" \
                 : "=r"(r0), "=r"(r1), "=r"(r2), "=r"(r3) : "r"(addr))

#define MMA16816(d, a, b)                                                      \
    asm volatile("mma.sync.aligned.m16n8k16.row.col.f32.bf16.bf16.f32 "        \
                 "{%0,%1,%2,%3}, {%4,%5,%6,%7}, {%8,%9}, {%0,%1,%2,%3};"       \
                 : "+f"((d)[0]), "+f"((d)[1]), "+f"((d)[2]), "+f"((d)[3])      \
                 : "r"((a)[0]), "r"((a)[1]), "r"((a)[2]), "r"((a)[3]),         \
                   "r"((b)[0]), "r"((b)[1]))

#define CP_ASYNC16(dst, src)                                                   \
    asm volatile("cp.async.cg.shared.global [%0], [%1], 16;"                   \
                 :: "r"(dst), "l"(src))
#define CP_COMMIT() asm volatile("cp.async.commit_group;" ::: "memory")
#define CP_WAIT(n)  asm volatile("cp.async.wait_group %0;" :: "n"(n) : "memory")

// One pipeline stage of the 128x128 loop: A[128][40] then B[128][40] bf16.
#define TSTAGE 20480u
#define MAIN_SMEM (3 * 20480)     // 61440

// Core loop: CTA 128x128, 8 warps (2Mx4N), K-step 32,
// 3-stage cp.async pipeline, ONE barrier per iteration. nIters >= 2.
__device__ __forceinline__ void mma_loop_128x128(
    char* smem, const __nv_bfloat16* __restrict__ Abase,
    const __nv_bfloat16* __restrict__ Bbase,
    int lda, int ldb, int nIters, float acc[4][4][4])
{
    const int tid  = threadIdx.x;
    const int lane = tid & 31;
    const int warp = tid >> 5;
    const int wm = (warp >> 2) * 64;
    const int wn = (warp & 3) * 32;

    const int grow = tid >> 2;
    const int gcol = (tid & 3) * 8;
    const __nv_bfloat16* Ap = Abase + (size_t)grow * lda + gcol;
    const __nv_bfloat16* Bp = Bbase + (size_t)grow * ldb + gcol;

    const uint32_t s0 = smem_u32(smem);
    const uint32_t aStOff = (uint32_t)(grow * 80 + gcol * 2);
    const uint32_t bStOff = 10240u + (uint32_t)(grow * 80 + gcol * 2);

    const int mrow  = lane & 15;
    const int kA    = (lane & 16) ? 16 : 0;
    const int nrow  = (lane & 7) + ((lane & 16) ? 8 : 0);
    const int kB    = (lane & 8) ? 16 : 0;
    const uint32_t aLdm = s0 + (uint32_t)((wm + mrow) * 80 + kA);
    const uint32_t bLdm = s0 + 10240u + (uint32_t)((wn + nrow) * 80 + kB);

#define ISSUE_TILE(g)                                                          \
    do {                                                                       \
        const uint32_t st = s0 + (uint32_t)((g) % 3) * TSTAGE;                 \
        const __nv_bfloat16* An = Ap + (g) * 32;                               \
        const __nv_bfloat16* Bn = Bp + (g) * 32;                               \
        CP_ASYNC16(st + aStOff, An);                                           \
        CP_ASYNC16(st + aStOff + 64u * 80u, An + (size_t)64 * lda);            \
        CP_ASYNC16(st + bStOff, Bn);                                           \
        CP_ASYNC16(st + bStOff + 64u * 80u, Bn + (size_t)64 * ldb);            \
        CP_COMMIT();                                                           \
    } while (0)

    ISSUE_TILE(0);
    ISSUE_TILE(1);

    for (int it = 0; it < nIters; ++it) {
        if (it + 1 < nIters) { CP_WAIT(1); } else { CP_WAIT(0); }
        __syncthreads();
        if (it + 2 < nIters) ISSUE_TILE(it + 2);

        const uint32_t cur = (uint32_t)(it % 3) * TSTAGE;
#pragma unroll
        for (int ks = 0; ks < 2; ++ks) {
            uint32_t a[4][4], b[4][2];
#pragma unroll
            for (int mi = 0; mi < 4; ++mi)
                LDSM_X4(a[mi][0], a[mi][1], a[mi][2], a[mi][3],
                        aLdm + cur + (uint32_t)(mi * 16 * 80 + ks * 32));
            LDSM_X4(b[0][0], b[0][1], b[1][0], b[1][1],
                    bLdm + cur + (uint32_t)(ks * 32));
            LDSM_X4(b[2][0], b[2][1], b[3][0], b[3][1],
                    bLdm + cur + (uint32_t)(16 * 80 + ks * 32));
#pragma unroll
            for (int mi = 0; mi < 4; ++mi)
#pragma unroll
                for (int ni = 0; ni < 4; ++ni)
                    MMA16816(acc[mi][ni], a[mi], b[ni]);
        }
    }
#undef ISSUE_TILE
}

// ---------------------------------------------------------------------------
// Projection GEMM: D[8192, 1024] = A'[8192, 3072] x B'[1024, 3072]^T + bias
// ---------------------------------------------------------------------------
template <int MODE>
__global__ __launch_bounds__(256) void proj_mma(
    const __nv_bfloat16* __restrict__ Ag, const __nv_bfloat16* __restrict__ Bg,
    const float* __restrict__ bias, float* __restrict__ Cf,
    __nv_bfloat16* __restrict__ Cs)
{
    extern __shared__ char smem[];
    const int mbase = blockIdx.y * 128;
    const int nbase = blockIdx.x * 128;

    float acc[4][4][4];
#pragma unroll
    for (int i = 0; i < 4; i++)
#pragma unroll
        for (int j = 0; j < 4; j++)
#pragma unroll
            for (int r = 0; r < 4; r++) acc[i][j][r] = 0.0f;

    mma_loop_128x128(smem, Ag + (size_t)mbase * GK, Bg + (size_t)nbase * GK,
                     GK, GK, GK / 32, acc);

    const int lane = threadIdx.x & 31;
    const int warp = threadIdx.x >> 5;
    const int wm = (warp >> 2) * 64;
    const int wn = (warp & 3) * 32;
    const int g = lane >> 2, tg = lane & 3;

#pragma unroll
    for (int mi = 0; mi < 4; ++mi) {
#pragma unroll
        for (int ni = 0; ni < 4; ++ni) {
#pragma unroll
            for (int half = 0; half < 2; ++half) {
                const int m = mbase + wm + mi * 16 + g + half * 8;
                const int ncol0 = nbase + wn + ni * 8 + tg * 2;
#pragma unroll
                for (int e = 0; e < 2; ++e) {
                    const int n = ncol0 + e;
                    float val = acc[mi][ni][half * 2 + e] + bias[n];
                    if (MODE == 0) {
                        Cf[(size_t)m * DMODEL + n] = val;
                    } else {
                        const int z = ((m >> 11) << 4) + (n >> 6);
                        const int s = m & (SEQ - 1);
                        const int d = n & 63;
                        if (MODE == 1) val *= 0.125f;   // fold 1/sqrt(dk)
                        const __nv_bfloat16 hi = __float2bfloat16(val);
                        const __nv_bfloat16 lo =
                            __float2bfloat16(val - __bfloat162float(hi));
                        if (MODE == 1) {         // Q: [hi | lo | hi]
                            const size_t base = ((size_t)z * SEQ + s) * SK;
                            Cs[base + d]        = hi;
                            Cs[base + 64 + d]   = lo;
                            Cs[base + 128 + d]  = hi;
                        } else if (MODE == 2) {  // K: [hi | hi | lo]
                            const size_t base = ((size_t)z * SEQ + s) * SK;
                            Cs[base + d]        = hi;
                            Cs[base + 64 + d]   = hi;
                            Cs[base + 128 + d]  = lo;
                        } else {                 // V^T split for AV
                            const size_t base =
                                ((size_t)z * DHEAD + d) * VK + 96 * (s >> 5) + (s & 31);
                            Cs[base]       = hi;
                            Cs[base + 32]  = hi;
                            Cs[base + 64]  = lo;
                        }
                    }
                }
            }
        }
    }
}

// ---------------------------------------------------------------------------
// Scores GEMM per head-slice z: attn[z,q,k] = Qsp[q,:] . Ksp[k,:]
// ---------------------------------------------------------------------------
__global__ __launch_bounds__(256) void scores_mma(
    const __nv_bfloat16* __restrict__ qsp, const __nv_bfloat16* __restrict__ ksp,
    float* __restrict__ attn)
{
    extern __shared__ char smem[];
    const int z     = blockIdx.z;
    const int qbase = blockIdx.y * 128;
    const int kbase = blockIdx.x * 128;

    float acc[4][4][4];
#pragma unroll
    for (int i = 0; i < 4; i++)
#pragma unroll
        for (int j = 0; j < 4; j++)
#pragma unroll
            for (int r = 0; r < 4; r++) acc[i][j][r] = 0.0f;

    const __nv_bfloat16* Abase = qsp + ((size_t)z * SEQ + qbase) * SK;
    const __nv_bfloat16* Bbase = ksp + ((size_t)z * SEQ + kbase) * SK;
    mma_loop_128x128(smem, Abase, Bbase, SK, SK, SK / 32, acc);

    const int lane = threadIdx.x & 31;
    const int warp = threadIdx.x >> 5;
    const int wm = (warp >> 2) * 64;
    const int wn = (warp & 3) * 32;
    const int g = lane >> 2, tg = lane & 3;

    float* out = attn + ((size_t)z * SEQ + qbase) * SEQ + kbase;
#pragma unroll
    for (int mi = 0; mi < 4; ++mi) {
#pragma unroll
        for (int ni = 0; ni < 4; ++ni) {
#pragma unroll
            for (int half = 0; half < 2; ++half) {
                const int r = wm + mi * 16 + g + half * 8;
                const int c = wn + ni * 8 + tg * 2;
                float2 v;
                v.x = acc[mi][ni][half * 2 + 0];
                v.y = acc[mi][ni][half * 2 + 1];
                *(float2*)&out[(size_t)r * SEQ + c] = v;
            }
        }
    }
}

// ---------------------------------------------------------------------------
// AV GEMM: per z: O[q,d] = sum_k P[q,k] V[k,d]. CTA 128x64, K_eff 6144.
// Double-buffered smem, ONE barrier per iter. P: reg-convert; V: cp.async.
// Stage layout (46080 B each): A 3sub x128x40 (30720), B 3sub x64x40 (15360).
// ---------------------------------------------------------------------------
#define AV_STAGE 46080u
#define AV_SMEM  (2 * 46080)

__global__ __launch_bounds__(256) void av_mma(
    const float* __restrict__ attn, const __nv_bfloat16* __restrict__ vsp,
    __nv_bfloat16* __restrict__ ohs)
{
    extern __shared__ char smem[];
    const int z = blockIdx.y;
    const int mbase = blockIdx.x * 128;
    const int b = z >> 4, h = z & 15;
    const int tid = threadIdx.x, lane = tid & 31, warp = tid >> 5;
    const int wm = (warp >> 1) * 32, wn = (warp & 1) * 32;

    const float* P = attn + ((size_t)z * SEQ + mbase) * SEQ;
    const __nv_bfloat16* Vb = vsp + (size_t)z * DHEAD * VK;

    float acc[2][4][4];
#pragma unroll
    for (int i = 0; i < 2; i++)
#pragma unroll
        for (int j = 0; j < 4; j++)
#pragma unroll
            for (int r = 0; r < 4; r++) acc[i][j][r] = 0.0f;

    const uint32_t s0 = smem_u32(smem);
    const int mrow = lane & 15;
    const int kA = (lane & 16) ? 16 : 0;
    const int nr = (lane & 7) + ((lane & 16) ? 8 : 0);
    const int kB = (lane & 8) ? 16 : 0;

    // V cp.async mapping: 3 x 16B chunks per thread per stage
    const int vIdx0 = tid;                 // + i*256
    // P load/convert mapping: 4 x float4 per thread
    // issue V for iteration 'g' into stage g&1
#define AV_ISSUE_V(g)                                                          \
    do {                                                                       \
        const uint32_t st = s0 + (uint32_t)((g) & 1) * AV_STAGE + 30720u;      \
        _Pragma("unroll")                                                      \
        for (int i = 0; i < 3; ++i) {                                          \
            const int idx = vIdx0 + i * 256;                                   \
            const int d = idx / 12, jc = (idx % 12) * 8;                       \
            CP_ASYNC16(st + (uint32_t)((jc >> 5) * 5120 + d * 80 + (jc & 31) * 2), \
                       Vb + (size_t)d * VK + (g) * 96 + jc);                   \
        }                                                                      \
        CP_COMMIT();                                                           \
    } while (0)

    AV_ISSUE_V(0);

    float4 pa[4];
#pragma unroll
    for (int i = 0; i < 4; ++i) {
        const int idx = tid + i * 256;
        pa[i] = *(const float4*)&P[(size_t)(idx >> 3) * SEQ + (idx & 7) * 4];
    }

    const int nIt = SEQ / 32;   // 64
    for (int it = 0; it < nIt; ++it) {
        const uint32_t stA = s0 + (uint32_t)(it & 1) * AV_STAGE;
        // convert + store P chunk -> [hi|lo|hi] subs
#pragma unroll
        for (int i = 0; i < 4; ++i) {
            const int idx = tid + i * 256;
            const int row = idx >> 3, c4 = (idx & 7) * 4;
            float xs[4] = {pa[i].x, pa[i].y, pa[i].z, pa[i].w};
            __nv_bfloat16 hi[4], lo[4];
#pragma unroll
            for (int j = 0; j < 4; ++j) {
                hi[j] = __float2bfloat16(xs[j]);
                lo[j] = __float2bfloat16(xs[j] - __bfloat162float(hi[j]));
            }
            uint2 hp, lp;
            hp.x = *(const uint32_t*)&__nv_bfloat162(hi[0], hi[1]);
            hp.y = *(const uint32_t*)&__nv_bfloat162(hi[2], hi[3]);
            lp.x = *(const uint32_t*)&__nv_bfloat162(lo[0], lo[1]);
            lp.y = *(const uint32_t*)&__nv_bfloat162(lo[2], lo[3]);
            const uint32_t ro = (uint32_t)(row * 80 + c4 * 2);
            *(uint2*)(smem + (stA - s0) + ro)          = hp;   // sub 0
            *(uint2*)(smem + (stA - s0) + 10240 + ro)  = lp;   // sub 1
            *(uint2*)(smem + (stA - s0) + 20480 + ro)  = hp;   // sub 2
        }
        // prefetch next P chunk
        if (it + 1 < nIt) {
#pragma unroll
            for (int i = 0; i < 4; ++i) {
                const int idx = tid + i * 256;
                pa[i] = *(const float4*)&P[(size_t)(idx >> 3) * SEQ +
                                           (it + 1) * 32 + (idx & 7) * 4];
            }
        }
        CP_WAIT(0);            // V(it) complete
        __syncthreads();       // publish P stores + V; proves MMA(it-1) done
        if (it + 1 < nIt) AV_ISSUE_V(it + 1);

        const uint32_t stB = stA + 30720u;
#pragma unroll
        for (int sub = 0; sub < 3; ++sub) {
            const uint32_t aBase = stA + (uint32_t)sub * 10240u;
            const uint32_t bBase = stB + (uint32_t)sub * 5120u;
#pragma unroll
            for (int ks = 0; ks < 2; ++ks) {
                uint32_t a[2][4], bq[4][2];
#pragma unroll
                for (int mi = 0; mi < 2; ++mi)
                    LDSM_X4(a[mi][0], a[mi][1], a[mi][2], a[mi][3],
                            aBase + (uint32_t)((wm + mi * 16 + mrow) * 80 + kA + ks * 32));
                LDSM_X4(bq[0][0], bq[0][1], bq[1][0], bq[1][1],
                        bBase + (uint32_t)((wn + nr) * 80 + kB + ks * 32));
                LDSM_X4(bq[2][0], bq[2][1], bq[3][0], bq[3][1],
                        bBase + (uint32_t)((wn + 16 + nr) * 80 + kB + ks * 32));
#pragma unroll
                for (int mi = 0; mi < 2; ++mi)
#pragma unroll
                    for (int ni = 0; ni < 4; ++ni)
                        MMA16816(acc[mi][ni], a[mi], bq[ni]);
            }
        }
    }
#undef AV_ISSUE_V

    // epilogue -> g_ohs split [hi|lo|hi]
    const int g = lane >> 2, tg = lane & 3;
#pragma unroll
    for (int mi = 0; mi < 2; ++mi) {
#pragma unroll
        for (int ni = 0; ni < 4; ++ni) {
#pragma unroll
            for (int half = 0; half < 2; ++half) {
                const int r = wm + mi * 16 + g + half * 8;
                const int c = wn + ni * 8 + tg * 2;
                const float v0 = acc[mi][ni][half * 2 + 0];
                const float v1 = acc[mi][ni][half * 2 + 1];
                const __nv_bfloat16 h0 = __float2bfloat16(v0);
                const __nv_bfloat16 l0 = __float2bfloat16(v0 - __bfloat162float(h0));
                const __nv_bfloat16 h1 = __float2bfloat16(v1);
                const __nv_bfloat16 l1 = __float2bfloat16(v1 - __bfloat162float(h1));
                const size_t row = (size_t)(b * SEQ + mbase + r);
                const size_t base = row * GK + h * DHEAD + c;
                *(__nv_bfloat162*)&ohs[base]        = __nv_bfloat162(h0, h1);
                *(__nv_bfloat162*)&ohs[base + 1024] = __nv_bfloat162(l0, l1);
                *(__nv_bfloat162*)&ohs[base + 2048] = __nv_bfloat162(h0, h1);
            }
        }
    }
}

// ---------------------------------------------------------------------------
// prep_act: X[R,1024] fp32 -> Y[R,3072] bf16 as [hi | lo | hi]
// ---------------------------------------------------------------------------
__global__ __launch_bounds__(256) void prep_act(
    const float* __restrict__ X, __nv_bfloat16* __restrict__ Y, int total4)
{
    int i = blockIdx.x * 256 + threadIdx.x;
    if (i >= total4) return;
    float4 xv = ((const float4*)X)[i];
    int r = i >> 8;
    int k = (i & 255) * 4;
    size_t base = (size_t)r * GK + k;

    float xs[4] = {xv.x, xv.y, xv.z, xv.w};
    __nv_bfloat16 hi[4], lo[4];
#pragma unroll
    for (int j = 0; j < 4; j++) {
        hi[j] = __float2bfloat16(xs[j]);
        lo[j] = __float2bfloat16(xs[j] - __bfloat162float(hi[j]));
    }
    *(__nv_bfloat162*)(Y + base)        = __nv_bfloat162(hi[0], hi[1]);
    *(__nv_bfloat162*)(Y + base + 2)    = __nv_bfloat162(hi[2], hi[3]);
    *(__nv_bfloat162*)(Y + base + 1024) = __nv_bfloat162(lo[0], lo[1]);
    *(__nv_bfloat162*)(Y + base + 1026) = __nv_bfloat162(lo[2], lo[3]);
    *(__nv_bfloat162*)(Y + base + 2048) = __nv_bfloat162(hi[0], hi[1]);
    *(__nv_bfloat162*)(Y + base + 2050) = __nv_bfloat162(hi[2], hi[3]);
}

// ---------------------------------------------------------------------------
// prep_wgt: W[1024,1024] fp32 (K rows) -> Ws[N=1024, 3072] bf16 [hi|hi|lo]
// ---------------------------------------------------------------------------
__global__ __launch_bounds__(256) void prep_wgt(
    const float* __restrict__ W, __nv_bfloat16* __restrict__ Ws)
{
    __shared__ float t[32][33];
    const int k0 = blockIdx.y * 32, n0 = blockIdx.x * 32;
    const int tx = threadIdx.x, ty = threadIdx.y;   // (32, 8)
#pragma unroll
    for (int r = ty; r < 32; r += 8)
        t[r][tx] = W[(size_t)(k0 + r) * DMODEL + n0 + tx];
    __syncthreads();
#pragma unroll
    for (int r = ty; r < 32; r += 8) {
        const int n = n0 + r;
        const int k = k0 + tx;
        const float x = t[tx][r];
        __nv_bfloat16 hi = __float2bfloat16(x);
        __nv_bfloat16 lo = __float2bfloat16(x - __bfloat162float(hi));
        size_t base = (size_t)n * GK;
        Ws[base + k]        = hi;
        Ws[base + 1024 + k] = hi;
        Ws[base + 2048 + k] = lo;
    }
}

// ---------------------------------------------------------------------------
// Row softmax over 2048 elements, in place.
// ---------------------------------------------------------------------------
__global__ __launch_bounds__(256) void softmax_kernel(float* __restrict__ attn)
{
    const size_t row = blockIdx.x;
    float* x = attn + row * (size_t)SEQ;
    const int tid = threadIdx.x;

    float4 v0 = ((float4*)x)[tid * 2];
    float4 v1 = ((float4*)x)[tid * 2 + 1];

    float m = fmaxf(fmaxf(fmaxf(v0.x, v0.y), fmaxf(v0.z, v0.w)),
                    fmaxf(fmaxf(v1.x, v1.y), fmaxf(v1.z, v1.w)));

    __shared__ float red[8];
#pragma unroll
    for (int o = 16; o; o >>= 1) m = fmaxf(m, __shfl_xor_sync(0xffffffffu, m, o));
    if ((tid & 31) == 0) red[tid >> 5] = m;
    __syncthreads();
    m = red[0];
#pragma unroll
    for (int i = 1; i < 8; i++) m = fmaxf(m, red[i]);
    __syncthreads();

    v0.x = __expf(v0.x - m); v0.y = __expf(v0.y - m);
    v0.z = __expf(v0.z - m); v0.w = __expf(v0.w - m);
    v1.x = __expf(v1.x - m); v1.y = __expf(v1.y - m);
    v1.z = __expf(v1.z - m); v1.w = __expf(v1.w - m);

    float s = v0.x + v0.y + v0.z + v0.w + v1.x + v1.y + v1.z + v1.w;
#pragma unroll
    for (int o = 16; o; o >>= 1) s += __shfl_xor_sync(0xffffffffu, s, o);
    if ((tid & 31) == 0) red[tid >> 5] = s;
    __syncthreads();
    s = red[0] + red[1] + red[2] + red[3] + red[4] + red[5] + red[6] + red[7];
    const float inv = 1.0f / s;

    v0.x *= inv; v0.y *= inv; v0.z *= inv; v0.w *= inv;
    v1.x *= inv; v1.y *= inv; v1.z *= inv; v1.w *= inv;
    ((float4*)x)[tid * 2]     = v0;
    ((float4*)x)[tid * 2 + 1] = v1;
}

// ---------------------------------------------------------------------------
extern "C" void kernel_launch(void* const* d_in, const int* in_sizes, int n_in,
                              void* d_out, int out_size)
{
    const float* q  = (const float*)d_in[0];
    const float* k  = (const float*)d_in[1];
    const float* v  = (const float*)d_in[2];
    const float* Wq = (const float*)d_in[3];
    const float* bq = (const float*)d_in[4];
    const float* Wk = (const float*)d_in[5];
    const float* bk = (const float*)d_in[6];
    const float* Wv = (const float*)d_in[7];
    const float* bv = (const float*)d_in[8];
    const float* Wo = (const float*)d_in[9];
    const float* bo = (const float*)d_in[10];

    float* out  = (float*)d_out;
    float* attn = out + OUT_ELEMS;

    __nv_bfloat16 *qs, *ks, *vs, *ohs, *wqs, *wks, *wvs, *wos, *qsp, *ksp, *vsp;
    cudaGetSymbolAddress((void**)&qs,  g_qs);
    cudaGetSymbolAddress((void**)&ks,  g_ks);
    cudaGetSymbolAddress((void**)&vs,  g_vs);
    cudaGetSymbolAddress((void**)&ohs, g_ohs);
    cudaGetSymbolAddress((void**)&wqs, g_wqs);
    cudaGetSymbolAddress((void**)&wks, g_wks);
    cudaGetSymbolAddress((void**)&wvs, g_wvs);
    cudaGetSymbolAddress((void**)&wos, g_wos);
    cudaGetSymbolAddress((void**)&qsp, g_qsp);
    cudaGetSymbolAddress((void**)&ksp, g_ksp);
    cudaGetSymbolAddress((void**)&vsp, g_vsp);

    // raise dynamic smem limits (idempotent, capture-safe config calls)
    cudaFuncSetAttribute(proj_mma<0>, cudaFuncAttributeMaxDynamicSharedMemorySize, MAIN_SMEM);
    cudaFuncSetAttribute(proj_mma<1>, cudaFuncAttributeMaxDynamicSharedMemorySize, MAIN_SMEM);
    cudaFuncSetAttribute(proj_mma<2>, cudaFuncAttributeMaxDynamicSharedMemorySize, MAIN_SMEM);
    cudaFuncSetAttribute(proj_mma<3>, cudaFuncAttributeMaxDynamicSharedMemorySize, MAIN_SMEM);
    cudaFuncSetAttribute(scores_mma,  cudaFuncAttributeMaxDynamicSharedMemorySize, MAIN_SMEM);
    cudaFuncSetAttribute(av_mma,      cudaFuncAttributeMaxDynamicSharedMemorySize, AV_SMEM);

    const int act4 = MROWS * DMODEL / 4;
    dim3 wgrid(32, 32);
    dim3 wblk(32, 8);
    dim3 ggrid(DMODEL / 128, MROWS / 128);  // (8, 64)

    // 0) split-bf16 conversions
    prep_wgt<<<wgrid, wblk>>>(Wq, wqs);
    prep_wgt<<<wgrid, wblk>>>(Wk, wks);
    prep_wgt<<<wgrid, wblk>>>(Wv, wvs);
    prep_wgt<<<wgrid, wblk>>>(Wo, wos);
    prep_act<<<(act4 + 255) / 256, 256>>>(q, qs, act4);
    prep_act<<<(act4 + 255) / 256, 256>>>(k, ks, act4);
    prep_act<<<(act4 + 255) / 256, 256>>>(v, vs, act4);

    // 1) Q/K/V projections (HMMA)
    proj_mma<1><<<ggrid, 256, MAIN_SMEM>>>(qs, wqs, bq, nullptr, qsp);
    proj_mma<2><<<ggrid, 256, MAIN_SMEM>>>(ks, wks, bk, nullptr, ksp);
    proj_mma<3><<<ggrid, 256, MAIN_SMEM>>>(vs, wvs, bv, nullptr, vsp);

    // 2) Scores -> attn region
    dim3 gs(SEQ / 128, SEQ / 128, NZ);  // (16, 16, 64)
    scores_mma<<<gs, 256, MAIN_SMEM>>>(qsp, ksp, attn);

    // 3) Softmax rows in place
    softmax_kernel<<<NZ * SEQ, 256>>>(attn);

    // 4) AV -> g_ohs split directly
    dim3 ga(SEQ / 128, NZ);  // (16, 64)
    av_mma<<<ga, 256, AV_SMEM>>>(attn, vsp, ohs);

    // 5) Output projection -> d_out
    proj_mma<0><<<ggrid, 256, MAIN_SMEM>>>(ohs, wos, bo, out, nullptr);
}

// round 7
// speedup vs baseline: 2.4525x; 1.0513x over previous
#include <cuda_runtime.h>
#include <cuda_bf16.h>
#include <cstdint>

// Problem constants
#define BATCH 4
#define SEQ   2048
#define DMODEL 1024
#define NHEAD 16
#define DHEAD 64
#define MROWS (BATCH * SEQ)                       // 8192
#define OUT_ELEMS ((size_t)BATCH * SEQ * DMODEL)  // 8388608
#define GK 3072                                   // split-bf16 K (3 x 1024)
#define SK 192                                    // split-bf16 K for scores (3 x 64)
#define NZ (BATCH * NHEAD)                        // 64 head-slices
#define VK 6144                                   // split K_eff for AV (3 x 2048)

// ---------------------------------------------------------------------------
// Scratch (device globals; allocation-free rule)
// ---------------------------------------------------------------------------
__device__ __nv_bfloat16 g_qs [(size_t)MROWS * GK];
__device__ __nv_bfloat16 g_ks [(size_t)MROWS * GK];
__device__ __nv_bfloat16 g_vs [(size_t)MROWS * GK];
__device__ __nv_bfloat16 g_ohs[(size_t)MROWS * GK];
__device__ __nv_bfloat16 g_wqs[(size_t)DMODEL * GK];
__device__ __nv_bfloat16 g_wks[(size_t)DMODEL * GK];
__device__ __nv_bfloat16 g_wvs[(size_t)DMODEL * GK];
__device__ __nv_bfloat16 g_wos[(size_t)DMODEL * GK];
__device__ __nv_bfloat16 g_qsp[(size_t)NZ * SEQ * SK];  // [hi|lo|hi], pre-scaled 0.125
__device__ __nv_bfloat16 g_ksp[(size_t)NZ * SEQ * SK];  // [hi|hi|lo]
__device__ __nv_bfloat16 g_vsp[(size_t)NZ * DHEAD * VK];
// per-row partial sums of exp(score): [z*SEQ + row][16 k-tiles]
__device__ float g_psum[(size_t)NZ * SEQ * 16];

// ---------------------------------------------------------------------------
// MMA / async-copy helpers
// ---------------------------------------------------------------------------
__device__ __forceinline__ uint32_t smem_u32(const void* p) {
    uint32_t a;
    asm("{ .reg .u64 t; cvta.to.shared.u64 t, %1; cvt.u32.u64 %0, t; }"
        : "=r"(a) : "l"(p));
    return a;
}

#define LDSM_X4(r0, r1, r2, r3, addr)                                          \
    asm volatile("ldmatrix.sync.aligned.m8n8.x4.shared.b16 {%0,%1,%2,%3}, [%4];" \
                 : "=r"(r0), "=r"(r1), "=r"(r2), "=r"(r3) : "r"(addr))

#define MMA16816(d, a, b)                                                      \
    asm volatile("mma.sync.aligned.m16n8k16.row.col.f32.bf16.bf16.f32 "        \
                 "{%0,%1,%2,%3}, {%4,%5,%6,%7}, {%8,%9}, {%0,%1,%2,%3};"       \
                 : "+f"((d)[0]), "+f"((d)[1]), "+f"((d)[2]), "+f"((d)[3])      \
                 : "r"((a)[0]), "r"((a)[1]), "r"((a)[2]), "r"((a)[3]),         \
                   "r"((b)[0]), "r"((b)[1]))

#define CP_ASYNC16(dst, src)                                                   \
    asm volatile("cp.async.cg.shared.global [%0], [%1], 16;"                   \
                 :: "r"(dst), "l"(src))
#define CP_COMMIT() asm volatile("cp.async.commit_group;" ::: "memory")
#define CP_WAIT(n)  asm volatile("cp.async.wait_group %0;" :: "n"(n) : "memory")

// One pipeline stage of the 128x128 loop: A[128][40] then B[128][40] bf16.
#define TSTAGE 20480u
#define MAIN_SMEM (3 * 20480)     // 61440

// Core loop: CTA 128x128, 8 warps (2Mx4N), K-step 32,
// 3-stage cp.async pipeline, ONE barrier per iteration. nIters >= 2.
__device__ __forceinline__ void mma_loop_128x128(
    char* smem, const __nv_bfloat16* __restrict__ Abase,
    const __nv_bfloat16* __restrict__ Bbase,
    int lda, int ldb, int nIters, float acc[4][4][4])
{
    const int tid  = threadIdx.x;
    const int lane = tid & 31;
    const int warp = tid >> 5;
    const int wm = (warp >> 2) * 64;
    const int wn = (warp & 3) * 32;

    const int grow = tid >> 2;
    const int gcol = (tid & 3) * 8;
    const __nv_bfloat16* Ap = Abase + (size_t)grow * lda + gcol;
    const __nv_bfloat16* Bp = Bbase + (size_t)grow * ldb + gcol;

    const uint32_t s0 = smem_u32(smem);
    const uint32_t aStOff = (uint32_t)(grow * 80 + gcol * 2);
    const uint32_t bStOff = 10240u + (uint32_t)(grow * 80 + gcol * 2);

    const int mrow  = lane & 15;
    const int kA    = (lane & 16) ? 16 : 0;
    const int nrow  = (lane & 7) + ((lane & 16) ? 8 : 0);
    const int kB    = (lane & 8) ? 16 : 0;
    const uint32_t aLdm = s0 + (uint32_t)((wm + mrow) * 80 + kA);
    const uint32_t bLdm = s0 + 10240u + (uint32_t)((wn + nrow) * 80 + kB);

#define ISSUE_TILE(g)                                                          \
    do {                                                                       \
        const uint32_t st = s0 + (uint32_t)((g) % 3) * TSTAGE;                 \
        const __nv_bfloat16* An = Ap + (g) * 32;                               \
        const __nv_bfloat16* Bn = Bp + (g) * 32;                               \
        CP_ASYNC16(st + aStOff, An);                                           \
        CP_ASYNC16(st + aStOff + 64u * 80u, An + (size_t)64 * lda);            \
        CP_ASYNC16(st + bStOff, Bn);                                           \
        CP_ASYNC16(st + bStOff + 64u * 80u, Bn + (size_t)64 * ldb);            \
        CP_COMMIT();                                                           \
    } while (0)

    ISSUE_TILE(0);
    ISSUE_TILE(1);

    for (int it = 0; it < nIters; ++it) {
        if (it + 1 < nIters) { CP_WAIT(1); } else { CP_WAIT(0); }
        __syncthreads();
        if (it + 2 < nIters) ISSUE_TILE(it + 2);

        const uint32_t cur = (uint32_t)(it % 3) * TSTAGE;
#pragma unroll
        for (int ks = 0; ks < 2; ++ks) {
            uint32_t a[4][4], b[4][2];
#pragma unroll
            for (int mi = 0; mi < 4; ++mi)
                LDSM_X4(a[mi][0], a[mi][1], a[mi][2], a[mi][3],
                        aLdm + cur + (uint32_t)(mi * 16 * 80 + ks * 32));
            LDSM_X4(b[0][0], b[0][1], b[1][0], b[1][1],
                    bLdm + cur + (uint32_t)(ks * 32));
            LDSM_X4(b[2][0], b[2][1], b[3][0], b[3][1],
                    bLdm + cur + (uint32_t)(16 * 80 + ks * 32));
#pragma unroll
            for (int mi = 0; mi < 4; ++mi)
#pragma unroll
                for (int ni = 0; ni < 4; ++ni)
                    MMA16816(acc[mi][ni], a[mi], b[ni]);
        }
    }
#undef ISSUE_TILE
}

// ---------------------------------------------------------------------------
// Projection GEMM: D[8192, 1024] = A'[8192, 3072] x B'[1024, 3072]^T + bias
// ---------------------------------------------------------------------------
template <int MODE>
__global__ __launch_bounds__(256) void proj_mma(
    const __nv_bfloat16* __restrict__ Ag, const __nv_bfloat16* __restrict__ Bg,
    const float* __restrict__ bias, float* __restrict__ Cf,
    __nv_bfloat16* __restrict__ Cs)
{
    extern __shared__ char smem[];
    const int mbase = blockIdx.y * 128;
    const int nbase = blockIdx.x * 128;

    float acc[4][4][4];
#pragma unroll
    for (int i = 0; i < 4; i++)
#pragma unroll
        for (int j = 0; j < 4; j++)
#pragma unroll
            for (int r = 0; r < 4; r++) acc[i][j][r] = 0.0f;

    mma_loop_128x128(smem, Ag + (size_t)mbase * GK, Bg + (size_t)nbase * GK,
                     GK, GK, GK / 32, acc);

    const int lane = threadIdx.x & 31;
    const int warp = threadIdx.x >> 5;
    const int wm = (warp >> 2) * 64;
    const int wn = (warp & 3) * 32;
    const int g = lane >> 2, tg = lane & 3;

#pragma unroll
    for (int mi = 0; mi < 4; ++mi) {
#pragma unroll
        for (int ni = 0; ni < 4; ++ni) {
#pragma unroll
            for (int half = 0; half < 2; ++half) {
                const int m = mbase + wm + mi * 16 + g + half * 8;
                const int ncol0 = nbase + wn + ni * 8 + tg * 2;
#pragma unroll
                for (int e = 0; e < 2; ++e) {
                    const int n = ncol0 + e;
                    float val = acc[mi][ni][half * 2 + e] + bias[n];
                    if (MODE == 0) {
                        Cf[(size_t)m * DMODEL + n] = val;
                    } else {
                        const int z = ((m >> 11) << 4) + (n >> 6);
                        const int s = m & (SEQ - 1);
                        const int d = n & 63;
                        if (MODE == 1) val *= 0.125f;   // fold 1/sqrt(dk)
                        const __nv_bfloat16 hi = __float2bfloat16(val);
                        const __nv_bfloat16 lo =
                            __float2bfloat16(val - __bfloat162float(hi));
                        if (MODE == 1) {         // Q: [hi | lo | hi]
                            const size_t base = ((size_t)z * SEQ + s) * SK;
                            Cs[base + d]        = hi;
                            Cs[base + 64 + d]   = lo;
                            Cs[base + 128 + d]  = hi;
                        } else if (MODE == 2) {  // K: [hi | hi | lo]
                            const size_t base = ((size_t)z * SEQ + s) * SK;
                            Cs[base + d]        = hi;
                            Cs[base + 64 + d]   = hi;
                            Cs[base + 128 + d]  = lo;
                        } else {                 // V^T split for AV
                            const size_t base =
                                ((size_t)z * DHEAD + d) * VK + 96 * (s >> 5) + (s & 31);
                            Cs[base]       = hi;
                            Cs[base + 32]  = hi;
                            Cs[base + 64]  = lo;
                        }
                    }
                }
            }
        }
    }
}

// ---------------------------------------------------------------------------
// Scores GEMM per head-slice z: writes e = exp(score) to attn and per-row
// partial sums (over this CTA's 128 cols) to psum[row][blockIdx.x].
// Deterministic reduction: shfl over tg -> smem per wn-warp -> fixed-order sum.
// ---------------------------------------------------------------------------
__global__ __launch_bounds__(256) void scores_mma(
    const __nv_bfloat16* __restrict__ qsp, const __nv_bfloat16* __restrict__ ksp,
    float* __restrict__ attn, float* __restrict__ psum)
{
    extern __shared__ char smem[];
    __shared__ float rowpart[4][128];
    const int z     = blockIdx.z;
    const int qbase = blockIdx.y * 128;
    const int kbase = blockIdx.x * 128;

    float acc[4][4][4];
#pragma unroll
    for (int i = 0; i < 4; i++)
#pragma unroll
        for (int j = 0; j < 4; j++)
#pragma unroll
            for (int r = 0; r < 4; r++) acc[i][j][r] = 0.0f;

    const __nv_bfloat16* Abase = qsp + ((size_t)z * SEQ + qbase) * SK;
    const __nv_bfloat16* Bbase = ksp + ((size_t)z * SEQ + kbase) * SK;
    mma_loop_128x128(smem, Abase, Bbase, SK, SK, SK / 32, acc);

    const int lane = threadIdx.x & 31;
    const int warp = threadIdx.x >> 5;
    const int wm = (warp >> 2) * 64;
    const int wn = (warp & 3) * 32;
    const int g = lane >> 2, tg = lane & 3;

    float* out = attn + ((size_t)z * SEQ + qbase) * SEQ + kbase;
#pragma unroll
    for (int mi = 0; mi < 4; ++mi) {
#pragma unroll
        for (int half = 0; half < 2; ++half) {
            const int r = wm + mi * 16 + g + half * 8;
            float s8 = 0.0f;
#pragma unroll
            for (int ni = 0; ni < 4; ++ni) {
                const int c = wn + ni * 8 + tg * 2;
                float2 v;
                v.x = __expf(acc[mi][ni][half * 2 + 0]);
                v.y = __expf(acc[mi][ni][half * 2 + 1]);
                *(float2*)&out[(size_t)r * SEQ + c] = v;
                s8 += v.x + v.y;
            }
            s8 += __shfl_xor_sync(0xffffffffu, s8, 1);
            s8 += __shfl_xor_sync(0xffffffffu, s8, 2);
            if (tg == 0) rowpart[warp & 3][r] = s8;
        }
    }
    __syncthreads();
    if (threadIdx.x < 128) {
        const float s = (rowpart[0][threadIdx.x] + rowpart[1][threadIdx.x])
                      + (rowpart[2][threadIdx.x] + rowpart[3][threadIdx.x]);
        psum[((size_t)z * SEQ + qbase + threadIdx.x) * 16 + blockIdx.x] = s;
    }
}

// ---------------------------------------------------------------------------
// AV GEMM: per z: O[q,d] = sum_k P[q,k] V[k,d]. CTA 128x64, K_eff 6144.
// Reads e from attn, normalizes on the fly (inv row-sum from psum),
// writes normalized p back to attn, converts p to split bf16 for HMMA.
// ---------------------------------------------------------------------------
#define AV_STAGE 46080u
#define AV_SMEM  (2 * 46080)

__global__ __launch_bounds__(256) void av_mma(
    float* __restrict__ attn, const float* __restrict__ psum,
    const __nv_bfloat16* __restrict__ vsp, __nv_bfloat16* __restrict__ ohs)
{
    extern __shared__ char smem[];
    const int z = blockIdx.y;
    const int mbase = blockIdx.x * 128;
    const int b = z >> 4, h = z & 15;
    const int tid = threadIdx.x, lane = tid & 31, warp = tid >> 5;
    const int wm = (warp >> 1) * 32, wn = (warp & 1) * 32;

    float* P = attn + ((size_t)z * SEQ + mbase) * SEQ;
    const __nv_bfloat16* Vb = vsp + (size_t)z * DHEAD * VK;
    const float* ps = psum + ((size_t)z * SEQ + mbase) * 16;

    // per-thread inverse row sums (rows fixed per thread across iterations)
    float inv[4];
#pragma unroll
    for (int i = 0; i < 4; ++i) {
        const int row = (tid + i * 256) >> 3;
        const float* pr = ps + (size_t)row * 16;
        float s = 0.0f;
#pragma unroll
        for (int j = 0; j < 16; ++j) s += pr[j];
        inv[i] = 1.0f / s;
    }

    float acc[2][4][4];
#pragma unroll
    for (int i = 0; i < 2; i++)
#pragma unroll
        for (int j = 0; j < 4; j++)
#pragma unroll
            for (int r = 0; r < 4; r++) acc[i][j][r] = 0.0f;

    const uint32_t s0 = smem_u32(smem);
    const int mrow = lane & 15;
    const int kA = (lane & 16) ? 16 : 0;
    const int nr = (lane & 7) + ((lane & 16) ? 8 : 0);
    const int kB = (lane & 8) ? 16 : 0;

    const int vIdx0 = tid;
#define AV_ISSUE_V(g)                                                          \
    do {                                                                       \
        const uint32_t st = s0 + (uint32_t)((g) & 1) * AV_STAGE + 30720u;      \
        _Pragma("unroll")                                                      \
        for (int i = 0; i < 3; ++i) {                                          \
            const int idx = vIdx0 + i * 256;                                   \
            const int d = idx / 12, jc = (idx % 12) * 8;                       \
            CP_ASYNC16(st + (uint32_t)((jc >> 5) * 5120 + d * 80 + (jc & 31) * 2), \
                       Vb + (size_t)d * VK + (g) * 96 + jc);                   \
        }                                                                      \
        CP_COMMIT();                                                           \
    } while (0)

    AV_ISSUE_V(0);

    float4 pa[4];
#pragma unroll
    for (int i = 0; i < 4; ++i) {
        const int idx = tid + i * 256;
        pa[i] = *(const float4*)&P[(size_t)(idx >> 3) * SEQ + (idx & 7) * 4];
    }

    const int nIt = SEQ / 32;   // 64
    for (int it = 0; it < nIt; ++it) {
        const uint32_t stA = s0 + (uint32_t)(it & 1) * AV_STAGE;
        // normalize, write back p, convert to split bf16 -> smem subs
#pragma unroll
        for (int i = 0; i < 4; ++i) {
            const int idx = tid + i * 256;
            const int row = idx >> 3, c4 = (idx & 7) * 4;
            float xs[4] = {pa[i].x * inv[i], pa[i].y * inv[i],
                           pa[i].z * inv[i], pa[i].w * inv[i]};
            // write normalized attn (this is the attn output)
            *(float4*)&P[(size_t)row * SEQ + it * 32 + c4] =
                make_float4(xs[0], xs[1], xs[2], xs[3]);
            __nv_bfloat16 hi[4], lo[4];
#pragma unroll
            for (int j = 0; j < 4; ++j) {
                hi[j] = __float2bfloat16(xs[j]);
                lo[j] = __float2bfloat16(xs[j] - __bfloat162float(hi[j]));
            }
            uint2 hp, lp;
            hp.x = *(const uint32_t*)&__nv_bfloat162(hi[0], hi[1]);
            hp.y = *(const uint32_t*)&__nv_bfloat162(hi[2], hi[3]);
            lp.x = *(const uint32_t*)&__nv_bfloat162(lo[0], lo[1]);
            lp.y = *(const uint32_t*)&__nv_bfloat162(lo[2], lo[3]);
            const uint32_t ro = (uint32_t)(row * 80 + c4 * 2);
            *(uint2*)(smem + (stA - s0) + ro)          = hp;   // sub 0
            *(uint2*)(smem + (stA - s0) + 10240 + ro)  = lp;   // sub 1
            *(uint2*)(smem + (stA - s0) + 20480 + ro)  = hp;   // sub 2
        }
        // prefetch next e chunk
        if (it + 1 < nIt) {
#pragma unroll
            for (int i = 0; i < 4; ++i) {
                const int idx = tid + i * 256;
                pa[i] = *(const float4*)&P[(size_t)(idx >> 3) * SEQ +
                                           (it + 1) * 32 + (idx & 7) * 4];
            }
        }
        CP_WAIT(0);            // V(it) complete
        __syncthreads();       // publish P stores + V; proves MMA(it-1) done
        if (it + 1 < nIt) AV_ISSUE_V(it + 1);

        const uint32_t stB = stA + 30720u;
#pragma unroll
        for (int sub = 0; sub < 3; ++sub) {
            const uint32_t aBase = stA + (uint32_t)sub * 10240u;
            const uint32_t bBase = stB + (uint32_t)sub * 5120u;
#pragma unroll
            for (int ks = 0; ks < 2; ++ks) {
                uint32_t a[2][4], bq[4][2];
#pragma unroll
                for (int mi = 0; mi < 2; ++mi)
                    LDSM_X4(a[mi][0], a[mi][1], a[mi][2], a[mi][3],
                            aBase + (uint32_t)((wm + mi * 16 + mrow) * 80 + kA + ks * 32));
                LDSM_X4(bq[0][0], bq[0][1], bq[1][0], bq[1][1],
                        bBase + (uint32_t)((wn + nr) * 80 + kB + ks * 32));
                LDSM_X4(bq[2][0], bq[2][1], bq[3][0], bq[3][1],
                        bBase + (uint32_t)((wn + 16 + nr) * 80 + kB + ks * 32));
#pragma unroll
                for (int mi = 0; mi < 2; ++mi)
#pragma unroll
                    for (int ni = 0; ni < 4; ++ni)
                        MMA16816(acc[mi][ni], a[mi], bq[ni]);
            }
        }
    }
#undef AV_ISSUE_V

    // epilogue -> g_ohs split [hi|lo|hi]
    const int g = lane >> 2, tg = lane & 3;
#pragma unroll
    for (int mi = 0; mi < 2; ++mi) {
#pragma unroll
        for (int ni = 0; ni < 4; ++ni) {
#pragma unroll
            for (int half = 0; half < 2; ++half) {
                const int r = wm + mi * 16 + g + half * 8;
                const int c = wn + ni * 8 + tg * 2;
                const float v0 = acc[mi][ni][half * 2 + 0];
                const float v1 = acc[mi][ni][half * 2 + 1];
                const __nv_bfloat16 h0 = __float2bfloat16(v0);
                const __nv_bfloat16 l0 = __float2bfloat16(v0 - __bfloat162float(h0));
                const __nv_bfloat16 h1 = __float2bfloat16(v1);
                const __nv_bfloat16 l1 = __float2bfloat16(v1 - __bfloat162float(h1));
                const size_t row = (size_t)(b * SEQ + mbase + r);
                const size_t base = row * GK + h * DHEAD + c;
                *(__nv_bfloat162*)&ohs[base]        = __nv_bfloat162(h0, h1);
                *(__nv_bfloat162*)&ohs[base + 1024] = __nv_bfloat162(l0, l1);
                *(__nv_bfloat162*)&ohs[base + 2048] = __nv_bfloat162(h0, h1);
            }
        }
    }
}

// ---------------------------------------------------------------------------
// prep_act: X[R,1024] fp32 -> Y[R,3072] bf16 as [hi | lo | hi]
// ---------------------------------------------------------------------------
__global__ __launch_bounds__(256) void prep_act(
    const float* __restrict__ X, __nv_bfloat16* __restrict__ Y, int total4)
{
    int i = blockIdx.x * 256 + threadIdx.x;
    if (i >= total4) return;
    float4 xv = ((const float4*)X)[i];
    int r = i >> 8;
    int k = (i & 255) * 4;
    size_t base = (size_t)r * GK + k;

    float xs[4] = {xv.x, xv.y, xv.z, xv.w};
    __nv_bfloat16 hi[4], lo[4];
#pragma unroll
    for (int j = 0; j < 4; j++) {
        hi[j] = __float2bfloat16(xs[j]);
        lo[j] = __float2bfloat16(xs[j] - __bfloat162float(hi[j]));
    }
    *(__nv_bfloat162*)(Y + base)        = __nv_bfloat162(hi[0], hi[1]);
    *(__nv_bfloat162*)(Y + base + 2)    = __nv_bfloat162(hi[2], hi[3]);
    *(__nv_bfloat162*)(Y + base + 1024) = __nv_bfloat162(lo[0], lo[1]);
    *(__nv_bfloat162*)(Y + base + 1026) = __nv_bfloat162(lo[2], lo[3]);
    *(__nv_bfloat162*)(Y + base + 2048) = __nv_bfloat162(hi[0], hi[1]);
    *(__nv_bfloat162*)(Y + base + 2050) = __nv_bfloat162(hi[2], hi[3]);
}

// ---------------------------------------------------------------------------
// prep_wgt: W[1024,1024] fp32 (K rows) -> Ws[N=1024, 3072] bf16 [hi|hi|lo]
// ---------------------------------------------------------------------------
__global__ __launch_bounds__(256) void prep_wgt(
    const float* __restrict__ W, __nv_bfloat16* __restrict__ Ws)
{
    __shared__ float t[32][33];
    const int k0 = blockIdx.y * 32, n0 = blockIdx.x * 32;
    const int tx = threadIdx.x, ty = threadIdx.y;   // (32, 8)
#pragma unroll
    for (int r = ty; r < 32; r += 8)
        t[r][tx] = W[(size_t)(k0 + r) * DMODEL + n0 + tx];
    __syncthreads();
#pragma unroll
    for (int r = ty; r < 32; r += 8) {
        const int n = n0 + r;
        const int k = k0 + tx;
        const float x = t[tx][r];
        __nv_bfloat16 hi = __float2bfloat16(x);
        __nv_bfloat16 lo = __float2bfloat16(x - __bfloat162float(hi));
        size_t base = (size_t)n * GK;
        Ws[base + k]        = hi;
        Ws[base + 1024 + k] = hi;
        Ws[base + 2048 + k] = lo;
    }
}

// ---------------------------------------------------------------------------
extern "C" void kernel_launch(void* const* d_in, const int* in_sizes, int n_in,
                              void* d_out, int out_size)
{
    const float* q  = (const float*)d_in[0];
    const float* k  = (const float*)d_in[1];
    const float* v  = (const float*)d_in[2];
    const float* Wq = (const float*)d_in[3];
    const float* bq = (const float*)d_in[4];
    const float* Wk = (const float*)d_in[5];
    const float* bk = (const float*)d_in[6];
    const float* Wv = (const float*)d_in[7];
    const float* bv = (const float*)d_in[8];
    const float* Wo = (const float*)d_in[9];
    const float* bo = (const float*)d_in[10];

    float* out  = (float*)d_out;
    float* attn = out + OUT_ELEMS;

    __nv_bfloat16 *qs, *ks, *vs, *ohs, *wqs, *wks, *wvs, *wos, *qsp, *ksp, *vsp;
    float* psum;
    cudaGetSymbolAddress((void**)&qs,  g_qs);
    cudaGetSymbolAddress((void**)&ks,  g_ks);
    cudaGetSymbolAddress((void**)&vs,  g_vs);
    cudaGetSymbolAddress((void**)&ohs, g_ohs);
    cudaGetSymbolAddress((void**)&wqs, g_wqs);
    cudaGetSymbolAddress((void**)&wks, g_wks);
    cudaGetSymbolAddress((void**)&wvs, g_wvs);
    cudaGetSymbolAddress((void**)&wos, g_wos);
    cudaGetSymbolAddress((void**)&qsp, g_qsp);
    cudaGetSymbolAddress((void**)&ksp, g_ksp);
    cudaGetSymbolAddress((void**)&vsp, g_vsp);
    cudaGetSymbolAddress((void**)&psum, g_psum);

    cudaFuncSetAttribute(proj_mma<0>, cudaFuncAttributeMaxDynamicSharedMemorySize, MAIN_SMEM);
    cudaFuncSetAttribute(proj_mma<1>, cudaFuncAttributeMaxDynamicSharedMemorySize, MAIN_SMEM);
    cudaFuncSetAttribute(proj_mma<2>, cudaFuncAttributeMaxDynamicSharedMemorySize, MAIN_SMEM);
    cudaFuncSetAttribute(proj_mma<3>, cudaFuncAttributeMaxDynamicSharedMemorySize, MAIN_SMEM);
    cudaFuncSetAttribute(scores_mma,  cudaFuncAttributeMaxDynamicSharedMemorySize, MAIN_SMEM);
    cudaFuncSetAttribute(av_mma,      cudaFuncAttributeMaxDynamicSharedMemorySize, AV_SMEM);

    const int act4 = MROWS * DMODEL / 4;
    dim3 wgrid(32, 32);
    dim3 wblk(32, 8);
    dim3 ggrid(DMODEL / 128, MROWS / 128);  // (8, 64)

    // 0) split-bf16 conversions
    prep_wgt<<<wgrid, wblk>>>(Wq, wqs);
    prep_wgt<<<wgrid, wblk>>>(Wk, wks);
    prep_wgt<<<wgrid, wblk>>>(Wv, wvs);
    prep_wgt<<<wgrid, wblk>>>(Wo, wos);
    prep_act<<<(act4 + 255) / 256, 256>>>(q, qs, act4);
    prep_act<<<(act4 + 255) / 256, 256>>>(k, ks, act4);
    prep_act<<<(act4 + 255) / 256, 256>>>(v, vs, act4);

    // 1) Q/K/V projections (HMMA)
    proj_mma<1><<<ggrid, 256, MAIN_SMEM>>>(qs, wqs, bq, nullptr, qsp);
    proj_mma<2><<<ggrid, 256, MAIN_SMEM>>>(ks, wks, bk, nullptr, ksp);
    proj_mma<3><<<ggrid, 256, MAIN_SMEM>>>(vs, wvs, bv, nullptr, vsp);

    // 2) Scores -> e = exp(score) into attn + per-row partial sums
    dim3 gs(SEQ / 128, SEQ / 128, NZ);  // (16, 16, 64)
    scores_mma<<<gs, 256, MAIN_SMEM>>>(qsp, ksp, attn, psum);

    // 3) AV: normalize on the fly, write p back to attn, O -> g_ohs split
    dim3 ga(SEQ / 128, NZ);  // (16, 64)
    av_mma<<<ga, 256, AV_SMEM>>>(attn, psum, vsp, ohs);

    // 4) Output projection -> d_out
    proj_mma<0><<<ggrid, 256, MAIN_SMEM>>>(ohs, wos, bo, out, nullptr);
}

// round 8
// speedup vs baseline: 3.3719x; 1.3749x over previous
#include <cuda_runtime.h>
#include <cuda_fp16.h>
#include <cstdint>

// Problem constants
#define BATCH 4
#define SEQ   2048
#define DMODEL 1024
#define NHEAD 16
#define DHEAD 64
#define MROWS (BATCH * SEQ)                       // 8192
#define OUT_ELEMS ((size_t)BATCH * SEQ * DMODEL)  // 8388608
#define GK 2048                                   // fp16 2-term K (2 x 1024)
#define SK 128                                    // fp16 2-term K for scores
#define NZ (BATCH * NHEAD)                        // 64 head-slices
#define VK 4096                                   // fp16 2-term K_eff for AV

// ---------------------------------------------------------------------------
// Scratch (device globals; allocation-free rule)
// ---------------------------------------------------------------------------
__device__ __half g_qs [(size_t)MROWS * GK];    // activations [hi | lo]
__device__ __half g_ks [(size_t)MROWS * GK];
__device__ __half g_vs [(size_t)MROWS * GK];
__device__ __half g_ohs[(size_t)MROWS * GK];
__device__ __half g_wqs[(size_t)DMODEL * GK];   // weights^T [hi | hi]
__device__ __half g_wks[(size_t)DMODEL * GK];
__device__ __half g_wvs[(size_t)DMODEL * GK];
__device__ __half g_wos[(size_t)DMODEL * GK];
__device__ __half g_qsp[(size_t)NZ * SEQ * SK]; // Q heads [hi|lo], pre-scaled 0.125
__device__ __half g_ksp[(size_t)NZ * SEQ * SK]; // K heads [hi|hi]
__device__ __half g_vsp[(size_t)NZ * DHEAD * VK]; // V^T, per-32-chunk [hi|hi]
// per-row partial sums of exp(score): [z*SEQ + row][16 k-tiles]
__device__ float g_psum[(size_t)NZ * SEQ * 16];

// ---------------------------------------------------------------------------
// MMA / async-copy helpers
// ---------------------------------------------------------------------------
__device__ __forceinline__ uint32_t smem_u32(const void* p) {
    uint32_t a;
    asm("{ .reg .u64 t; cvta.to.shared.u64 t, %1; cvt.u32.u64 %0, t; }"
        : "=r"(a) : "l"(p));
    return a;
}

#define LDSM_X4(r0, r1, r2, r3, addr)                                          \
    asm volatile("ldmatrix.sync.aligned.m8n8.x4.shared.b16 {%0,%1,%2,%3}, [%4];" \
                 : "=r"(r0), "=r"(r1), "=r"(r2), "=r"(r3) : "r"(addr))

#define MMA16816(d, a, b)                                                      \
    asm volatile("mma.sync.aligned.m16n8k16.row.col.f32.f16.f16.f32 "          \
                 "{%0,%1,%2,%3}, {%4,%5,%6,%7}, {%8,%9}, {%0,%1,%2,%3};"       \
                 : "+f"((d)[0]), "+f"((d)[1]), "+f"((d)[2]), "+f"((d)[3])      \
                 : "r"((a)[0]), "r"((a)[1]), "r"((a)[2]), "r"((a)[3]),         \
                   "r"((b)[0]), "r"((b)[1]))

#define CP_ASYNC16(dst, src)                                                   \
    asm volatile("cp.async.cg.shared.global [%0], [%1], 16;"                   \
                 :: "r"(dst), "l"(src))
#define CP_COMMIT() asm volatile("cp.async.commit_group;" ::: "memory")
#define CP_WAIT(n)  asm volatile("cp.async.wait_group %0;" :: "n"(n) : "memory")

__device__ __forceinline__ uint32_t pack_h2(__half a, __half b) {
    __half2 h = __halves2half2(a, b);
    return *(uint32_t*)&h;
}

// One pipeline stage of the 128x128 loop: A[128][40] then B[128][40] halves.
#define TSTAGE 20480u
#define MAIN_SMEM (3 * 20480)     // 61440

// Core loop: CTA 128x128, 8 warps (2Mx4N), K-step 32,
// 3-stage cp.async pipeline, ONE barrier per iteration. nIters >= 2.
__device__ __forceinline__ void mma_loop_128x128(
    char* smem, const __half* __restrict__ Abase,
    const __half* __restrict__ Bbase,
    int lda, int ldb, int nIters, float acc[4][4][4])
{
    const int tid  = threadIdx.x;
    const int lane = tid & 31;
    const int warp = tid >> 5;
    const int wm = (warp >> 2) * 64;
    const int wn = (warp & 3) * 32;

    const int grow = tid >> 2;
    const int gcol = (tid & 3) * 8;
    const __half* Ap = Abase + (size_t)grow * lda + gcol;
    const __half* Bp = Bbase + (size_t)grow * ldb + gcol;

    const uint32_t s0 = smem_u32(smem);
    const uint32_t aStOff = (uint32_t)(grow * 80 + gcol * 2);
    const uint32_t bStOff = 10240u + (uint32_t)(grow * 80 + gcol * 2);

    const int mrow  = lane & 15;
    const int kA    = (lane & 16) ? 16 : 0;
    const int nrow  = (lane & 7) + ((lane & 16) ? 8 : 0);
    const int kB    = (lane & 8) ? 16 : 0;
    const uint32_t aLdm = s0 + (uint32_t)((wm + mrow) * 80 + kA);
    const uint32_t bLdm = s0 + 10240u + (uint32_t)((wn + nrow) * 80 + kB);

#define ISSUE_TILE(g)                                                          \
    do {                                                                       \
        const uint32_t st = s0 + (uint32_t)((g) % 3) * TSTAGE;                 \
        const __half* An = Ap + (g) * 32;                                      \
        const __half* Bn = Bp + (g) * 32;                                      \
        CP_ASYNC16(st + aStOff, An);                                           \
        CP_ASYNC16(st + aStOff + 64u * 80u, An + (size_t)64 * lda);            \
        CP_ASYNC16(st + bStOff, Bn);                                           \
        CP_ASYNC16(st + bStOff + 64u * 80u, Bn + (size_t)64 * ldb);            \
        CP_COMMIT();                                                           \
    } while (0)

    ISSUE_TILE(0);
    ISSUE_TILE(1);

    for (int it = 0; it < nIters; ++it) {
        if (it + 1 < nIters) { CP_WAIT(1); } else { CP_WAIT(0); }
        __syncthreads();
        if (it + 2 < nIters) ISSUE_TILE(it + 2);

        const uint32_t cur = (uint32_t)(it % 3) * TSTAGE;
#pragma unroll
        for (int ks = 0; ks < 2; ++ks) {
            uint32_t a[4][4], b[4][2];
#pragma unroll
            for (int mi = 0; mi < 4; ++mi)
                LDSM_X4(a[mi][0], a[mi][1], a[mi][2], a[mi][3],
                        aLdm + cur + (uint32_t)(mi * 16 * 80 + ks * 32));
            LDSM_X4(b[0][0], b[0][1], b[1][0], b[1][1],
                    bLdm + cur + (uint32_t)(ks * 32));
            LDSM_X4(b[2][0], b[2][1], b[3][0], b[3][1],
                    bLdm + cur + (uint32_t)(16 * 80 + ks * 32));
#pragma unroll
            for (int mi = 0; mi < 4; ++mi)
#pragma unroll
                for (int ni = 0; ni < 4; ++ni)
                    MMA16816(acc[mi][ni], a[mi], b[ni]);
        }
    }
#undef ISSUE_TILE
}

// ---------------------------------------------------------------------------
// Projection GEMM: D[8192, 1024] = A'[8192, 2048] x B'[1024, 2048]^T + bias
// MODE 0: fp32 row-major. MODE 1: Q heads [hi|lo] scaled. MODE 2: K heads
// [hi|hi]. MODE 3: V^T [hi|hi] chunked for AV.
// ---------------------------------------------------------------------------
template <int MODE>
__global__ __launch_bounds__(256) void proj_mma(
    const __half* __restrict__ Ag, const __half* __restrict__ Bg,
    const float* __restrict__ bias, float* __restrict__ Cf,
    __half* __restrict__ Cs)
{
    extern __shared__ char smem[];
    const int mbase = blockIdx.y * 128;
    const int nbase = blockIdx.x * 128;

    float acc[4][4][4];
#pragma unroll
    for (int i = 0; i < 4; i++)
#pragma unroll
        for (int j = 0; j < 4; j++)
#pragma unroll
            for (int r = 0; r < 4; r++) acc[i][j][r] = 0.0f;

    mma_loop_128x128(smem, Ag + (size_t)mbase * GK, Bg + (size_t)nbase * GK,
                     GK, GK, GK / 32, acc);

    const int lane = threadIdx.x & 31;
    const int warp = threadIdx.x >> 5;
    const int wm = (warp >> 2) * 64;
    const int wn = (warp & 3) * 32;
    const int g = lane >> 2, tg = lane & 3;

#pragma unroll
    for (int mi = 0; mi < 4; ++mi) {
#pragma unroll
        for (int ni = 0; ni < 4; ++ni) {
#pragma unroll
            for (int half = 0; half < 2; ++half) {
                const int m = mbase + wm + mi * 16 + g + half * 8;
                const int n0 = nbase + wn + ni * 8 + tg * 2;
                float v0 = acc[mi][ni][half * 2 + 0] + bias[n0];
                float v1 = acc[mi][ni][half * 2 + 1] + bias[n0 + 1];
                if (MODE == 0) {
                    *(float2*)&Cf[(size_t)m * DMODEL + n0] = make_float2(v0, v1);
                } else {
                    const int z = ((m >> 11) << 4) + (n0 >> 6);
                    const int s = m & (SEQ - 1);
                    const int d = n0 & 63;
                    if (MODE == 1) { v0 *= 0.125f; v1 *= 0.125f; }
                    const __half h0 = __float2half_rn(v0);
                    const __half l0 = __float2half_rn(v0 - __half2float(h0));
                    const __half h1 = __float2half_rn(v1);
                    const __half l1 = __float2half_rn(v1 - __half2float(h1));
                    if (MODE == 1) {         // Q: [hi | lo]
                        __half* p = Cs + ((size_t)z * SEQ + s) * SK;
                        *(uint32_t*)(p + d)      = pack_h2(h0, h1);
                        *(uint32_t*)(p + 64 + d) = pack_h2(l0, l1);
                    } else if (MODE == 2) {  // K: [hi | hi]
                        __half* p = Cs + ((size_t)z * SEQ + s) * SK;
                        const uint32_t hh = pack_h2(h0, h1);
                        *(uint32_t*)(p + d)      = hh;
                        *(uint32_t*)(p + 64 + d) = hh;
                    } else {                 // V^T: per-32-chunk [hi | hi]
                        const size_t b0 =
                            ((size_t)z * DHEAD + d) * VK + 64 * (s >> 5) + (s & 31);
                        Cs[b0]       = h0;
                        Cs[b0 + 32]  = h0;
                        const size_t b1 = b0 + VK;   // d+1 row
                        Cs[b1]       = h1;
                        Cs[b1 + 32]  = h1;
                    }
                }
            }
        }
    }
}

// ---------------------------------------------------------------------------
// Scores GEMM per head-slice z: writes e = exp(score) to attn and per-row
// partial sums (this CTA's 128 cols) to psum[row][blockIdx.x].
// ---------------------------------------------------------------------------
__global__ __launch_bounds__(256) void scores_mma(
    const __half* __restrict__ qsp, const __half* __restrict__ ksp,
    float* __restrict__ attn, float* __restrict__ psum)
{
    extern __shared__ char smem[];
    __shared__ float rowpart[4][128];
    const int z     = blockIdx.z;
    const int qbase = blockIdx.y * 128;
    const int kbase = blockIdx.x * 128;

    float acc[4][4][4];
#pragma unroll
    for (int i = 0; i < 4; i++)
#pragma unroll
        for (int j = 0; j < 4; j++)
#pragma unroll
            for (int r = 0; r < 4; r++) acc[i][j][r] = 0.0f;

    const __half* Abase = qsp + ((size_t)z * SEQ + qbase) * SK;
    const __half* Bbase = ksp + ((size_t)z * SEQ + kbase) * SK;
    mma_loop_128x128(smem, Abase, Bbase, SK, SK, SK / 32, acc);

    const int lane = threadIdx.x & 31;
    const int warp = threadIdx.x >> 5;
    const int wm = (warp >> 2) * 64;
    const int wn = (warp & 3) * 32;
    const int g = lane >> 2, tg = lane & 3;

    float* out = attn + ((size_t)z * SEQ + qbase) * SEQ + kbase;
#pragma unroll
    for (int mi = 0; mi < 4; ++mi) {
#pragma unroll
        for (int half = 0; half < 2; ++half) {
            const int r = wm + mi * 16 + g + half * 8;
            float s8 = 0.0f;
#pragma unroll
            for (int ni = 0; ni < 4; ++ni) {
                const int c = wn + ni * 8 + tg * 2;
                float2 v;
                v.x = __expf(acc[mi][ni][half * 2 + 0]);
                v.y = __expf(acc[mi][ni][half * 2 + 1]);
                *(float2*)&out[(size_t)r * SEQ + c] = v;
                s8 += v.x + v.y;
            }
            s8 += __shfl_xor_sync(0xffffffffu, s8, 1);
            s8 += __shfl_xor_sync(0xffffffffu, s8, 2);
            if (tg == 0) rowpart[warp & 3][r] = s8;
        }
    }
    __syncthreads();
    if (threadIdx.x < 128) {
        const float s = (rowpart[0][threadIdx.x] + rowpart[1][threadIdx.x])
                      + (rowpart[2][threadIdx.x] + rowpart[3][threadIdx.x]);
        psum[((size_t)z * SEQ + qbase + threadIdx.x) * 16 + blockIdx.x] = s;
    }
}

// ---------------------------------------------------------------------------
// AV GEMM: per z: O[q,d] = sum_k P[q,k] V[k,d]. CTA 128x64, K_eff 4096.
// Reads e from attn, normalizes on the fly, writes p back to attn, converts
// p to [hi|lo] fp16 for HMMA. V [hi|hi] streamed via cp.async.
// Stage layout (30720 B each): A 2sub x128x40 (20480), B 2sub x64x40 (10240).
// ---------------------------------------------------------------------------
#define AV_STAGE 30720u
#define AV_SMEM  (2 * 30720)

__global__ __launch_bounds__(256) void av_mma(
    float* __restrict__ attn, const float* __restrict__ psum,
    const __half* __restrict__ vsp, __half* __restrict__ ohs)
{
    extern __shared__ char smem[];
    const int z = blockIdx.y;
    const int mbase = blockIdx.x * 128;
    const int b = z >> 4, h = z & 15;
    const int tid = threadIdx.x, lane = tid & 31, warp = tid >> 5;
    const int wm = (warp >> 1) * 32, wn = (warp & 1) * 32;

    float* P = attn + ((size_t)z * SEQ + mbase) * SEQ;
    const __half* Vb = vsp + (size_t)z * DHEAD * VK;
    const float* ps = psum + ((size_t)z * SEQ + mbase) * 16;

    float inv[4];
#pragma unroll
    for (int i = 0; i < 4; ++i) {
        const int row = (tid + i * 256) >> 3;
        const float* pr = ps + (size_t)row * 16;
        float s = 0.0f;
#pragma unroll
        for (int j = 0; j < 16; ++j) s += pr[j];
        inv[i] = 1.0f / s;
    }

    float acc[2][4][4];
#pragma unroll
    for (int i = 0; i < 2; i++)
#pragma unroll
        for (int j = 0; j < 4; j++)
#pragma unroll
            for (int r = 0; r < 4; r++) acc[i][j][r] = 0.0f;

    const uint32_t s0 = smem_u32(smem);
    const int mrow = lane & 15;
    const int kA = (lane & 16) ? 16 : 0;
    const int nr = (lane & 7) + ((lane & 16) ? 8 : 0);
    const int kB = (lane & 8) ? 16 : 0;

    // V cp.async: 512 x 16B chunks per stage, 2 per thread
#define AV_ISSUE_V(gIt)                                                        \
    do {                                                                       \
        const uint32_t st = s0 + (uint32_t)((gIt) & 1) * AV_STAGE + 20480u;    \
        _Pragma("unroll")                                                      \
        for (int i = 0; i < 2; ++i) {                                          \
            const int idx = tid + i * 256;                                     \
            const int sub = idx >> 8, rem = idx & 255;                         \
            const int d = rem >> 2, jc = (rem & 3) * 8;                        \
            CP_ASYNC16(st + (uint32_t)(sub * 5120 + d * 80 + jc * 2),          \
                       Vb + (size_t)d * VK + (gIt) * 64 + sub * 32 + jc);      \
        }                                                                      \
        CP_COMMIT();                                                           \
    } while (0)

    AV_ISSUE_V(0);

    float4 pa[4];
#pragma unroll
    for (int i = 0; i < 4; ++i) {
        const int idx = tid + i * 256;
        pa[i] = *(const float4*)&P[(size_t)(idx >> 3) * SEQ + (idx & 7) * 4];
    }

    const int nIt = SEQ / 32;   // 64
    for (int it = 0; it < nIt; ++it) {
        const uint32_t stOff = (uint32_t)(it & 1) * AV_STAGE;
        // normalize, write back p, convert to [hi|lo] -> smem subs
#pragma unroll
        for (int i = 0; i < 4; ++i) {
            const int idx = tid + i * 256;
            const int row = idx >> 3, c4 = (idx & 7) * 4;
            float xs[4] = {pa[i].x * inv[i], pa[i].y * inv[i],
                           pa[i].z * inv[i], pa[i].w * inv[i]};
            *(float4*)&P[(size_t)row * SEQ + it * 32 + c4] =
                make_float4(xs[0], xs[1], xs[2], xs[3]);
            __half hi[4], lo[4];
#pragma unroll
            for (int j = 0; j < 4; ++j) {
                hi[j] = __float2half_rn(xs[j]);
                lo[j] = __float2half_rn(xs[j] - __half2float(hi[j]));
            }
            uint2 hp, lp;
            hp.x = pack_h2(hi[0], hi[1]); hp.y = pack_h2(hi[2], hi[3]);
            lp.x = pack_h2(lo[0], lo[1]); lp.y = pack_h2(lo[2], lo[3]);
            const uint32_t ro = (uint32_t)(row * 80 + c4 * 2);
            *(uint2*)(smem + stOff + ro)          = hp;   // sub 0: hi
            *(uint2*)(smem + stOff + 10240 + ro)  = lp;   // sub 1: lo
        }
        if (it + 1 < nIt) {
#pragma unroll
            for (int i = 0; i < 4; ++i) {
                const int idx = tid + i * 256;
                pa[i] = *(const float4*)&P[(size_t)(idx >> 3) * SEQ +
                                           (it + 1) * 32 + (idx & 7) * 4];
            }
        }
        CP_WAIT(0);            // V(it) complete
        __syncthreads();       // publish P stores + V; proves MMA(it-1) done
        if (it + 1 < nIt) AV_ISSUE_V(it + 1);

#pragma unroll
        for (int sub = 0; sub < 2; ++sub) {
            const uint32_t aBase = s0 + stOff + (uint32_t)sub * 10240u;
            const uint32_t bBase = s0 + stOff + 20480u + (uint32_t)sub * 5120u;
#pragma unroll
            for (int ks = 0; ks < 2; ++ks) {
                uint32_t a[2][4], bq[4][2];
#pragma unroll
                for (int mi = 0; mi < 2; ++mi)
                    LDSM_X4(a[mi][0], a[mi][1], a[mi][2], a[mi][3],
                            aBase + (uint32_t)((wm + mi * 16 + mrow) * 80 + kA + ks * 32));
                LDSM_X4(bq[0][0], bq[0][1], bq[1][0], bq[1][1],
                        bBase + (uint32_t)((wn + nr) * 80 + kB + ks * 32));
                LDSM_X4(bq[2][0], bq[2][1], bq[3][0], bq[3][1],
                        bBase + (uint32_t)((wn + 16 + nr) * 80 + kB + ks * 32));
#pragma unroll
                for (int mi = 0; mi < 2; ++mi)
#pragma unroll
                    for (int ni = 0; ni < 4; ++ni)
                        MMA16816(acc[mi][ni], a[mi], bq[ni]);
            }
        }
    }
#undef AV_ISSUE_V

    // epilogue -> g_ohs [hi|lo]
    const int g = lane >> 2, tg = lane & 3;
#pragma unroll
    for (int mi = 0; mi < 2; ++mi) {
#pragma unroll
        for (int ni = 0; ni < 4; ++ni) {
#pragma unroll
            for (int half = 0; half < 2; ++half) {
                const int r = wm + mi * 16 + g + half * 8;
                const int c = wn + ni * 8 + tg * 2;
                const float v0 = acc[mi][ni][half * 2 + 0];
                const float v1 = acc[mi][ni][half * 2 + 1];
                const __half h0 = __float2half_rn(v0);
                const __half l0 = __float2half_rn(v0 - __half2float(h0));
                const __half h1 = __float2half_rn(v1);
                const __half l1 = __float2half_rn(v1 - __half2float(h1));
                const size_t row = (size_t)(b * SEQ + mbase + r);
                __half* p = ohs + row * GK + h * DHEAD + c;
                *(uint32_t*)p          = pack_h2(h0, h1);
                *(uint32_t*)(p + 1024) = pack_h2(l0, l1);
            }
        }
    }
}

// ---------------------------------------------------------------------------
// prep_act: X[R,1024] fp32 -> Y[R,2048] fp16 as [hi | lo]
// ---------------------------------------------------------------------------
__global__ __launch_bounds__(256) void prep_act(
    const float* __restrict__ X, __half* __restrict__ Y, int total4)
{
    int i = blockIdx.x * 256 + threadIdx.x;
    if (i >= total4) return;
    float4 xv = ((const float4*)X)[i];
    int r = i >> 8;
    int k = (i & 255) * 4;
    __half* p = Y + (size_t)r * GK + k;

    float xs[4] = {xv.x, xv.y, xv.z, xv.w};
    __half hi[4], lo[4];
#pragma unroll
    for (int j = 0; j < 4; j++) {
        hi[j] = __float2half_rn(xs[j]);
        lo[j] = __float2half_rn(xs[j] - __half2float(hi[j]));
    }
    *(uint32_t*)(p)          = pack_h2(hi[0], hi[1]);
    *(uint32_t*)(p + 2)      = pack_h2(hi[2], hi[3]);
    *(uint32_t*)(p + 1024)   = pack_h2(lo[0], lo[1]);
    *(uint32_t*)(p + 1026)   = pack_h2(lo[2], lo[3]);
}

// ---------------------------------------------------------------------------
// prep_wgt: W[1024,1024] fp32 (K rows) -> Ws[N=1024, 2048] fp16 [hi | hi]
// ---------------------------------------------------------------------------
__global__ __launch_bounds__(256) void prep_wgt(
    const float* __restrict__ W, __half* __restrict__ Ws)
{
    __shared__ float t[32][33];
    const int k0 = blockIdx.y * 32, n0 = blockIdx.x * 32;
    const int tx = threadIdx.x, ty = threadIdx.y;   // (32, 8)
#pragma unroll
    for (int r = ty; r < 32; r += 8)
        t[r][tx] = W[(size_t)(k0 + r) * DMODEL + n0 + tx];
    __syncthreads();
#pragma unroll
    for (int r = ty; r < 32; r += 8) {
        const int n = n0 + r;
        const int k = k0 + tx;
        const __half hi = __float2half_rn(t[tx][r]);
        __half* p = Ws + (size_t)n * GK;
        p[k]        = hi;
        p[1024 + k] = hi;
    }
}

// ---------------------------------------------------------------------------
extern "C" void kernel_launch(void* const* d_in, const int* in_sizes, int n_in,
                              void* d_out, int out_size)
{
    const float* q  = (const float*)d_in[0];
    const float* k  = (const float*)d_in[1];
    const float* v  = (const float*)d_in[2];
    const float* Wq = (const float*)d_in[3];
    const float* bq = (const float*)d_in[4];
    const float* Wk = (const float*)d_in[5];
    const float* bk = (const float*)d_in[6];
    const float* Wv = (const float*)d_in[7];
    const float* bv = (const float*)d_in[8];
    const float* Wo = (const float*)d_in[9];
    const float* bo = (const float*)d_in[10];

    float* out  = (float*)d_out;
    float* attn = out + OUT_ELEMS;

    __half *qs, *ks, *vs, *ohs, *wqs, *wks, *wvs, *wos, *qsp, *ksp, *vsp;
    float* psum;
    cudaGetSymbolAddress((void**)&qs,  g_qs);
    cudaGetSymbolAddress((void**)&ks,  g_ks);
    cudaGetSymbolAddress((void**)&vs,  g_vs);
    cudaGetSymbolAddress((void**)&ohs, g_ohs);
    cudaGetSymbolAddress((void**)&wqs, g_wqs);
    cudaGetSymbolAddress((void**)&wks, g_wks);
    cudaGetSymbolAddress((void**)&wvs, g_wvs);
    cudaGetSymbolAddress((void**)&wos, g_wos);
    cudaGetSymbolAddress((void**)&qsp, g_qsp);
    cudaGetSymbolAddress((void**)&ksp, g_ksp);
    cudaGetSymbolAddress((void**)&vsp, g_vsp);
    cudaGetSymbolAddress((void**)&psum, g_psum);

    cudaFuncSetAttribute(proj_mma<0>, cudaFuncAttributeMaxDynamicSharedMemorySize, MAIN_SMEM);
    cudaFuncSetAttribute(proj_mma<1>, cudaFuncAttributeMaxDynamicSharedMemorySize, MAIN_SMEM);
    cudaFuncSetAttribute(proj_mma<2>, cudaFuncAttributeMaxDynamicSharedMemorySize, MAIN_SMEM);
    cudaFuncSetAttribute(proj_mma<3>, cudaFuncAttributeMaxDynamicSharedMemorySize, MAIN_SMEM);
    cudaFuncSetAttribute(scores_mma,  cudaFuncAttributeMaxDynamicSharedMemorySize, MAIN_SMEM);
    cudaFuncSetAttribute(av_mma,      cudaFuncAttributeMaxDynamicSharedMemorySize, AV_SMEM);

    const int act4 = MROWS * DMODEL / 4;
    dim3 wgrid(32, 32);
    dim3 wblk(32, 8);
    dim3 ggrid(DMODEL / 128, MROWS / 128);  // (8, 64)

    // 0) fp16 2-term conversions
    prep_wgt<<<wgrid, wblk>>>(Wq, wqs);
    prep_wgt<<<wgrid, wblk>>>(Wk, wks);
    prep_wgt<<<wgrid, wblk>>>(Wv, wvs);
    prep_wgt<<<wgrid, wblk>>>(Wo, wos);
    prep_act<<<(act4 + 255) / 256, 256>>>(q, qs, act4);
    prep_act<<<(act4 + 255) / 256, 256>>>(k, ks, act4);
    prep_act<<<(act4 + 255) / 256, 256>>>(v, vs, act4);

    // 1) Q/K/V projections (HMMA)
    proj_mma<1><<<ggrid, 256, MAIN_SMEM>>>(qs, wqs, bq, nullptr, qsp);
    proj_mma<2><<<ggrid, 256, MAIN_SMEM>>>(ks, wks, bk, nullptr, ksp);
    proj_mma<3><<<ggrid, 256, MAIN_SMEM>>>(vs, wvs, bv, nullptr, vsp);

    // 2) Scores -> e = exp(score) into attn + per-row partial sums
    dim3 gs(SEQ / 128, SEQ / 128, NZ);  // (16, 16, 64)
    scores_mma<<<gs, 256, MAIN_SMEM>>>(qsp, ksp, attn, psum);

    // 3) AV: normalize on the fly, write p back, O -> g_ohs [hi|lo]
    dim3 ga(SEQ / 128, NZ);  // (16, 64)
    av_mma<<<ga, 256, AV_SMEM>>>(attn, psum, vsp, ohs);

    // 4) Output projection -> d_out
    proj_mma<0><<<ggrid, 256, MAIN_SMEM>>>(ohs, wos, bo, out, nullptr);
}

// round 9
// speedup vs baseline: 3.3844x; 1.0037x over previous
#include <cuda_runtime.h>
#include <cuda_fp16.h>
#include <cstdint>

// Problem constants
#define BATCH 4
#define SEQ   2048
#define DMODEL 1024
#define NHEAD 16
#define DHEAD 64
#define MROWS (BATCH * SEQ)                       // 8192
#define OUT_ELEMS ((size_t)BATCH * SEQ * DMODEL)  // 8388608
#define GK 2048                                   // fp16 2-term K (2 x 1024)
#define SK 128                                    // fp16 2-term K for scores
#define NZ (BATCH * NHEAD)                        // 64 head-slices
#define VK 4096                                   // fp16 2-term K_eff for AV

// ---------------------------------------------------------------------------
// Scratch (device globals; allocation-free rule)
// ---------------------------------------------------------------------------
__device__ __half g_qs [(size_t)MROWS * GK];    // activations [hi | lo]
__device__ __half g_ks [(size_t)MROWS * GK];
__device__ __half g_vs [(size_t)MROWS * GK];
__device__ __half g_ohs[(size_t)MROWS * GK];
__device__ __half g_wqs[(size_t)DMODEL * GK];   // weights^T [hi | hi]
__device__ __half g_wks[(size_t)DMODEL * GK];
__device__ __half g_wvs[(size_t)DMODEL * GK];
__device__ __half g_wos[(size_t)DMODEL * GK];
__device__ __half g_qsp[(size_t)NZ * SEQ * SK]; // Q heads [hi|lo], pre-scaled 0.125
__device__ __half g_ksp[(size_t)NZ * SEQ * SK]; // K heads [hi|hi]
__device__ __half g_vsp[(size_t)NZ * DHEAD * VK]; // V^T, per-32-chunk [hi|hi]
__device__ float g_psum[(size_t)NZ * SEQ * 16];

// ---------------------------------------------------------------------------
// MMA / async-copy helpers
// ---------------------------------------------------------------------------
__device__ __forceinline__ uint32_t smem_u32(const void* p) {
    uint32_t a;
    asm("{ .reg .u64 t; cvta.to.shared.u64 t, %1; cvt.u32.u64 %0, t; }"
        : "=r"(a) : "l"(p));
    return a;
}

#define LDSM_X4(r0, r1, r2, r3, addr)                                          \
    asm volatile("ldmatrix.sync.aligned.m8n8.x4.shared.b16 {%0,%1,%2,%3}, [%4];" \
                 : "=r"(r0), "=r"(r1), "=r"(r2), "=r"(r3) : "r"(addr))

#define MMA16816(d, a, b)                                                      \
    asm volatile("mma.sync.aligned.m16n8k16.row.col.f32.f16.f16.f32 "          \
                 "{%0,%1,%2,%3}, {%4,%5,%6,%7}, {%8,%9}, {%0,%1,%2,%3};"       \
                 : "+f"((d)[0]), "+f"((d)[1]), "+f"((d)[2]), "+f"((d)[3])      \
                 : "r"((a)[0]), "r"((a)[1]), "r"((a)[2]), "r"((a)[3]),         \
                   "r"((b)[0]), "r"((b)[1]))

#define CP_ASYNC16(dst, src)                                                   \
    asm volatile("cp.async.cg.shared.global [%0], [%1], 16;"                   \
                 :: "r"(dst), "l"(src))
#define CP_COMMIT() asm volatile("cp.async.commit_group;" ::: "memory")
#define CP_WAIT(n)  asm volatile("cp.async.wait_group %0;" :: "n"(n) : "memory")

__device__ __forceinline__ uint32_t pack_h2(__half a, __half b) {
    __half2 h = __halves2half2(a, b);
    return *(uint32_t*)&h;
}

// One pipeline stage of the 128x128 loop: A[128][40] then B[128][40] halves.
#define TSTAGE 20480u
#define MAIN_SMEM (3 * 20480)     // 61440

// Core loop: CTA 128x128, 8 warps (2Mx4N), K-step 32,
// 3-stage cp.async pipeline, ONE barrier per iteration. nIters >= 2.
__device__ __forceinline__ void mma_loop_128x128(
    char* smem, const __half* __restrict__ Abase,
    const __half* __restrict__ Bbase,
    int lda, int ldb, int nIters, float acc[4][4][4])
{
    const int tid  = threadIdx.x;
    const int lane = tid & 31;
    const int warp = tid >> 5;
    const int wm = (warp >> 2) * 64;
    const int wn = (warp & 3) * 32;

    const int grow = tid >> 2;
    const int gcol = (tid & 3) * 8;
    const __half* Ap = Abase + (size_t)grow * lda + gcol;
    const __half* Bp = Bbase + (size_t)grow * ldb + gcol;

    const uint32_t s0 = smem_u32(smem);
    const uint32_t aStOff = (uint32_t)(grow * 80 + gcol * 2);
    const uint32_t bStOff = 10240u + (uint32_t)(grow * 80 + gcol * 2);

    const int mrow  = lane & 15;
    const int kA    = (lane & 16) ? 16 : 0;
    const int nrow  = (lane & 7) + ((lane & 16) ? 8 : 0);
    const int kB    = (lane & 8) ? 16 : 0;
    const uint32_t aLdm = s0 + (uint32_t)((wm + mrow) * 80 + kA);
    const uint32_t bLdm = s0 + 10240u + (uint32_t)((wn + nrow) * 80 + kB);

#define ISSUE_TILE(g)                                                          \
    do {                                                                       \
        const uint32_t st = s0 + (uint32_t)((g) % 3) * TSTAGE;                 \
        const __half* An = Ap + (g) * 32;                                      \
        const __half* Bn = Bp + (g) * 32;                                      \
        CP_ASYNC16(st + aStOff, An);                                           \
        CP_ASYNC16(st + aStOff + 64u * 80u, An + (size_t)64 * lda);            \
        CP_ASYNC16(st + bStOff, Bn);                                           \
        CP_ASYNC16(st + bStOff + 64u * 80u, Bn + (size_t)64 * ldb);            \
        CP_COMMIT();                                                           \
    } while (0)

    ISSUE_TILE(0);
    ISSUE_TILE(1);

    for (int it = 0; it < nIters; ++it) {
        if (it + 1 < nIters) { CP_WAIT(1); } else { CP_WAIT(0); }
        __syncthreads();
        if (it + 2 < nIters) ISSUE_TILE(it + 2);

        const uint32_t cur = (uint32_t)(it % 3) * TSTAGE;
#pragma unroll
        for (int ks = 0; ks < 2; ++ks) {
            uint32_t a[4][4], b[4][2];
#pragma unroll
            for (int mi = 0; mi < 4; ++mi)
                LDSM_X4(a[mi][0], a[mi][1], a[mi][2], a[mi][3],
                        aLdm + cur + (uint32_t)(mi * 16 * 80 + ks * 32));
            LDSM_X4(b[0][0], b[0][1], b[1][0], b[1][1],
                    bLdm + cur + (uint32_t)(ks * 32));
            LDSM_X4(b[2][0], b[2][1], b[3][0], b[3][1],
                    bLdm + cur + (uint32_t)(16 * 80 + ks * 32));
#pragma unroll
            for (int mi = 0; mi < 4; ++mi)
#pragma unroll
                for (int ni = 0; ni < 4; ++ni)
                    MMA16816(acc[mi][ni], a[mi], b[ni]);
        }
    }
#undef ISSUE_TILE
}

// ---------------------------------------------------------------------------
// Merged Q/K/V projection: grid (8, 64, 3). z=0:Q, z=1:K, z=2:V.
// ---------------------------------------------------------------------------
struct QKVArgs {
    const __half* A[3];
    const __half* W[3];
    const float*  bias[3];
    __half*       C[3];
};

__global__ __launch_bounds__(256) void proj_qkv(QKVArgs args)
{
    extern __shared__ char smem[];
    const int zk = blockIdx.z;       // 0=Q, 1=K, 2=V
    const int mbase = blockIdx.y * 128;
    const int nbase = blockIdx.x * 128;

    const __half* Ag = args.A[zk];
    const __half* Bg = args.W[zk];
    const float* bias = args.bias[zk];
    __half* Cs = args.C[zk];

    float acc[4][4][4];
#pragma unroll
    for (int i = 0; i < 4; i++)
#pragma unroll
        for (int j = 0; j < 4; j++)
#pragma unroll
            for (int r = 0; r < 4; r++) acc[i][j][r] = 0.0f;

    mma_loop_128x128(smem, Ag + (size_t)mbase * GK, Bg + (size_t)nbase * GK,
                     GK, GK, GK / 32, acc);

    const int lane = threadIdx.x & 31;
    const int warp = threadIdx.x >> 5;
    const int wm = (warp >> 2) * 64;
    const int wn = (warp & 3) * 32;
    const int g = lane >> 2, tg = lane & 3;

#pragma unroll
    for (int mi = 0; mi < 4; ++mi) {
#pragma unroll
        for (int ni = 0; ni < 4; ++ni) {
#pragma unroll
            for (int half = 0; half < 2; ++half) {
                const int m = mbase + wm + mi * 16 + g + half * 8;
                const int n0 = nbase + wn + ni * 8 + tg * 2;
                float v0 = acc[mi][ni][half * 2 + 0] + bias[n0];
                float v1 = acc[mi][ni][half * 2 + 1] + bias[n0 + 1];
                const int z = ((m >> 11) << 4) + (n0 >> 6);
                const int s = m & (SEQ - 1);
                const int d = n0 & 63;
                if (zk == 0) { v0 *= 0.125f; v1 *= 0.125f; }
                const __half h0 = __float2half_rn(v0);
                const __half h1 = __float2half_rn(v1);
                if (zk == 0) {           // Q: [hi | lo], pre-scaled
                    const __half l0 = __float2half_rn(v0 - __half2float(h0));
                    const __half l1 = __float2half_rn(v1 - __half2float(h1));
                    __half* p = Cs + ((size_t)z * SEQ + s) * SK;
                    *(uint32_t*)(p + d)      = pack_h2(h0, h1);
                    *(uint32_t*)(p + 64 + d) = pack_h2(l0, l1);
                } else if (zk == 1) {    // K: [hi | hi]
                    __half* p = Cs + ((size_t)z * SEQ + s) * SK;
                    const uint32_t hh = pack_h2(h0, h1);
                    *(uint32_t*)(p + d)      = hh;
                    *(uint32_t*)(p + 64 + d) = hh;
                } else {                 // V^T: per-32-chunk [hi | hi]
                    const size_t b0 =
                        ((size_t)z * DHEAD + d) * VK + 64 * (s >> 5) + (s & 31);
                    Cs[b0]       = h0;
                    Cs[b0 + 32]  = h0;
                    const size_t b1 = b0 + VK;   // d+1 row
                    Cs[b1]       = h1;
                    Cs[b1 + 32]  = h1;
                }
            }
        }
    }
}

// ---------------------------------------------------------------------------
// Output projection: D[8192,1024] fp32 = ohs[8192,2048] x wos[1024,2048]^T + bias
// ---------------------------------------------------------------------------
__global__ __launch_bounds__(256) void proj_out(
    const __half* __restrict__ Ag, const __half* __restrict__ Bg,
    const float* __restrict__ bias, float* __restrict__ Cf)
{
    extern __shared__ char smem[];
    const int mbase = blockIdx.y * 128;
    const int nbase = blockIdx.x * 128;

    float acc[4][4][4];
#pragma unroll
    for (int i = 0; i < 4; i++)
#pragma unroll
        for (int j = 0; j < 4; j++)
#pragma unroll
            for (int r = 0; r < 4; r++) acc[i][j][r] = 0.0f;

    mma_loop_128x128(smem, Ag + (size_t)mbase * GK, Bg + (size_t)nbase * GK,
                     GK, GK, GK / 32, acc);

    const int lane = threadIdx.x & 31;
    const int warp = threadIdx.x >> 5;
    const int wm = (warp >> 2) * 64;
    const int wn = (warp & 3) * 32;
    const int g = lane >> 2, tg = lane & 3;

#pragma unroll
    for (int mi = 0; mi < 4; ++mi) {
#pragma unroll
        for (int ni = 0; ni < 4; ++ni) {
#pragma unroll
            for (int half = 0; half < 2; ++half) {
                const int m = mbase + wm + mi * 16 + g + half * 8;
                const int n0 = nbase + wn + ni * 8 + tg * 2;
                float v0 = acc[mi][ni][half * 2 + 0] + bias[n0];
                float v1 = acc[mi][ni][half * 2 + 1] + bias[n0 + 1];
                *(float2*)&Cf[(size_t)m * DMODEL + n0] = make_float2(v0, v1);
            }
        }
    }
}

// ---------------------------------------------------------------------------
// Scores GEMM per head-slice z: writes e = exp(score) to attn and per-row
// partial sums (this CTA's 128 cols) to psum[row][blockIdx.x].
// ---------------------------------------------------------------------------
__global__ __launch_bounds__(256) void scores_mma(
    const __half* __restrict__ qsp, const __half* __restrict__ ksp,
    float* __restrict__ attn, float* __restrict__ psum)
{
    extern __shared__ char smem[];
    __shared__ float rowpart[4][128];
    const int z     = blockIdx.z;
    const int qbase = blockIdx.y * 128;
    const int kbase = blockIdx.x * 128;

    float acc[4][4][4];
#pragma unroll
    for (int i = 0; i < 4; i++)
#pragma unroll
        for (int j = 0; j < 4; j++)
#pragma unroll
            for (int r = 0; r < 4; r++) acc[i][j][r] = 0.0f;

    const __half* Abase = qsp + ((size_t)z * SEQ + qbase) * SK;
    const __half* Bbase = ksp + ((size_t)z * SEQ + kbase) * SK;
    mma_loop_128x128(smem, Abase, Bbase, SK, SK, SK / 32, acc);

    const int lane = threadIdx.x & 31;
    const int warp = threadIdx.x >> 5;
    const int wm = (warp >> 2) * 64;
    const int wn = (warp & 3) * 32;
    const int g = lane >> 2, tg = lane & 3;

    float* out = attn + ((size_t)z * SEQ + qbase) * SEQ + kbase;
#pragma unroll
    for (int mi = 0; mi < 4; ++mi) {
#pragma unroll
        for (int half = 0; half < 2; ++half) {
            const int r = wm + mi * 16 + g + half * 8;
            float s8 = 0.0f;
#pragma unroll
            for (int ni = 0; ni < 4; ++ni) {
                const int c = wn + ni * 8 + tg * 2;
                float2 v;
                v.x = __expf(acc[mi][ni][half * 2 + 0]);
                v.y = __expf(acc[mi][ni][half * 2 + 1]);
                *(float2*)&out[(size_t)r * SEQ + c] = v;
                s8 += v.x + v.y;
            }
            s8 += __shfl_xor_sync(0xffffffffu, s8, 1);
            s8 += __shfl_xor_sync(0xffffffffu, s8, 2);
            if (tg == 0) rowpart[warp & 3][r] = s8;
        }
    }
    __syncthreads();
    if (threadIdx.x < 128) {
        const float s = (rowpart[0][threadIdx.x] + rowpart[1][threadIdx.x])
                      + (rowpart[2][threadIdx.x] + rowpart[3][threadIdx.x]);
        psum[((size_t)z * SEQ + qbase + threadIdx.x) * 16 + blockIdx.x] = s;
    }
}

// ---------------------------------------------------------------------------
// AV GEMM: per z: O[q,d] = sum_k P[q,k] V[k,d]. CTA 128x64, K_eff 4096.
// ---------------------------------------------------------------------------
#define AV_STAGE 30720u
#define AV_SMEM  (2 * 30720)

__global__ __launch_bounds__(256) void av_mma(
    float* __restrict__ attn, const float* __restrict__ psum,
    const __half* __restrict__ vsp, __half* __restrict__ ohs)
{
    extern __shared__ char smem[];
    const int z = blockIdx.y;
    const int mbase = blockIdx.x * 128;
    const int b = z >> 4, h = z & 15;
    const int tid = threadIdx.x, lane = tid & 31, warp = tid >> 5;
    const int wm = (warp >> 1) * 32, wn = (warp & 1) * 32;

    float* P = attn + ((size_t)z * SEQ + mbase) * SEQ;
    const __half* Vb = vsp + (size_t)z * DHEAD * VK;
    const float* ps = psum + ((size_t)z * SEQ + mbase) * 16;

    float inv[4];
#pragma unroll
    for (int i = 0; i < 4; ++i) {
        const int row = (tid + i * 256) >> 3;
        const float* pr = ps + (size_t)row * 16;
        float s = 0.0f;
#pragma unroll
        for (int j = 0; j < 16; ++j) s += pr[j];
        inv[i] = 1.0f / s;
    }

    float acc[2][4][4];
#pragma unroll
    for (int i = 0; i < 2; i++)
#pragma unroll
        for (int j = 0; j < 4; j++)
#pragma unroll
            for (int r = 0; r < 4; r++) acc[i][j][r] = 0.0f;

    const uint32_t s0 = smem_u32(smem);
    const int mrow = lane & 15;
    const int kA = (lane & 16) ? 16 : 0;
    const int nr = (lane & 7) + ((lane & 16) ? 8 : 0);
    const int kB = (lane & 8) ? 16 : 0;

#define AV_ISSUE_V(gIt)                                                        \
    do {                                                                       \
        const uint32_t st = s0 + (uint32_t)((gIt) & 1) * AV_STAGE + 20480u;    \
        _Pragma("unroll")                                                      \
        for (int i = 0; i < 2; ++i) {                                          \
            const int idx = tid + i * 256;                                     \
            const int sub = idx >> 8, rem = idx & 255;                         \
            const int d = rem >> 2, jc = (rem & 3) * 8;                        \
            CP_ASYNC16(st + (uint32_t)(sub * 5120 + d * 80 + jc * 2),          \
                       Vb + (size_t)d * VK + (gIt) * 64 + sub * 32 + jc);      \
        }                                                                      \
        CP_COMMIT();                                                           \
    } while (0)

    AV_ISSUE_V(0);

    float4 pa[4];
#pragma unroll
    for (int i = 0; i < 4; ++i) {
        const int idx = tid + i * 256;
        pa[i] = *(const float4*)&P[(size_t)(idx >> 3) * SEQ + (idx & 7) * 4];
    }

    const int nIt = SEQ / 32;   // 64
    for (int it = 0; it < nIt; ++it) {
        const uint32_t stOff = (uint32_t)(it & 1) * AV_STAGE;
#pragma unroll
        for (int i = 0; i < 4; ++i) {
            const int idx = tid + i * 256;
            const int row = idx >> 3, c4 = (idx & 7) * 4;
            float xs[4] = {pa[i].x * inv[i], pa[i].y * inv[i],
                           pa[i].z * inv[i], pa[i].w * inv[i]};
            *(float4*)&P[(size_t)row * SEQ + it * 32 + c4] =
                make_float4(xs[0], xs[1], xs[2], xs[3]);
            __half hi[4], lo[4];
#pragma unroll
            for (int j = 0; j < 4; ++j) {
                hi[j] = __float2half_rn(xs[j]);
                lo[j] = __float2half_rn(xs[j] - __half2float(hi[j]));
            }
            uint2 hp, lp;
            hp.x = pack_h2(hi[0], hi[1]); hp.y = pack_h2(hi[2], hi[3]);
            lp.x = pack_h2(lo[0], lo[1]); lp.y = pack_h2(lo[2], lo[3]);
            const uint32_t ro = (uint32_t)(row * 80 + c4 * 2);
            *(uint2*)(smem + stOff + ro)          = hp;   // sub 0: hi
            *(uint2*)(smem + stOff + 10240 + ro)  = lp;   // sub 1: lo
        }
        if (it + 1 < nIt) {
#pragma unroll
            for (int i = 0; i < 4; ++i) {
                const int idx = tid + i * 256;
                pa[i] = *(const float4*)&P[(size_t)(idx >> 3) * SEQ +
                                           (it + 1) * 32 + (idx & 7) * 4];
            }
        }
        CP_WAIT(0);
        __syncthreads();
        if (it + 1 < nIt) AV_ISSUE_V(it + 1);

#pragma unroll
        for (int sub = 0; sub < 2; ++sub) {
            const uint32_t aBase = s0 + stOff + (uint32_t)sub * 10240u;
            const uint32_t bBase = s0 + stOff + 20480u + (uint32_t)sub * 5120u;
#pragma unroll
            for (int ks = 0; ks < 2; ++ks) {
                uint32_t a[2][4], bq[4][2];
#pragma unroll
                for (int mi = 0; mi < 2; ++mi)
                    LDSM_X4(a[mi][0], a[mi][1], a[mi][2], a[mi][3],
                            aBase + (uint32_t)((wm + mi * 16 + mrow) * 80 + kA + ks * 32));
                LDSM_X4(bq[0][0], bq[0][1], bq[1][0], bq[1][1],
                        bBase + (uint32_t)((wn + nr) * 80 + kB + ks * 32));
                LDSM_X4(bq[2][0], bq[2][1], bq[3][0], bq[3][1],
                        bBase + (uint32_t)((wn + 16 + nr) * 80 + kB + ks * 32));
#pragma unroll
                for (int mi = 0; mi < 2; ++mi)
#pragma unroll
                    for (int ni = 0; ni < 4; ++ni)
                        MMA16816(acc[mi][ni], a[mi], bq[ni]);
            }
        }
    }
#undef AV_ISSUE_V

    // epilogue -> g_ohs [hi|lo]
    const int g = lane >> 2, tg = lane & 3;
#pragma unroll
    for (int mi = 0; mi < 2; ++mi) {
#pragma unroll
        for (int ni = 0; ni < 4; ++ni) {
#pragma unroll
            for (int half = 0; half < 2; ++half) {
                const int r = wm + mi * 16 + g + half * 8;
                const int c = wn + ni * 8 + tg * 2;
                const float v0 = acc[mi][ni][half * 2 + 0];
                const float v1 = acc[mi][ni][half * 2 + 1];
                const __half h0 = __float2half_rn(v0);
                const __half l0 = __float2half_rn(v0 - __half2float(h0));
                const __half h1 = __float2half_rn(v1);
                const __half l1 = __float2half_rn(v1 - __half2float(h1));
                const size_t row = (size_t)(b * SEQ + mbase + r);
                __half* p = ohs + row * GK + h * DHEAD + c;
                *(uint32_t*)p          = pack_h2(h0, h1);
                *(uint32_t*)(p + 1024) = pack_h2(l0, l1);
            }
        }
    }
}

// ---------------------------------------------------------------------------
// Merged prep_act: grid (total4/256, 3). X[R,1024] fp32 -> Y[R,2048] [hi|lo]
// ---------------------------------------------------------------------------
struct PrepActArgs { const float* X[3]; __half* Y[3]; };

__global__ __launch_bounds__(256) void prep_act3(PrepActArgs args)
{
    const float* X = args.X[blockIdx.y];
    __half* Y = args.Y[blockIdx.y];
    int i = blockIdx.x * 256 + threadIdx.x;
    float4 xv = ((const float4*)X)[i];
    int r = i >> 8;
    int k = (i & 255) * 4;
    __half* p = Y + (size_t)r * GK + k;

    float xs[4] = {xv.x, xv.y, xv.z, xv.w};
    __half hi[4], lo[4];
#pragma unroll
    for (int j = 0; j < 4; j++) {
        hi[j] = __float2half_rn(xs[j]);
        lo[j] = __float2half_rn(xs[j] - __half2float(hi[j]));
    }
    *(uint32_t*)(p)          = pack_h2(hi[0], hi[1]);
    *(uint32_t*)(p + 2)      = pack_h2(hi[2], hi[3]);
    *(uint32_t*)(p + 1024)   = pack_h2(lo[0], lo[1]);
    *(uint32_t*)(p + 1026)   = pack_h2(lo[2], lo[3]);
}

// ---------------------------------------------------------------------------
// Merged prep_wgt: grid (32, 32, 4). W[1024,1024] -> Ws[N=1024,2048] [hi|hi]
// ---------------------------------------------------------------------------
struct PrepWgtArgs { const float* W[4]; __half* Ws[4]; };

__global__ __launch_bounds__(256) void prep_wgt4(PrepWgtArgs args)
{
    const float* W = args.W[blockIdx.z];
    __half* Ws = args.Ws[blockIdx.z];
    __shared__ float t[32][33];
    const int k0 = blockIdx.y * 32, n0 = blockIdx.x * 32;
    const int tx = threadIdx.x, ty = threadIdx.y;   // (32, 8)
#pragma unroll
    for (int r = ty; r < 32; r += 8)
        t[r][tx] = W[(size_t)(k0 + r) * DMODEL + n0 + tx];
    __syncthreads();
#pragma unroll
    for (int r = ty; r < 32; r += 8) {
        const int n = n0 + r;
        const int k = k0 + tx;
        const __half hi = __float2half_rn(t[tx][r]);
        __half* p = Ws + (size_t)n * GK;
        p[k]        = hi;
        p[1024 + k] = hi;
    }
}

// ---------------------------------------------------------------------------
extern "C" void kernel_launch(void* const* d_in, const int* in_sizes, int n_in,
                              void* d_out, int out_size)
{
    const float* q  = (const float*)d_in[0];
    const float* k  = (const float*)d_in[1];
    const float* v  = (const float*)d_in[2];
    const float* Wq = (const float*)d_in[3];
    const float* bq = (const float*)d_in[4];
    const float* Wk = (const float*)d_in[5];
    const float* bk = (const float*)d_in[6];
    const float* Wv = (const float*)d_in[7];
    const float* bv = (const float*)d_in[8];
    const float* Wo = (const float*)d_in[9];
    const float* bo = (const float*)d_in[10];

    float* out  = (float*)d_out;
    float* attn = out + OUT_ELEMS;

    __half *qs, *ks, *vs, *ohs, *wqs, *wks, *wvs, *wos, *qsp, *ksp, *vsp;
    float* psum;
    cudaGetSymbolAddress((void**)&qs,  g_qs);
    cudaGetSymbolAddress((void**)&ks,  g_ks);
    cudaGetSymbolAddress((void**)&vs,  g_vs);
    cudaGetSymbolAddress((void**)&ohs, g_ohs);
    cudaGetSymbolAddress((void**)&wqs, g_wqs);
    cudaGetSymbolAddress((void**)&wks, g_wks);
    cudaGetSymbolAddress((void**)&wvs, g_wvs);
    cudaGetSymbolAddress((void**)&wos, g_wos);
    cudaGetSymbolAddress((void**)&qsp, g_qsp);
    cudaGetSymbolAddress((void**)&ksp, g_ksp);
    cudaGetSymbolAddress((void**)&vsp, g_vsp);
    cudaGetSymbolAddress((void**)&psum, g_psum);

    cudaFuncSetAttribute(proj_qkv,   cudaFuncAttributeMaxDynamicSharedMemorySize, MAIN_SMEM);
    cudaFuncSetAttribute(proj_out,   cudaFuncAttributeMaxDynamicSharedMemorySize, MAIN_SMEM);
    cudaFuncSetAttribute(scores_mma, cudaFuncAttributeMaxDynamicSharedMemorySize, MAIN_SMEM);
    cudaFuncSetAttribute(av_mma,     cudaFuncAttributeMaxDynamicSharedMemorySize, AV_SMEM);

    const int act4 = MROWS * DMODEL / 4;   // 2097152 -> 8192 blocks

    // 0) fp16 2-term conversions (merged launches)
    PrepWgtArgs wargs;
    wargs.W[0] = Wq; wargs.W[1] = Wk; wargs.W[2] = Wv; wargs.W[3] = Wo;
    wargs.Ws[0] = wqs; wargs.Ws[1] = wks; wargs.Ws[2] = wvs; wargs.Ws[3] = wos;
    prep_wgt4<<<dim3(32, 32, 4), dim3(32, 8)>>>(wargs);

    PrepActArgs aargs;
    aargs.X[0] = q; aargs.X[1] = k; aargs.X[2] = v;
    aargs.Y[0] = qs; aargs.Y[1] = ks; aargs.Y[2] = vs;
    prep_act3<<<dim3(act4 / 256, 3), 256>>>(aargs);

    // 1) Q/K/V projections merged (HMMA): grid (8, 64, 3)
    QKVArgs pargs;
    pargs.A[0] = qs;  pargs.A[1] = ks;  pargs.A[2] = vs;
    pargs.W[0] = wqs; pargs.W[1] = wks; pargs.W[2] = wvs;
    pargs.bias[0] = bq; pargs.bias[1] = bk; pargs.bias[2] = bv;
    pargs.C[0] = qsp; pargs.C[1] = ksp; pargs.C[2] = vsp;
    proj_qkv<<<dim3(DMODEL / 128, MROWS / 128, 3), 256, MAIN_SMEM>>>(pargs);

    // 2) Scores -> e = exp(score) into attn + per-row partial sums
    dim3 gs(SEQ / 128, SEQ / 128, NZ);  // (16, 16, 64)
    scores_mma<<<gs, 256, MAIN_SMEM>>>(qsp, ksp, attn, psum);

    // 3) AV: normalize on the fly, write p back, O -> g_ohs [hi|lo]
    dim3 ga(SEQ / 128, NZ);  // (16, 64)
    av_mma<<<ga, 256, AV_SMEM>>>(attn, psum, vsp, ohs);

    // 4) Output projection -> d_out
    proj_out<<<dim3(DMODEL / 128, MROWS / 128), 256, MAIN_SMEM>>>(ohs, wos, bo, out);
}

// round 10
// speedup vs baseline: 3.5107x; 1.0373x over previous
#include <cuda_runtime.h>
#include <cuda_fp16.h>
#include <cstdint>

// Problem constants
#define BATCH 4
#define SEQ   2048
#define DMODEL 1024
#define NHEAD 16
#define DHEAD 64
#define MROWS (BATCH * SEQ)                       // 8192
#define OUT_ELEMS ((size_t)BATCH * SEQ * DMODEL)  // 8388608
#define GK 2048                                   // fp16 2-term K (2 x 1024)
#define SK 128                                    // fp16 2-term K for scores
#define NZ (BATCH * NHEAD)                        // 64 head-slices
#define VK 4096                                   // fp16 2-term K_eff for AV

// ---------------------------------------------------------------------------
// Scratch (device globals; allocation-free rule)
// ---------------------------------------------------------------------------
__device__ __half g_qs [(size_t)MROWS * GK];    // activations [hi | lo]
__device__ __half g_ks [(size_t)MROWS * GK];
__device__ __half g_vs [(size_t)MROWS * GK];
__device__ __half g_ohs[(size_t)MROWS * GK];
__device__ __half g_wqs[(size_t)DMODEL * GK];   // weights^T [hi | hi]
__device__ __half g_wks[(size_t)DMODEL * GK];
__device__ __half g_wvs[(size_t)DMODEL * GK];
__device__ __half g_wos[(size_t)DMODEL * GK];
__device__ __half g_qsp[(size_t)NZ * SEQ * SK]; // Q heads [hi|lo], pre-scaled 0.125
__device__ __half g_ksp[(size_t)NZ * SEQ * SK]; // K heads [hi|hi]
__device__ __half g_vsp[(size_t)NZ * DHEAD * VK]; // V^T, per-32-chunk [hi|hi]
__device__ __half g_eh [(size_t)NZ * SEQ * SEQ]; // unnormalized exp(score), fp16
__device__ float g_psum[(size_t)NZ * SEQ * 16];

// ---------------------------------------------------------------------------
// MMA / async-copy helpers
// ---------------------------------------------------------------------------
__device__ __forceinline__ uint32_t smem_u32(const void* p) {
    uint32_t a;
    asm("{ .reg .u64 t; cvta.to.shared.u64 t, %1; cvt.u32.u64 %0, t; }"
        : "=r"(a) : "l"(p));
    return a;
}

#define LDSM_X4(r0, r1, r2, r3, addr)                                          \
    asm volatile("ldmatrix.sync.aligned.m8n8.x4.shared.b16 {%0,%1,%2,%3}, [%4];" \
                 : "=r"(r0), "=r"(r1), "=r"(r2), "=r"(r3) : "r"(addr))

#define MMA16816(d, a, b)                                                      \
    asm volatile("mma.sync.aligned.m16n8k16.row.col.f32.f16.f16.f32 "          \
                 "{%0,%1,%2,%3}, {%4,%5,%6,%7}, {%8,%9}, {%0,%1,%2,%3};"       \
                 : "+f"((d)[0]), "+f"((d)[1]), "+f"((d)[2]), "+f"((d)[3])      \
                 : "r"((a)[0]), "r"((a)[1]), "r"((a)[2]), "r"((a)[3]),         \
                   "r"((b)[0]), "r"((b)[1]))

#define CP_ASYNC16(dst, src)                                                   \
    asm volatile("cp.async.cg.shared.global [%0], [%1], 16;"                   \
                 :: "r"(dst), "l"(src))
#define CP_COMMIT() asm volatile("cp.async.commit_group;" ::: "memory")
#define CP_WAIT(n)  asm volatile("cp.async.wait_group %0;" :: "n"(n) : "memory")

__device__ __forceinline__ uint32_t pack_h2(__half a, __half b) {
    __half2 h = __halves2half2(a, b);
    return *(uint32_t*)&h;
}

// One pipeline stage of the 128x128 loop: A[128][40] then B[128][40] halves.
#define TSTAGE 20480u
#define MAIN_SMEM (3 * 20480)     // 61440

// Core loop: CTA 128x128, 8 warps (2Mx4N), K-step 32,
// 3-stage cp.async pipeline, ONE barrier per iteration. nIters >= 2.
__device__ __forceinline__ void mma_loop_128x128(
    char* smem, const __half* __restrict__ Abase,
    const __half* __restrict__ Bbase,
    int lda, int ldb, int nIters, float acc[4][4][4])
{
    const int tid  = threadIdx.x;
    const int lane = tid & 31;
    const int warp = tid >> 5;
    const int wm = (warp >> 2) * 64;
    const int wn = (warp & 3) * 32;

    const int grow = tid >> 2;
    const int gcol = (tid & 3) * 8;
    const __half* Ap = Abase + (size_t)grow * lda + gcol;
    const __half* Bp = Bbase + (size_t)grow * ldb + gcol;

    const uint32_t s0 = smem_u32(smem);
    const uint32_t aStOff = (uint32_t)(grow * 80 + gcol * 2);
    const uint32_t bStOff = 10240u + (uint32_t)(grow * 80 + gcol * 2);

    const int mrow  = lane & 15;
    const int kA    = (lane & 16) ? 16 : 0;
    const int nrow  = (lane & 7) + ((lane & 16) ? 8 : 0);
    const int kB    = (lane & 8) ? 16 : 0;
    const uint32_t aLdm = s0 + (uint32_t)((wm + mrow) * 80 + kA);
    const uint32_t bLdm = s0 + 10240u + (uint32_t)((wn + nrow) * 80 + kB);

#define ISSUE_TILE(g)                                                          \
    do {                                                                       \
        const uint32_t st = s0 + (uint32_t)((g) % 3) * TSTAGE;                 \
        const __half* An = Ap + (g) * 32;                                      \
        const __half* Bn = Bp + (g) * 32;                                      \
        CP_ASYNC16(st + aStOff, An);                                           \
        CP_ASYNC16(st + aStOff + 64u * 80u, An + (size_t)64 * lda);            \
        CP_ASYNC16(st + bStOff, Bn);                                           \
        CP_ASYNC16(st + bStOff + 64u * 80u, Bn + (size_t)64 * ldb);            \
        CP_COMMIT();                                                           \
    } while (0)

    ISSUE_TILE(0);
    ISSUE_TILE(1);

    for (int it = 0; it < nIters; ++it) {
        if (it + 1 < nIters) { CP_WAIT(1); } else { CP_WAIT(0); }
        __syncthreads();
        if (it + 2 < nIters) ISSUE_TILE(it + 2);

        const uint32_t cur = (uint32_t)(it % 3) * TSTAGE;
#pragma unroll
        for (int ks = 0; ks < 2; ++ks) {
            uint32_t a[4][4], b[4][2];
#pragma unroll
            for (int mi = 0; mi < 4; ++mi)
                LDSM_X4(a[mi][0], a[mi][1], a[mi][2], a[mi][3],
                        aLdm + cur + (uint32_t)(mi * 16 * 80 + ks * 32));
            LDSM_X4(b[0][0], b[0][1], b[1][0], b[1][1],
                    bLdm + cur + (uint32_t)(ks * 32));
            LDSM_X4(b[2][0], b[2][1], b[3][0], b[3][1],
                    bLdm + cur + (uint32_t)(16 * 80 + ks * 32));
#pragma unroll
            for (int mi = 0; mi < 4; ++mi)
#pragma unroll
                for (int ni = 0; ni < 4; ++ni)
                    MMA16816(acc[mi][ni], a[mi], b[ni]);
        }
    }
#undef ISSUE_TILE
}

// ---------------------------------------------------------------------------
// Merged Q/K/V projection: grid (8, 64, 3). z=0:Q, z=1:K, z=2:V.
// ---------------------------------------------------------------------------
struct QKVArgs {
    const __half* A[3];
    const __half* W[3];
    const float*  bias[3];
    __half*       C[3];
};

__global__ __launch_bounds__(256) void proj_qkv(QKVArgs args)
{
    extern __shared__ char smem[];
    const int zk = blockIdx.z;       // 0=Q, 1=K, 2=V
    const int mbase = blockIdx.y * 128;
    const int nbase = blockIdx.x * 128;

    const __half* Ag = args.A[zk];
    const __half* Bg = args.W[zk];
    const float* bias = args.bias[zk];
    __half* Cs = args.C[zk];

    float acc[4][4][4];
#pragma unroll
    for (int i = 0; i < 4; i++)
#pragma unroll
        for (int j = 0; j < 4; j++)
#pragma unroll
            for (int r = 0; r < 4; r++) acc[i][j][r] = 0.0f;

    mma_loop_128x128(smem, Ag + (size_t)mbase * GK, Bg + (size_t)nbase * GK,
                     GK, GK, GK / 32, acc);

    const int lane = threadIdx.x & 31;
    const int warp = threadIdx.x >> 5;
    const int wm = (warp >> 2) * 64;
    const int wn = (warp & 3) * 32;
    const int g = lane >> 2, tg = lane & 3;

#pragma unroll
    for (int mi = 0; mi < 4; ++mi) {
#pragma unroll
        for (int ni = 0; ni < 4; ++ni) {
#pragma unroll
            for (int half = 0; half < 2; ++half) {
                const int m = mbase + wm + mi * 16 + g + half * 8;
                const int n0 = nbase + wn + ni * 8 + tg * 2;
                float v0 = acc[mi][ni][half * 2 + 0] + bias[n0];
                float v1 = acc[mi][ni][half * 2 + 1] + bias[n0 + 1];
                const int z = ((m >> 11) << 4) + (n0 >> 6);
                const int s = m & (SEQ - 1);
                const int d = n0 & 63;
                if (zk == 0) { v0 *= 0.125f; v1 *= 0.125f; }
                const __half h0 = __float2half_rn(v0);
                const __half h1 = __float2half_rn(v1);
                if (zk == 0) {           // Q: [hi | lo], pre-scaled
                    const __half l0 = __float2half_rn(v0 - __half2float(h0));
                    const __half l1 = __float2half_rn(v1 - __half2float(h1));
                    __half* p = Cs + ((size_t)z * SEQ + s) * SK;
                    *(uint32_t*)(p + d)      = pack_h2(h0, h1);
                    *(uint32_t*)(p + 64 + d) = pack_h2(l0, l1);
                } else if (zk == 1) {    // K: [hi | hi]
                    __half* p = Cs + ((size_t)z * SEQ + s) * SK;
                    const uint32_t hh = pack_h2(h0, h1);
                    *(uint32_t*)(p + d)      = hh;
                    *(uint32_t*)(p + 64 + d) = hh;
                } else {                 // V^T: per-32-chunk [hi | hi]
                    const size_t b0 =
                        ((size_t)z * DHEAD + d) * VK + 64 * (s >> 5) + (s & 31);
                    Cs[b0]       = h0;
                    Cs[b0 + 32]  = h0;
                    const size_t b1 = b0 + VK;   // d+1 row
                    Cs[b1]       = h1;
                    Cs[b1 + 32]  = h1;
                }
            }
        }
    }
}

// ---------------------------------------------------------------------------
// Output projection: D[8192,1024] fp32 = ohs[8192,2048] x wos[1024,2048]^T + bias
// ---------------------------------------------------------------------------
__global__ __launch_bounds__(256) void proj_out(
    const __half* __restrict__ Ag, const __half* __restrict__ Bg,
    const float* __restrict__ bias, float* __restrict__ Cf)
{
    extern __shared__ char smem[];
    const int mbase = blockIdx.y * 128;
    const int nbase = blockIdx.x * 128;

    float acc[4][4][4];
#pragma unroll
    for (int i = 0; i < 4; i++)
#pragma unroll
        for (int j = 0; j < 4; j++)
#pragma unroll
            for (int r = 0; r < 4; r++) acc[i][j][r] = 0.0f;

    mma_loop_128x128(smem, Ag + (size_t)mbase * GK, Bg + (size_t)nbase * GK,
                     GK, GK, GK / 32, acc);

    const int lane = threadIdx.x & 31;
    const int warp = threadIdx.x >> 5;
    const int wm = (warp >> 2) * 64;
    const int wn = (warp & 3) * 32;
    const int g = lane >> 2, tg = lane & 3;

#pragma unroll
    for (int mi = 0; mi < 4; ++mi) {
#pragma unroll
        for (int ni = 0; ni < 4; ++ni) {
#pragma unroll
            for (int half = 0; half < 2; ++half) {
                const int m = mbase + wm + mi * 16 + g + half * 8;
                const int n0 = nbase + wn + ni * 8 + tg * 2;
                float v0 = acc[mi][ni][half * 2 + 0] + bias[n0];
                float v1 = acc[mi][ni][half * 2 + 1] + bias[n0 + 1];
                *(float2*)&Cf[(size_t)m * DMODEL + n0] = make_float2(v0, v1);
            }
        }
    }
}

// ---------------------------------------------------------------------------
// Scores GEMM per head-slice z: writes e = exp(score) as FP16 to g_eh and
// per-row partial sums (of the quantized values) to psum[row][blockIdx.x].
// ---------------------------------------------------------------------------
__global__ __launch_bounds__(256) void scores_mma(
    const __half* __restrict__ qsp, const __half* __restrict__ ksp,
    __half* __restrict__ eh, float* __restrict__ psum)
{
    extern __shared__ char smem[];
    __shared__ float rowpart[4][128];
    const int z     = blockIdx.z;
    const int qbase = blockIdx.y * 128;
    const int kbase = blockIdx.x * 128;

    float acc[4][4][4];
#pragma unroll
    for (int i = 0; i < 4; i++)
#pragma unroll
        for (int j = 0; j < 4; j++)
#pragma unroll
            for (int r = 0; r < 4; r++) acc[i][j][r] = 0.0f;

    const __half* Abase = qsp + ((size_t)z * SEQ + qbase) * SK;
    const __half* Bbase = ksp + ((size_t)z * SEQ + kbase) * SK;
    mma_loop_128x128(smem, Abase, Bbase, SK, SK, SK / 32, acc);

    const int lane = threadIdx.x & 31;
    const int warp = threadIdx.x >> 5;
    const int wm = (warp >> 2) * 64;
    const int wn = (warp & 3) * 32;
    const int g = lane >> 2, tg = lane & 3;

    __half* out = eh + ((size_t)z * SEQ + qbase) * SEQ + kbase;
#pragma unroll
    for (int mi = 0; mi < 4; ++mi) {
#pragma unroll
        for (int half = 0; half < 2; ++half) {
            const int r = wm + mi * 16 + g + half * 8;
            float s8 = 0.0f;
#pragma unroll
            for (int ni = 0; ni < 4; ++ni) {
                const int c = wn + ni * 8 + tg * 2;
                const __half h0 = __float2half_rn(__expf(acc[mi][ni][half * 2 + 0]));
                const __half h1 = __float2half_rn(__expf(acc[mi][ni][half * 2 + 1]));
                *(uint32_t*)&out[(size_t)r * SEQ + c] = pack_h2(h0, h1);
                s8 += __half2float(h0) + __half2float(h1);
            }
            s8 += __shfl_xor_sync(0xffffffffu, s8, 1);
            s8 += __shfl_xor_sync(0xffffffffu, s8, 2);
            if (tg == 0) rowpart[warp & 3][r] = s8;
        }
    }
    __syncthreads();
    if (threadIdx.x < 128) {
        const float s = (rowpart[0][threadIdx.x] + rowpart[1][threadIdx.x])
                      + (rowpart[2][threadIdx.x] + rowpart[3][threadIdx.x]);
        psum[((size_t)z * SEQ + qbase + threadIdx.x) * 16 + blockIdx.x] = s;
    }
}

// ---------------------------------------------------------------------------
// AV GEMM: per z: O[q,d] = sum_k P[q,k] V[k,d]. CTA 128x64, K_eff 4096.
// Reads e (fp16) from g_eh, normalizes (p = e*inv, fp32), writes final attn
// fp32, converts p to [hi|lo] fp16 for HMMA. V [hi|hi] via cp.async.
// ---------------------------------------------------------------------------
#define AV_STAGE 30720u
#define AV_SMEM  (2 * 30720)

__global__ __launch_bounds__(256) void av_mma(
    const __half* __restrict__ eh, float* __restrict__ attn,
    const float* __restrict__ psum,
    const __half* __restrict__ vsp, __half* __restrict__ ohs)
{
    extern __shared__ char smem[];
    const int z = blockIdx.y;
    const int mbase = blockIdx.x * 128;
    const int b = z >> 4, h = z & 15;
    const int tid = threadIdx.x, lane = tid & 31, warp = tid >> 5;
    const int wm = (warp >> 1) * 32, wn = (warp & 1) * 32;

    const __half* E = eh + ((size_t)z * SEQ + mbase) * SEQ;
    float* P = attn + ((size_t)z * SEQ + mbase) * SEQ;
    const __half* Vb = vsp + (size_t)z * DHEAD * VK;
    const float* ps = psum + ((size_t)z * SEQ + mbase) * 16;

    // per-thread rows: row_i = (tid + i*256)>>2, i in {0,1}
    float inv[2];
#pragma unroll
    for (int i = 0; i < 2; ++i) {
        const int row = (tid + i * 256) >> 2;
        const float* pr = ps + (size_t)row * 16;
        float s = 0.0f;
#pragma unroll
        for (int j = 0; j < 16; ++j) s += pr[j];
        inv[i] = 1.0f / s;
    }

    float acc[2][4][4];
#pragma unroll
    for (int i = 0; i < 2; i++)
#pragma unroll
        for (int j = 0; j < 4; j++)
#pragma unroll
            for (int r = 0; r < 4; r++) acc[i][j][r] = 0.0f;

    const uint32_t s0 = smem_u32(smem);
    const int mrow = lane & 15;
    const int kA = (lane & 16) ? 16 : 0;
    const int nr = (lane & 7) + ((lane & 16) ? 8 : 0);
    const int kB = (lane & 8) ? 16 : 0;

#define AV_ISSUE_V(gIt)                                                        \
    do {                                                                       \
        const uint32_t st = s0 + (uint32_t)((gIt) & 1) * AV_STAGE + 20480u;    \
        _Pragma("unroll")                                                      \
        for (int i = 0; i < 2; ++i) {                                          \
            const int idx = tid + i * 256;                                     \
            const int sub = idx >> 8, rem = idx & 255;                         \
            const int d = rem >> 2, jc = (rem & 3) * 8;                        \
            CP_ASYNC16(st + (uint32_t)(sub * 5120 + d * 80 + jc * 2),          \
                       Vb + (size_t)d * VK + (gIt) * 64 + sub * 32 + jc);      \
        }                                                                      \
        CP_COMMIT();                                                           \
    } while (0)

    AV_ISSUE_V(0);

    // e prefetch: 2 x uint4 (8 halves each) per thread
    uint4 pe[2];
#pragma unroll
    for (int i = 0; i < 2; ++i) {
        const int idx = tid + i * 256;
        const int row = idx >> 2, c8 = (idx & 3) * 8;
        pe[i] = *(const uint4*)&E[(size_t)row * SEQ + c8];
    }

    const int nIt = SEQ / 32;   // 64
    for (int it = 0; it < nIt; ++it) {
        const uint32_t stOff = (uint32_t)(it & 1) * AV_STAGE;
#pragma unroll
        for (int i = 0; i < 2; ++i) {
            const int idx = tid + i * 256;
            const int row = idx >> 2, c8 = (idx & 3) * 8;
            const __half2* eh2 = (const __half2*)&pe[i];
            float p[8];
#pragma unroll
            for (int j = 0; j < 4; ++j) {
                float2 f = __half22float2(eh2[j]);
                p[2 * j]     = f.x * inv[i];
                p[2 * j + 1] = f.y * inv[i];
            }
            // final normalized attn (fp32 output)
            float* Pw = &P[(size_t)row * SEQ + it * 32 + c8];
            *(float4*)(Pw)     = make_float4(p[0], p[1], p[2], p[3]);
            *(float4*)(Pw + 4) = make_float4(p[4], p[5], p[6], p[7]);
            // split p -> [hi | lo]
            uint4 hp, lp;
            __half hh[8], ll[8];
#pragma unroll
            for (int j = 0; j < 8; ++j) {
                hh[j] = __float2half_rn(p[j]);
                ll[j] = __float2half_rn(p[j] - __half2float(hh[j]));
            }
            hp.x = pack_h2(hh[0], hh[1]); hp.y = pack_h2(hh[2], hh[3]);
            hp.z = pack_h2(hh[4], hh[5]); hp.w = pack_h2(hh[6], hh[7]);
            lp.x = pack_h2(ll[0], ll[1]); lp.y = pack_h2(ll[2], ll[3]);
            lp.z = pack_h2(ll[4], ll[5]); lp.w = pack_h2(ll[6], ll[7]);
            const uint32_t ro = (uint32_t)(row * 80 + c8 * 2);
            *(uint4*)(smem + stOff + ro)          = hp;   // sub 0: hi
            *(uint4*)(smem + stOff + 10240 + ro)  = lp;   // sub 1: lo
        }
        if (it + 1 < nIt) {
#pragma unroll
            for (int i = 0; i < 2; ++i) {
                const int idx = tid + i * 256;
                const int row = idx >> 2, c8 = (idx & 3) * 8;
                pe[i] = *(const uint4*)&E[(size_t)row * SEQ + (it + 1) * 32 + c8];
            }
        }
        CP_WAIT(0);
        __syncthreads();
        if (it + 1 < nIt) AV_ISSUE_V(it + 1);

#pragma unroll
        for (int sub = 0; sub < 2; ++sub) {
            const uint32_t aBase = s0 + stOff + (uint32_t)sub * 10240u;
            const uint32_t bBase = s0 + stOff + 20480u + (uint32_t)sub * 5120u;
#pragma unroll
            for (int ks = 0; ks < 2; ++ks) {
                uint32_t a[2][4], bq[4][2];
#pragma unroll
                for (int mi = 0; mi < 2; ++mi)
                    LDSM_X4(a[mi][0], a[mi][1], a[mi][2], a[mi][3],
                            aBase + (uint32_t)((wm + mi * 16 + mrow) * 80 + kA + ks * 32));
                LDSM_X4(bq[0][0], bq[0][1], bq[1][0], bq[1][1],
                        bBase + (uint32_t)((wn + nr) * 80 + kB + ks * 32));
                LDSM_X4(bq[2][0], bq[2][1], bq[3][0], bq[3][1],
                        bBase + (uint32_t)((wn + 16 + nr) * 80 + kB + ks * 32));
#pragma unroll
                for (int mi = 0; mi < 2; ++mi)
#pragma unroll
                    for (int ni = 0; ni < 4; ++ni)
                        MMA16816(acc[mi][ni], a[mi], bq[ni]);
            }
        }
    }
#undef AV_ISSUE_V

    // epilogue -> g_ohs [hi|lo]
    const int g = lane >> 2, tg = lane & 3;
#pragma unroll
    for (int mi = 0; mi < 2; ++mi) {
#pragma unroll
        for (int ni = 0; ni < 4; ++ni) {
#pragma unroll
            for (int half = 0; half < 2; ++half) {
                const int r = wm + mi * 16 + g + half * 8;
                const int c = wn + ni * 8 + tg * 2;
                const float v0 = acc[mi][ni][half * 2 + 0];
                const float v1 = acc[mi][ni][half * 2 + 1];
                const __half h0 = __float2half_rn(v0);
                const __half l0 = __float2half_rn(v0 - __half2float(h0));
                const __half h1 = __float2half_rn(v1);
                const __half l1 = __float2half_rn(v1 - __half2float(h1));
                const size_t row = (size_t)(b * SEQ + mbase + r);
                __half* p = ohs + row * GK + h * DHEAD + c;
                *(uint32_t*)p          = pack_h2(h0, h1);
                *(uint32_t*)(p + 1024) = pack_h2(l0, l1);
            }
        }
    }
}

// ---------------------------------------------------------------------------
// Merged prep_act: grid (total4/256, 3). X[R,1024] fp32 -> Y[R,2048] [hi|lo]
// ---------------------------------------------------------------------------
struct PrepActArgs { const float* X[3]; __half* Y[3]; };

__global__ __launch_bounds__(256) void prep_act3(PrepActArgs args)
{
    const float* X = args.X[blockIdx.y];
    __half* Y = args.Y[blockIdx.y];
    int i = blockIdx.x * 256 + threadIdx.x;
    float4 xv = ((const float4*)X)[i];
    int r = i >> 8;
    int k = (i & 255) * 4;
    __half* p = Y + (size_t)r * GK + k;

    float xs[4] = {xv.x, xv.y, xv.z, xv.w};
    __half hi[4], lo[4];
#pragma unroll
    for (int j = 0; j < 4; j++) {
        hi[j] = __float2half_rn(xs[j]);
        lo[j] = __float2half_rn(xs[j] - __half2float(hi[j]));
    }
    *(uint32_t*)(p)          = pack_h2(hi[0], hi[1]);
    *(uint32_t*)(p + 2)      = pack_h2(hi[2], hi[3]);
    *(uint32_t*)(p + 1024)   = pack_h2(lo[0], lo[1]);
    *(uint32_t*)(p + 1026)   = pack_h2(lo[2], lo[3]);
}

// ---------------------------------------------------------------------------
// Merged prep_wgt: grid (32, 32, 4). W[1024,1024] -> Ws[N=1024,2048] [hi|hi]
// ---------------------------------------------------------------------------
struct PrepWgtArgs { const float* W[4]; __half* Ws[4]; };

__global__ __launch_bounds__(256) void prep_wgt4(PrepWgtArgs args)
{
    const float* W = args.W[blockIdx.z];
    __half* Ws = args.Ws[blockIdx.z];
    __shared__ float t[32][33];
    const int k0 = blockIdx.y * 32, n0 = blockIdx.x * 32;
    const int tx = threadIdx.x, ty = threadIdx.y;   // (32, 8)
#pragma unroll
    for (int r = ty; r < 32; r += 8)
        t[r][tx] = W[(size_t)(k0 + r) * DMODEL + n0 + tx];
    __syncthreads();
#pragma unroll
    for (int r = ty; r < 32; r += 8) {
        const int n = n0 + r;
        const int k = k0 + tx;
        const __half hi = __float2half_rn(t[tx][r]);
        __half* p = Ws + (size_t)n * GK;
        p[k]        = hi;
        p[1024 + k] = hi;
    }
}

// ---------------------------------------------------------------------------
extern "C" void kernel_launch(void* const* d_in, const int* in_sizes, int n_in,
                              void* d_out, int out_size)
{
    const float* q  = (const float*)d_in[0];
    const float* k  = (const float*)d_in[1];
    const float* v  = (const float*)d_in[2];
    const float* Wq = (const float*)d_in[3];
    const float* bq = (const float*)d_in[4];
    const float* Wk = (const float*)d_in[5];
    const float* bk = (const float*)d_in[6];
    const float* Wv = (const float*)d_in[7];
    const float* bv = (const float*)d_in[8];
    const float* Wo = (const float*)d_in[9];
    const float* bo = (const float*)d_in[10];

    float* out  = (float*)d_out;
    float* attn = out + OUT_ELEMS;

    __half *qs, *ks, *vs, *ohs, *wqs, *wks, *wvs, *wos, *qsp, *ksp, *vsp, *ehp;
    float* psum;
    cudaGetSymbolAddress((void**)&qs,  g_qs);
    cudaGetSymbolAddress((void**)&ks,  g_ks);
    cudaGetSymbolAddress((void**)&vs,  g_vs);
    cudaGetSymbolAddress((void**)&ohs, g_ohs);
    cudaGetSymbolAddress((void**)&wqs, g_wqs);
    cudaGetSymbolAddress((void**)&wks, g_wks);
    cudaGetSymbolAddress((void**)&wvs, g_wvs);
    cudaGetSymbolAddress((void**)&wos, g_wos);
    cudaGetSymbolAddress((void**)&qsp, g_qsp);
    cudaGetSymbolAddress((void**)&ksp, g_ksp);
    cudaGetSymbolAddress((void**)&vsp, g_vsp);
    cudaGetSymbolAddress((void**)&ehp, g_eh);
    cudaGetSymbolAddress((void**)&psum, g_psum);

    cudaFuncSetAttribute(proj_qkv,   cudaFuncAttributeMaxDynamicSharedMemorySize, MAIN_SMEM);
    cudaFuncSetAttribute(proj_out,   cudaFuncAttributeMaxDynamicSharedMemorySize, MAIN_SMEM);
    cudaFuncSetAttribute(scores_mma, cudaFuncAttributeMaxDynamicSharedMemorySize, MAIN_SMEM);
    cudaFuncSetAttribute(av_mma,     cudaFuncAttributeMaxDynamicSharedMemorySize, AV_SMEM);

    const int act4 = MROWS * DMODEL / 4;   // 2097152 -> 8192 blocks

    // 0) fp16 2-term conversions (merged launches)
    PrepWgtArgs wargs;
    wargs.W[0] = Wq; wargs.W[1] = Wk; wargs.W[2] = Wv; wargs.W[3] = Wo;
    wargs.Ws[0] = wqs; wargs.Ws[1] = wks; wargs.Ws[2] = wvs; wargs.Ws[3] = wos;
    prep_wgt4<<<dim3(32, 32, 4), dim3(32, 8)>>>(wargs);

    PrepActArgs aargs;
    aargs.X[0] = q; aargs.X[1] = k; aargs.X[2] = v;
    aargs.Y[0] = qs; aargs.Y[1] = ks; aargs.Y[2] = vs;
    prep_act3<<<dim3(act4 / 256, 3), 256>>>(aargs);

    // 1) Q/K/V projections merged (HMMA): grid (8, 64, 3)
    QKVArgs pargs;
    pargs.A[0] = qs;  pargs.A[1] = ks;  pargs.A[2] = vs;
    pargs.W[0] = wqs; pargs.W[1] = wks; pargs.W[2] = wvs;
    pargs.bias[0] = bq; pargs.bias[1] = bk; pargs.bias[2] = bv;
    pargs.C[0] = qsp; pargs.C[1] = ksp; pargs.C[2] = vsp;
    proj_qkv<<<dim3(DMODEL / 128, MROWS / 128, 3), 256, MAIN_SMEM>>>(pargs);

    // 2) Scores -> e = exp(score) fp16 into g_eh + per-row partial sums
    dim3 gs(SEQ / 128, SEQ / 128, NZ);  // (16, 16, 64)
    scores_mma<<<gs, 256, MAIN_SMEM>>>(qsp, ksp, ehp, psum);

    // 3) AV: normalize, write final attn fp32, O -> g_ohs [hi|lo]
    dim3 ga(SEQ / 128, NZ);  // (16, 64)
    av_mma<<<ga, 256, AV_SMEM>>>(ehp, attn, psum, vsp, ohs);

    // 4) Output projection -> d_out
    proj_out<<<dim3(DMODEL / 128, MROWS / 128), 256, MAIN_SMEM>>>(ohs, wos, bo, out);
}